// round 7
// baseline (speedup 1.0000x reference)
#include <cuda_runtime.h>
#include <cuda.h>
#include <cuda_bf16.h>
#include <math.h>
#include <stdint.h>

#define B_    2
#define S_    4096
#define T_    8192
#define IN_   1280
#define D_    768
#define H_    12
#define FF_   3072
#define L_    12
#define TGT_  1024
#define NB_   64
#define NQKV  2304

// weight arena (element offsets, [N,K] transposed planes)
#define OFF_PROJ 0
#define OFF_QKV  (IN_*D_)
#define OFF_WO   (OFF_QKV + L_*NQKV*D_)
#define OFF_WI   (OFF_WO + L_*D_*D_)
#define OFF_WO2  (OFF_WI + L_*D_*FF_)
#define WTOT     (OFF_WO2 + L_*FF_*D_)

#define STAGE_SZ 98304
#define GEMM_SMEM (1024 + 2*STAGE_SZ)
#define ATTN_SMEM 55296

// ---------------- scratch ----------------
__device__ float g_h[T_ * D_];
__device__ float g_tmp[T_ * D_];
__device__ float g_cls[2 * 512];
__device__ float g_bqkv[L_ * NQKV];
__device__ int   g_gi[NB_ * 8];

__device__ __align__(128) __nv_bfloat16 g_whi[WTOT];
__device__ __align__(128) __nv_bfloat16 g_wlo[WTOT];
__device__ __align__(128) __nv_bfloat16 g_xhi[T_ * IN_];
__device__ __align__(128) __nv_bfloat16 g_xlo[T_ * IN_];
__device__ __align__(128) __nv_bfloat16 g_hhi[T_ * D_];
__device__ __align__(128) __nv_bfloat16 g_hlo[T_ * D_];
__device__ __align__(128) __nv_bfloat16 g_chi[T_ * D_];
__device__ __align__(128) __nv_bfloat16 g_clo[T_ * D_];
__device__ __align__(128) __nv_bfloat16 g_fhi[T_ * FF_];
__device__ __align__(128) __nv_bfloat16 g_flo[T_ * FF_];
__device__ __align__(128) __nv_bfloat16 g_qkvhi[T_ * NQKV];
__device__ __align__(128) __nv_bfloat16 g_qkvlo[T_ * NQKV];
__device__ float g_part[B_ * H_ * 2 * 8 * 64 * 66];

// ---------------- PTX helpers ----------------
__device__ __forceinline__ uint32_t s2u(const void* p) { return (uint32_t)__cvta_generic_to_shared(p); }
__device__ __forceinline__ void mbar_init(uint32_t a, uint32_t c) {
    asm volatile("mbarrier.init.shared.b64 [%0], %1;" :: "r"(a), "r"(c) : "memory");
}
__device__ __forceinline__ void mbar_expect(uint32_t a, uint32_t b) {
    asm volatile("mbarrier.arrive.expect_tx.shared.b64 _, [%0], %1;" :: "r"(a), "r"(b) : "memory");
}
__device__ __forceinline__ void mbar_wait(uint32_t a, uint32_t par) {
    asm volatile("{\n\t.reg .pred P;\n\tW_%=:\n\t"
                 "mbarrier.try_wait.parity.acquire.cta.shared::cta.b64 P, [%0], %1, 0x989680;\n\t"
                 "@P bra.uni D_%=;\n\tbra.uni W_%=;\n\tD_%=:\n\t}" :: "r"(a), "r"(par) : "memory");
}
__device__ __forceinline__ void tma2d(uint32_t dst, const void* tm, int x, int y, uint32_t mb) {
    asm volatile("cp.async.bulk.tensor.2d.shared::cta.global.tile.mbarrier::complete_tx::bytes "
                 "[%0], [%1, {%2, %3}], [%4];" :: "r"(dst), "l"(tm), "r"(x), "r"(y), "r"(mb) : "memory");
}
__device__ __forceinline__ void tma3d(uint32_t dst, const void* tm, int x, int y, int z, uint32_t mb) {
    asm volatile("cp.async.bulk.tensor.3d.shared::cta.global.tile.mbarrier::complete_tx::bytes "
                 "[%0], [%1, {%2, %3, %4}], [%5];" :: "r"(dst), "l"(tm), "r"(x), "r"(y), "r"(z), "r"(mb) : "memory");
}
__device__ __forceinline__ void ldsm4a(uint32_t* r, uint32_t a) {
    asm volatile("ldmatrix.sync.aligned.m8n8.x4.shared.b16 {%0,%1,%2,%3}, [%4];"
                 : "=r"(r[0]), "=r"(r[1]), "=r"(r[2]), "=r"(r[3]) : "r"(a));
}
__device__ __forceinline__ void ldsm4t(uint32_t* r, uint32_t a) {
    asm volatile("ldmatrix.sync.aligned.m8n8.x4.trans.shared.b16 {%0,%1,%2,%3}, [%4];"
                 : "=r"(r[0]), "=r"(r[1]), "=r"(r[2]), "=r"(r[3]) : "r"(a));
}
__device__ __forceinline__ void mma16816(float* d, const uint32_t* a, uint32_t b0, uint32_t b1) {
    asm volatile("mma.sync.aligned.m16n8k16.row.col.f32.bf16.bf16.f32 "
                 "{%0,%1,%2,%3}, {%4,%5,%6,%7}, {%8,%9}, {%0,%1,%2,%3};"
                 : "+f"(d[0]), "+f"(d[1]), "+f"(d[2]), "+f"(d[3])
                 : "r"(a[0]), "r"(a[1]), "r"(a[2]), "r"(a[3]), "r"(b0), "r"(b1));
}
__device__ __forceinline__ uint32_t packbf2(float lo_e, float hi_e) {
    __nv_bfloat162 t;
    t.x = __float2bfloat16(lo_e);
    t.y = __float2bfloat16(hi_e);
    return *(uint32_t*)&t;
}

// ---------------- prep kernels ----------------
__global__ void split_kernel(const float* __restrict__ s, __nv_bfloat16* __restrict__ hi,
                             __nv_bfloat16* __restrict__ lo, int n) {
    int i = blockIdx.x * blockDim.x + threadIdx.x;
    if (i >= n) return;
    float v = s[i];
    __nv_bfloat16 h = __float2bfloat16(v);
    hi[i] = h;
    lo[i] = __float2bfloat16(v - __bfloat162float(h));
}

__global__ void tsplit_kernel(const float* __restrict__ src, __nv_bfloat16* __restrict__ hi,
                              __nv_bfloat16* __restrict__ lo, int K, int N, int lstride) {
    __shared__ float t[32][33];
    const int l = blockIdx.z;
    const int n0 = blockIdx.x * 32, k0 = blockIdx.y * 32;
    const float* S = src + (size_t)l * K * N;
    const int tx = threadIdx.x, ty = threadIdx.y;
#pragma unroll
    for (int j = 0; j < 4; ++j)
        t[ty + j * 8][tx] = S[(size_t)(k0 + ty + j * 8) * N + n0 + tx];
    __syncthreads();
    __nv_bfloat16* Ht = hi + (size_t)l * lstride;
    __nv_bfloat16* Lt = lo + (size_t)l * lstride;
#pragma unroll
    for (int j = 0; j < 4; ++j) {
        int n = n0 + ty + j * 8;
        float v = t[tx][ty + j * 8];
        __nv_bfloat16 h = __float2bfloat16(v);
        Ht[(size_t)n * K + k0 + tx] = h;
        Lt[(size_t)n * K + k0 + tx] = __float2bfloat16(v - __bfloat162float(h));
    }
}

__global__ void build_gi_kernel(const int* __restrict__ rb) {
    int n = threadIdx.x;
    if (n < 1 || n >= NB_ - 1) return;
    int* p = g_gi + n * 8;
    p[0] = 0; p[1] = n - 1; p[2] = n; p[3] = n + 1; p[4] = NB_ - 1;
    p[5] = rb[n * 3 + 0]; p[6] = rb[n * 3 + 1]; p[7] = rb[n * 3 + 2];
}

__global__ void bcat_kernel(const float* __restrict__ bq, const float* __restrict__ bk,
                            const float* __restrict__ bv) {
    int i = blockIdx.x * blockDim.x + threadIdx.x;
    if (i >= L_ * NQKV) return;
    int l = i / NQKV, n = i % NQKV;
    float v = (n < 768) ? bq[l * 768 + n] : (n < 1536) ? bk[l * 768 + n - 768] : bv[l * 768 + n - 1536];
    g_bqkv[i] = v;
}

// ---------------- TMA + mma.sync bf16x3 GEMM, 256x128 CTA tile ----------------
// C[M=8192,N] = A[M,K] @ W[K,N] + bias (+res)(+gelu).
// 512 thr = 16 warps (8x2 of 32x64 warp tiles). K64 chunks, 96 KB/stage, double buffered.
template<bool GELU, bool RES, bool SPLITOUT, bool WRITEF32>
__global__ __launch_bounds__(512, 1) void tgemm_kernel(
    const __grid_constant__ CUtensorMap tAh, const __grid_constant__ CUtensorMap tAl,
    const __grid_constant__ CUtensorMap tBh, const __grid_constant__ CUtensorMap tBl,
    const float* __restrict__ bias, const float* __restrict__ res,
    float* __restrict__ C, __nv_bfloat16* __restrict__ Chi, __nv_bfloat16* __restrict__ Clo,
    int N, int K, int layer)
{
    extern __shared__ char dsm[];
    const uint32_t ctl = s2u(dsm);
    const uint32_t tiles = (ctl + 64 + 1023) & ~1023u;
    const int tid = threadIdx.x;
    const int warp = tid >> 5, lane = tid & 31;
    const int wr = warp >> 1, wc = warp & 1;
    const int m0 = blockIdx.y * 256, n0 = blockIdx.x * 128;
    const int nch = K >> 6;

    if (tid == 0) {
        mbar_init(ctl, 1);
        mbar_init(ctl + 8, 1);
        asm volatile("fence.proxy.async.shared::cta;" ::: "memory");
    }
    __syncthreads();

    auto issue = [&](int i) {
        const int st = i & 1;
        const uint32_t mb = ctl + st * 8;
        const uint32_t tb = tiles + st * STAGE_SZ;
        mbar_expect(mb, STAGE_SZ);
        const int k0 = i << 6;
        tma2d(tb +     0, &tAh, k0, m0, mb);   // A-hi 256x64 = 32 KB
        tma2d(tb + 32768, &tAl, k0, m0, mb);   // A-lo 32 KB
        tma3d(tb + 65536, &tBh, k0, n0, layer, mb);  // B-hi 16 KB
        tma3d(tb + 81920, &tBl, k0, n0, layer, mb);  // B-lo 16 KB
    };
    const bool prod = (tid == 0);
    if (prod) { issue(0); issue(1); }

    float acc[2][8][4];
#pragma unroll
    for (int mi = 0; mi < 2; ++mi)
#pragma unroll
        for (int ni = 0; ni < 8; ++ni)
#pragma unroll
            for (int r = 0; r < 4; ++r) acc[mi][ni][r] = 0.f;

    const int lrow = lane & 15;
    const uint32_t hb16 = (lane >> 4) * 16;
    uint32_t arow[2], axr[2], brow[4], bxr[4];
#pragma unroll
    for (int mi = 0; mi < 2; ++mi) {
        int r = wr * 32 + mi * 16 + lrow;
        arow[mi] = r * 128; axr[mi] = (r & 7) * 16;
    }
#pragma unroll
    for (int np = 0; np < 4; ++np) {
        int r = wc * 64 + np * 16 + lrow;
        brow[np] = r * 128; bxr[np] = (r & 7) * 16;
    }

    for (int i = 0; i < nch; ++i) {
        const int st = i & 1;
        mbar_wait(ctl + st * 8, (i >> 1) & 1);
        const uint32_t bAh = tiles + st * STAGE_SZ;
        const uint32_t bAl = bAh + 32768;
        const uint32_t bBh = bAh + 65536;
        const uint32_t bBl = bAh + 81920;
#pragma unroll
        for (int ks = 0; ks < 4; ++ks) {
            const uint32_t colb = ks * 32 + hb16;
            uint32_t ah[2][4], al[2][4];
#pragma unroll
            for (int mi = 0; mi < 2; ++mi) {
                ldsm4a(ah[mi], bAh + arow[mi] + (colb ^ axr[mi]));
                ldsm4a(al[mi], bAl + arow[mi] + (colb ^ axr[mi]));
            }
#pragma unroll
            for (int np = 0; np < 4; ++np) {
                uint32_t bh[4], bl[4];
                ldsm4a(bh, bBh + brow[np] + (colb ^ bxr[np]));
                ldsm4a(bl, bBl + brow[np] + (colb ^ bxr[np]));
#pragma unroll
                for (int j = 0; j < 2; ++j) {
                    const int ni = np * 2 + j;
#pragma unroll
                    for (int mi = 0; mi < 2; ++mi) {
                        mma16816(acc[mi][ni], ah[mi], bh[j], bh[j + 2]);
                        mma16816(acc[mi][ni], ah[mi], bl[j], bl[j + 2]);
                        mma16816(acc[mi][ni], al[mi], bh[j], bh[j + 2]);
                    }
                }
            }
        }
        __syncthreads();
        if (prod && i + 2 < nch) issue(i + 2);
    }

#pragma unroll
    for (int mi = 0; mi < 2; ++mi) {
        const int rbase = m0 + wr * 32 + mi * 16 + (lane >> 2);
#pragma unroll
        for (int ni = 0; ni < 8; ++ni) {
            const int cbase = n0 + wc * 64 + ni * 8 + (lane & 3) * 2;
            const float b0 = bias[cbase], b1 = bias[cbase + 1];
#pragma unroll
            for (int hr = 0; hr < 2; ++hr) {
                const int row = rbase + hr * 8;
                float v0 = acc[mi][ni][hr * 2 + 0] + b0;
                float v1 = acc[mi][ni][hr * 2 + 1] + b1;
                if (RES) {
                    v0 += res[(size_t)row * N + cbase];
                    v1 += res[(size_t)row * N + cbase + 1];
                }
                if (GELU) {
                    float u = v0;
                    v0 = 0.5f * u * (1.0f + tanhf(0.7978845608028654f * (u + 0.044715f * u * u * u)));
                    u = v1;
                    v1 = 0.5f * u * (1.0f + tanhf(0.7978845608028654f * (u + 0.044715f * u * u * u)));
                }
                const size_t idx = (size_t)row * N + cbase;
                if (WRITEF32) { C[idx] = v0; C[idx + 1] = v1; }
                if (SPLITOUT) {
                    __nv_bfloat16 h0 = __float2bfloat16(v0);
                    __nv_bfloat16 h1 = __float2bfloat16(v1);
                    Chi[idx] = h0; Chi[idx + 1] = h1;
                    Clo[idx]     = __float2bfloat16(v0 - __bfloat162float(h0));
                    Clo[idx + 1] = __float2bfloat16(v1 - __bfloat162float(h1));
                }
            }
        }
    }
}

// ---------------- LayerNorm ----------------
__global__ __launch_bounds__(256) void ln_kernel(
    const float* __restrict__ in, const float* __restrict__ gamma,
    const float* __restrict__ beta, float* __restrict__ out,
    __nv_bfloat16* __restrict__ ohi, __nv_bfloat16* __restrict__ olo,
    const float* __restrict__ pos, const float* __restrict__ tok)
{
    const int r = blockIdx.x, s = r % S_, t = threadIdx.x;
    const float* row = in + (size_t)r * D_;
    float x[3];
#pragma unroll
    for (int j = 0; j < 3; ++j) {
        int i = t + j * 256;
        float v = row[i];
        if (pos) v += pos[(size_t)s * D_ + i] + tok[i];
        x[j] = v;
    }
    float sum = x[0] + x[1] + x[2];
    float sq  = x[0] * x[0] + x[1] * x[1] + x[2] * x[2];
    __shared__ float rs[8], rq[8];
#pragma unroll
    for (int o = 16; o > 0; o >>= 1) {
        sum += __shfl_xor_sync(0xffffffffu, sum, o);
        sq  += __shfl_xor_sync(0xffffffffu, sq, o);
    }
    if ((t & 31) == 0) { rs[t >> 5] = sum; rq[t >> 5] = sq; }
    __syncthreads();
    if (t < 32) {
        float s2 = (t < 8) ? rs[t] : 0.f;
        float q2 = (t < 8) ? rq[t] : 0.f;
#pragma unroll
        for (int o = 4; o > 0; o >>= 1) {
            s2 += __shfl_xor_sync(0xffffffffu, s2, o);
            q2 += __shfl_xor_sync(0xffffffffu, q2, o);
        }
        if (t == 0) { rs[0] = s2; rq[0] = q2; }
    }
    __syncthreads();
    const float mean = rs[0] * (1.0f / 768.0f);
    float var = rq[0] * (1.0f / 768.0f) - mean * mean;
    const float rstd = rsqrtf(fmaxf(var, 0.f) + 1e-12f);
#pragma unroll
    for (int j = 0; j < 3; ++j) {
        int i = t + j * 256;
        float y = (x[j] - mean) * rstd * gamma[i] + beta[i];
        size_t idx = (size_t)r * D_ + i;
        out[idx] = y;
        __nv_bfloat16 h = __float2bfloat16(y);
        ohi[idx] = h;
        olo[idx] = __float2bfloat16(y - __bfloat162float(h));
    }
}

// ---------------- tensor-core block-sparse flash attention ----------------
__global__ __launch_bounds__(128, 3) void attn_tc_kernel(
    const __nv_bfloat16* __restrict__ qkvh, const __nv_bfloat16* __restrict__ qkvl,
    const float* __restrict__ mask)
{
    extern __shared__ char smraw[];
    const uint32_t su = s2u(smraw);
    const uint32_t QH = su, QL = su + 9216, KH = su + 18432, KL = su + 27648,
                   VH = su + 36864, VL = su + 46080;

    const int b = blockIdx.z, hh = blockIdx.y, ib = blockIdx.x;
    const int tid = threadIdx.x, warp = tid >> 5, lane = tid & 31;

    int qb, t0 = 0, e = 0, slice = 0;
    bool edge;
    if (ib < 62) { qb = ib + 1; edge = false; }
    else {
        edge = true;
        int xx = ib - 62;
        e = xx >> 3; slice = xx & 7;
        qb = e ? (NB_ - 1) : 0;
        t0 = slice * 8;
    }

    const int rrow = tid >> 1, half = tid & 1;
    {
        const size_t gq = (size_t)(b * S_ + qb * 64 + rrow) * NQKV + hh * 64 + half * 32;
        const uint4* s0 = (const uint4*)(qkvh + gq);
        const uint4* s1 = (const uint4*)(qkvl + gq);
        uint4* d0 = (uint4*)(smraw + rrow * 144 + half * 64);
        uint4* d1 = (uint4*)(smraw + 9216 + rrow * 144 + half * 64);
#pragma unroll
        for (int j = 0; j < 4; ++j) { d0[j] = s0[j]; d1[j] = s1[j]; }
    }

    float Sf[8][4], Of[8][4];
#pragma unroll
    for (int f = 0; f < 8; ++f)
#pragma unroll
        for (int r = 0; r < 4; ++r) Of[f][r] = 0.f;
    float m0 = -1e30f, m1 = -1e30f, l0 = 0.f, l1 = 0.f;

    const uint32_t lr15 = (lane & 15);
    const uint32_t hb = (lane >> 4);

    for (int kt = 0; kt < 8; ++kt) {
        const int kb = edge ? (t0 + kt) : g_gi[qb * 8 + kt];
        __syncthreads();
        {
            const size_t gk = (size_t)(b * S_ + kb * 64 + rrow) * NQKV + hh * 64 + half * 32;
            const uint4* kh = (const uint4*)(qkvh + gk + 768);
            const uint4* kl = (const uint4*)(qkvl + gk + 768);
            const uint4* vh = (const uint4*)(qkvh + gk + 1536);
            const uint4* vl = (const uint4*)(qkvl + gk + 1536);
            const int off = rrow * 144 + half * 64;
            uint4* dkh = (uint4*)(smraw + 18432 + off);
            uint4* dkl = (uint4*)(smraw + 27648 + off);
            uint4* dvh = (uint4*)(smraw + 36864 + off);
            uint4* dvl = (uint4*)(smraw + 46080 + off);
#pragma unroll
            for (int j = 0; j < 4; ++j) { dkh[j] = kh[j]; dkl[j] = kl[j]; dvh[j] = vh[j]; dvl[j] = vl[j]; }
        }
        __syncthreads();

#pragma unroll
        for (int f = 0; f < 8; ++f)
#pragma unroll
            for (int r = 0; r < 4; ++r) Sf[f][r] = 0.f;
#pragma unroll
        for (int ks = 0; ks < 4; ++ks) {
            const uint32_t colb = ks * 32 + hb * 16;
            const uint32_t qoff = (warp * 16 + lr15) * 144 + colb;
            uint32_t qh[4], ql[4];
            ldsm4a(qh, QH + qoff);
            ldsm4a(ql, QL + qoff);
#pragma unroll
            for (int np = 0; np < 4; ++np) {
                const uint32_t koff = (np * 16 + lr15) * 144 + colb;
                uint32_t kh[4], kl[4];
                ldsm4a(kh, KH + koff);
                ldsm4a(kl, KL + koff);
#pragma unroll
                for (int j = 0; j < 2; ++j) {
                    mma16816(Sf[np * 2 + j], qh, kh[j], kh[j + 2]);
                    mma16816(Sf[np * 2 + j], qh, kl[j], kl[j + 2]);
                    mma16816(Sf[np * 2 + j], ql, kh[j], kh[j + 2]);
                }
            }
        }

        const float* mrow = mask + (size_t)b * S_ + kb * 64;
        float t0m = -1e30f, t1m = -1e30f;
#pragma unroll
        for (int f = 0; f < 8; ++f) {
            const int c = f * 8 + 2 * (lane & 3);
            const float2 mk = *(const float2*)(mrow + c);
            Sf[f][0] = Sf[f][0] * 0.125f - 1e9f * (1.f - mk.x);
            Sf[f][1] = Sf[f][1] * 0.125f - 1e9f * (1.f - mk.y);
            Sf[f][2] = Sf[f][2] * 0.125f - 1e9f * (1.f - mk.x);
            Sf[f][3] = Sf[f][3] * 0.125f - 1e9f * (1.f - mk.y);
            t0m = fmaxf(t0m, fmaxf(Sf[f][0], Sf[f][1]));
            t1m = fmaxf(t1m, fmaxf(Sf[f][2], Sf[f][3]));
        }
        t0m = fmaxf(t0m, __shfl_xor_sync(0xffffffffu, t0m, 1));
        t0m = fmaxf(t0m, __shfl_xor_sync(0xffffffffu, t0m, 2));
        t1m = fmaxf(t1m, __shfl_xor_sync(0xffffffffu, t1m, 1));
        t1m = fmaxf(t1m, __shfl_xor_sync(0xffffffffu, t1m, 2));
        const float mn0 = fmaxf(m0, t0m), mn1 = fmaxf(m1, t1m);
        const float cr0 = __expf(m0 - mn0), cr1 = __expf(m1 - mn1);
        float ps0 = 0.f, ps1 = 0.f;
#pragma unroll
        for (int f = 0; f < 8; ++f) {
            Sf[f][0] = __expf(Sf[f][0] - mn0);
            Sf[f][1] = __expf(Sf[f][1] - mn0);
            Sf[f][2] = __expf(Sf[f][2] - mn1);
            Sf[f][3] = __expf(Sf[f][3] - mn1);
            ps0 += Sf[f][0] + Sf[f][1];
            ps1 += Sf[f][2] + Sf[f][3];
        }
        ps0 += __shfl_xor_sync(0xffffffffu, ps0, 1);
        ps0 += __shfl_xor_sync(0xffffffffu, ps0, 2);
        ps1 += __shfl_xor_sync(0xffffffffu, ps1, 1);
        ps1 += __shfl_xor_sync(0xffffffffu, ps1, 2);
        l0 = l0 * cr0 + ps0; m0 = mn0;
        l1 = l1 * cr1 + ps1; m1 = mn1;
#pragma unroll
        for (int f = 0; f < 8; ++f) {
            Of[f][0] *= cr0; Of[f][1] *= cr0; Of[f][2] *= cr1; Of[f][3] *= cr1;
        }

        uint32_t ph[4][4], pl[4][4];
#pragma unroll
        for (int j2 = 0; j2 < 4; ++j2) {
            const float* A = Sf[2 * j2];
            const float* Bq = Sf[2 * j2 + 1];
            float la, lb;
            __nv_bfloat162 t;
            t.x = __float2bfloat16(A[0]); t.y = __float2bfloat16(A[1]);
            la = A[0] - __bfloat162float(t.x); lb = A[1] - __bfloat162float(t.y);
            ph[j2][0] = *(uint32_t*)&t; pl[j2][0] = packbf2(la, lb);
            t.x = __float2bfloat16(A[2]); t.y = __float2bfloat16(A[3]);
            la = A[2] - __bfloat162float(t.x); lb = A[3] - __bfloat162float(t.y);
            ph[j2][1] = *(uint32_t*)&t; pl[j2][1] = packbf2(la, lb);
            t.x = __float2bfloat16(Bq[0]); t.y = __float2bfloat16(Bq[1]);
            la = Bq[0] - __bfloat162float(t.x); lb = Bq[1] - __bfloat162float(t.y);
            ph[j2][2] = *(uint32_t*)&t; pl[j2][2] = packbf2(la, lb);
            t.x = __float2bfloat16(Bq[2]); t.y = __float2bfloat16(Bq[3]);
            la = Bq[2] - __bfloat162float(t.x); lb = Bq[3] - __bfloat162float(t.y);
            ph[j2][3] = *(uint32_t*)&t; pl[j2][3] = packbf2(la, lb);
        }

#pragma unroll
        for (int ks2 = 0; ks2 < 4; ++ks2) {
#pragma unroll
            for (int g = 0; g < 4; ++g) {
                const uint32_t voff = (ks2 * 16 + lr15) * 144 + (g * 16 + hb * 8) * 2;
                uint32_t vh[4], vl[4];
                ldsm4t(vh, VH + voff);
                ldsm4t(vl, VL + voff);
#pragma unroll
                for (int j = 0; j < 2; ++j) {
                    mma16816(Of[g * 2 + j], ph[ks2], vh[2 * j], vh[2 * j + 1]);
                    mma16816(Of[g * 2 + j], ph[ks2], vl[2 * j], vl[2 * j + 1]);
                    mma16816(Of[g * 2 + j], pl[ks2], vh[2 * j], vh[2 * j + 1]);
                }
            }
        }
    }

    const int r0 = warp * 16 + (lane >> 2);
    if (!edge) {
        const float inv0 = 1.f / l0, inv1 = 1.f / l1;
        const size_t tk0 = (size_t)(b * S_ + qb * 64 + r0) * D_ + hh * 64;
        const size_t tk1 = tk0 + 8 * D_;
#pragma unroll
        for (int f = 0; f < 8; ++f) {
            const int c = f * 8 + 2 * (lane & 3);
            float v0 = Of[f][0] * inv0, v1 = Of[f][1] * inv0;
            float v2 = Of[f][2] * inv1, v3 = Of[f][3] * inv1;
            __nv_bfloat162 h01, h23, l01, l23;
            h01.x = __float2bfloat16(v0); h01.y = __float2bfloat16(v1);
            l01.x = __float2bfloat16(v0 - __bfloat162float(h01.x));
            l01.y = __float2bfloat16(v1 - __bfloat162float(h01.y));
            h23.x = __float2bfloat16(v2); h23.y = __float2bfloat16(v3);
            l23.x = __float2bfloat16(v2 - __bfloat162float(h23.x));
            l23.y = __float2bfloat16(v3 - __bfloat162float(h23.y));
            *(__nv_bfloat162*)(g_chi + tk0 + c) = h01;
            *(__nv_bfloat162*)(g_clo + tk0 + c) = l01;
            *(__nv_bfloat162*)(g_chi + tk1 + c) = h23;
            *(__nv_bfloat162*)(g_clo + tk1 + c) = l23;
        }
    } else {
        float* base = g_part + ((size_t)((((b * H_ + hh) * 2 + e) * 8 + slice) * 64)) * 66;
        float* pp0 = base + (size_t)r0 * 66;
        float* pp1 = base + (size_t)(r0 + 8) * 66;
#pragma unroll
        for (int f = 0; f < 8; ++f) {
            const int c = f * 8 + 2 * (lane & 3);
            pp0[c] = Of[f][0]; pp0[c + 1] = Of[f][1];
            pp1[c] = Of[f][2]; pp1[c + 1] = Of[f][3];
        }
        if ((lane & 3) == 0) {
            pp0[64] = m0; pp0[65] = l0;
            pp1[64] = m1; pp1[65] = l1;
        }
    }
}

__global__ __launch_bounds__(256) void merge_kernel() {
    const int e = blockIdx.x, hh = blockIdx.y, b = blockIdx.z;
    const int tid = threadIdx.x;
    const int r = tid >> 2, t4 = tid & 3;
    const size_t base = ((size_t)(((b * H_ + hh) * 2 + e) * 8)) * 64 * 66;

    float M = -1e30f;
#pragma unroll
    for (int s = 0; s < 8; ++s) M = fmaxf(M, g_part[base + ((size_t)s * 64 + r) * 66 + 64]);
    float L = 0.f, acc[16];
#pragma unroll
    for (int i = 0; i < 16; ++i) acc[i] = 0.f;
#pragma unroll
    for (int s = 0; s < 8; ++s) {
        const float* pp = g_part + base + ((size_t)s * 64 + r) * 66;
        const float w = __expf(pp[64] - M);
        L += pp[65] * w;
#pragma unroll
        for (int i = 0; i < 16; ++i) acc[i] += pp[t4 * 16 + i] * w;
    }
    const float inv = 1.0f / L;
    const int qb = e ? (NB_ - 1) : 0;
    const size_t idx = ((size_t)(b * S_ + qb * 64 + r)) * D_ + hh * 64 + t4 * 16;
#pragma unroll
    for (int i = 0; i < 16; ++i) {
        float vv = acc[i] * inv;
        __nv_bfloat16 h = __float2bfloat16(vv);
        g_chi[idx + i] = h;
        g_clo[idx + i] = __float2bfloat16(vv - __bfloat162float(h));
    }
}

// ---------------- classifier ----------------
__global__ void cls1_kernel(const float* __restrict__ h, const float* __restrict__ w,
                            const float* __restrict__ bias, float* __restrict__ out) {
    int gid = blockIdx.x * blockDim.x + threadIdx.x;
    if (gid >= 2 * 512) return;
    int b = gid >> 9, n = gid & 511;
    const float* hrow = h + (size_t)b * S_ * D_;
    float s = 0.f;
    for (int k2 = 0; k2 < D_; ++k2) s += hrow[k2] * w[(size_t)k2 * 512 + n];
    out[gid] = fmaxf(s + bias[n], 0.f);
}
__global__ void cls2_kernel(const float* __restrict__ rin, const float* __restrict__ w,
                            const float* __restrict__ bias, float* __restrict__ out) {
    int gid = blockIdx.x * blockDim.x + threadIdx.x;
    if (gid >= 2 * TGT_) return;
    int b = gid >> 10, n = gid & 1023;
    float s = 0.f;
    for (int k2 = 0; k2 < 512; ++k2) s += rin[b * 512 + k2] * w[(size_t)k2 * TGT_ + n];
    out[gid] = s + bias[n];
}

// ---------------- host ----------------
typedef CUresult (*EncFn)(CUtensorMap*, CUtensorMapDataType, cuuint32_t, void*,
                          const cuuint64_t*, const cuuint64_t*, const cuuint32_t*, const cuuint32_t*,
                          CUtensorMapInterleave, CUtensorMapSwizzle, CUtensorMapL2promotion,
                          CUtensorMapFloatOOBfill);

extern "C" void kernel_launch(void* const* d_in, const int* in_sizes, int n_in,
                              void* d_out, int out_size)
{
    const float* x        = (const float*)d_in[0];
    const float* mask     = (const float*)d_in[1];
    const float* proj_b   = (const float*)d_in[3];
    const float* pos_emb  = (const float*)d_in[4];
    const float* tok_emb  = (const float*)d_in[5];
    const float* emb_g    = (const float*)d_in[6];
    const float* emb_b    = (const float*)d_in[7];
    const float* bq_all   = (const float*)d_in[9];
    const float* bk_all   = (const float*)d_in[11];
    const float* bv_all   = (const float*)d_in[13];
    const float* bo_all   = (const float*)d_in[15];
    const float* ln1g_all = (const float*)d_in[16];
    const float* ln1b_all = (const float*)d_in[17];
    const float* bi_all   = (const float*)d_in[19];
    const float* bo2_all  = (const float*)d_in[21];
    const float* ln2g_all = (const float*)d_in[22];
    const float* ln2b_all = (const float*)d_in[23];
    const float* cls_w1   = (const float*)d_in[24];
    const float* cls_b1   = (const float*)d_in[25];
    const float* cls_w2   = (const float*)d_in[26];
    const float* cls_b2   = (const float*)d_in[27];
    const int*   rb       = (const int*)d_in[28];
    float* out = (float*)d_out;

    float *ph, *ptmp, *pcls, *pbqkv;
    __nv_bfloat16 *pwhi, *pwlo, *pxhi, *pxlo, *phhi, *phlo, *pchi, *pclo, *pfhi, *pflo, *pqvh, *pqvl;
    cudaGetSymbolAddress((void**)&ph,   g_h);
    cudaGetSymbolAddress((void**)&ptmp, g_tmp);
    cudaGetSymbolAddress((void**)&pcls, g_cls);
    cudaGetSymbolAddress((void**)&pbqkv, g_bqkv);
    cudaGetSymbolAddress((void**)&pwhi, g_whi);
    cudaGetSymbolAddress((void**)&pwlo, g_wlo);
    cudaGetSymbolAddress((void**)&pxhi, g_xhi);
    cudaGetSymbolAddress((void**)&pxlo, g_xlo);
    cudaGetSymbolAddress((void**)&phhi, g_hhi);
    cudaGetSymbolAddress((void**)&phlo, g_hlo);
    cudaGetSymbolAddress((void**)&pchi, g_chi);
    cudaGetSymbolAddress((void**)&pclo, g_clo);
    cudaGetSymbolAddress((void**)&pfhi, g_fhi);
    cudaGetSymbolAddress((void**)&pflo, g_flo);
    cudaGetSymbolAddress((void**)&pqvh, g_qkvhi);
    cudaGetSymbolAddress((void**)&pqvl, g_qkvlo);

    EncFn enc = nullptr;
    cudaDriverEntryPointQueryResult qr;
    cudaGetDriverEntryPointByVersion("cuTensorMapEncodeTiled", (void**)&enc, 12000,
                                     cudaEnableDefault, &qr);

    auto mk2 = [&](CUtensorMap* m, void* p, uint64_t K) {
        cuuint64_t d[2] = {K, T_};
        cuuint64_t st[1] = {K * 2};
        cuuint32_t bx[2] = {64, 256}, es[2] = {1, 1};
        enc(m, CU_TENSOR_MAP_DATA_TYPE_BFLOAT16, 2, p, d, st, bx, es,
            CU_TENSOR_MAP_INTERLEAVE_NONE, CU_TENSOR_MAP_SWIZZLE_128B,
            CU_TENSOR_MAP_L2_PROMOTION_L2_128B, CU_TENSOR_MAP_FLOAT_OOB_FILL_NONE);
    };
    auto mk3 = [&](CUtensorMap* m, void* p, uint64_t K, uint64_t N, uint64_t Lz) {
        cuuint64_t d[3] = {K, N, Lz};
        cuuint64_t st[2] = {K * 2, N * K * 2};
        cuuint32_t bx[3] = {64, 128, 1}, es[3] = {1, 1, 1};
        enc(m, CU_TENSOR_MAP_DATA_TYPE_BFLOAT16, 3, p, d, st, bx, es,
            CU_TENSOR_MAP_INTERLEAVE_NONE, CU_TENSOR_MAP_SWIZZLE_128B,
            CU_TENSOR_MAP_L2_PROMOTION_L2_128B, CU_TENSOR_MAP_FLOAT_OOB_FILL_NONE);
    };

    CUtensorMap mxh, mxl, mhh, mhl, mch, mcl, mfh, mfl;
    CUtensorMap mpjh, mpjl, mqkvh, mqkvl, moh, mol, mih, mil, m2h, m2l;
    mk2(&mxh, pxhi, IN_); mk2(&mxl, pxlo, IN_);
    mk2(&mhh, phhi, D_);  mk2(&mhl, phlo, D_);
    mk2(&mch, pchi, D_);  mk2(&mcl, pclo, D_);
    mk2(&mfh, pfhi, FF_); mk2(&mfl, pflo, FF_);
    mk3(&mpjh, pwhi + OFF_PROJ, IN_, D_, 1);   mk3(&mpjl, pwlo + OFF_PROJ, IN_, D_, 1);
    mk3(&mqkvh, pwhi + OFF_QKV, D_, NQKV, L_); mk3(&mqkvl, pwlo + OFF_QKV, D_, NQKV, L_);
    mk3(&moh, pwhi + OFF_WO, D_, D_, L_);      mk3(&mol, pwlo + OFF_WO, D_, D_, L_);
    mk3(&mih, pwhi + OFF_WI, D_, FF_, L_);     mk3(&mil, pwlo + OFF_WI, D_, FF_, L_);
    mk3(&m2h, pwhi + OFF_WO2, FF_, D_, L_);    mk3(&m2l, pwlo + OFF_WO2, FF_, D_, L_);

    cudaFuncSetAttribute(tgemm_kernel<false, false, false, true>,
                         cudaFuncAttributeMaxDynamicSharedMemorySize, GEMM_SMEM);
    cudaFuncSetAttribute(tgemm_kernel<false, false, true, false>,
                         cudaFuncAttributeMaxDynamicSharedMemorySize, GEMM_SMEM);
    cudaFuncSetAttribute(tgemm_kernel<false, true, false, true>,
                         cudaFuncAttributeMaxDynamicSharedMemorySize, GEMM_SMEM);
    cudaFuncSetAttribute(tgemm_kernel<true, false, true, false>,
                         cudaFuncAttributeMaxDynamicSharedMemorySize, GEMM_SMEM);
    cudaFuncSetAttribute(attn_tc_kernel,
                         cudaFuncAttributeMaxDynamicSharedMemorySize, ATTN_SMEM);

    // prep
    dim3 tb(32, 8);
    tsplit_kernel<<<dim3(D_ / 32, IN_ / 32, 1), tb>>>((const float*)d_in[2], pwhi + OFF_PROJ, pwlo + OFF_PROJ, IN_, D_, IN_ * D_);
    tsplit_kernel<<<dim3(D_ / 32, D_ / 32, L_), tb>>>((const float*)d_in[8],  pwhi + OFF_QKV,               pwlo + OFF_QKV,               D_, D_, NQKV * D_);
    tsplit_kernel<<<dim3(D_ / 32, D_ / 32, L_), tb>>>((const float*)d_in[10], pwhi + OFF_QKV + 768 * 768,   pwlo + OFF_QKV + 768 * 768,   D_, D_, NQKV * D_);
    tsplit_kernel<<<dim3(D_ / 32, D_ / 32, L_), tb>>>((const float*)d_in[12], pwhi + OFF_QKV + 2 * 768 * 768, pwlo + OFF_QKV + 2 * 768 * 768, D_, D_, NQKV * D_);
    tsplit_kernel<<<dim3(D_ / 32, D_ / 32, L_), tb>>>((const float*)d_in[14], pwhi + OFF_WO, pwlo + OFF_WO, D_, D_, D_ * D_);
    tsplit_kernel<<<dim3(FF_ / 32, D_ / 32, L_), tb>>>((const float*)d_in[18], pwhi + OFF_WI, pwlo + OFF_WI, D_, FF_, D_ * FF_);
    tsplit_kernel<<<dim3(D_ / 32, FF_ / 32, L_), tb>>>((const float*)d_in[20], pwhi + OFF_WO2, pwlo + OFF_WO2, FF_, D_, FF_ * D_);
    split_kernel<<<(T_ * IN_ + 255) / 256, 256>>>(x, pxhi, pxlo, T_ * IN_);
    build_gi_kernel<<<1, 64>>>(rb);
    bcat_kernel<<<(L_ * NQKV + 255) / 256, 256>>>(bq_all, bk_all, bv_all);

    const dim3 gD(D_ / 128, T_ / 256);
    const dim3 gQKV(NQKV / 128, T_ / 256);
    const dim3 gF(FF_ / 128, T_ / 256);
    const dim3 gA(78, H_, B_);
    const dim3 gM(2, H_, B_);

    tgemm_kernel<false, false, false, true><<<gD, 512, GEMM_SMEM>>>(
        mxh, mxl, mpjh, mpjl, proj_b, nullptr, ptmp, nullptr, nullptr, D_, IN_, 0);
    ln_kernel<<<T_, 256>>>(ptmp, emb_g, emb_b, ph, phhi, phlo, pos_emb, tok_emb);

    for (int l = 0; l < L_; ++l) {
        tgemm_kernel<false, false, true, false><<<gQKV, 512, GEMM_SMEM>>>(
            mhh, mhl, mqkvh, mqkvl, pbqkv + (size_t)l * NQKV, nullptr,
            nullptr, pqvh, pqvl, NQKV, D_, l);

        attn_tc_kernel<<<gA, 128, ATTN_SMEM>>>(pqvh, pqvl, mask);
        merge_kernel<<<gM, 256>>>();

        tgemm_kernel<false, true, false, true><<<gD, 512, GEMM_SMEM>>>(
            mch, mcl, moh, mol, bo_all + (size_t)l * D_, ph, ptmp, nullptr, nullptr, D_, D_, l);
        ln_kernel<<<T_, 256>>>(ptmp, ln1g_all + (size_t)l * D_, ln1b_all + (size_t)l * D_,
                               ph, phhi, phlo, nullptr, nullptr);

        tgemm_kernel<true, false, true, false><<<gF, 512, GEMM_SMEM>>>(
            mhh, mhl, mih, mil, bi_all + (size_t)l * FF_, nullptr, nullptr, pfhi, pflo, FF_, D_, l);
        tgemm_kernel<false, true, false, true><<<gD, 512, GEMM_SMEM>>>(
            mfh, mfl, m2h, m2l, bo2_all + (size_t)l * D_, ph, ptmp, nullptr, nullptr, D_, FF_, l);
        ln_kernel<<<T_, 256>>>(ptmp, ln2g_all + (size_t)l * D_, ln2b_all + (size_t)l * D_,
                               ph, phhi, phlo, nullptr, nullptr);
    }

    cls1_kernel<<<4, 256>>>(ph, cls_w1, cls_b1, pcls);
    cls2_kernel<<<8, 256>>>(pcls, cls_w2, cls_b2, out);
}

// round 8
// speedup vs baseline: 1.0003x; 1.0003x over previous
#include <cuda_runtime.h>
#include <cuda.h>
#include <cuda_bf16.h>
#include <math.h>
#include <stdint.h>

#define B_    2
#define S_    4096
#define T_    8192
#define IN_   1280
#define D_    768
#define H_    12
#define FF_   3072
#define L_    12
#define TGT_  1024
#define NB_   64
#define NQKV  2304

// weight arena (element offsets, [N,K] transposed planes)
#define OFF_PROJ 0
#define OFF_QKV  (IN_*D_)
#define OFF_WO   (OFF_QKV + L_*NQKV*D_)
#define OFF_WI   (OFF_WO + L_*D_*D_)
#define OFF_WO2  (OFF_WI + L_*D_*FF_)
#define WTOT     (OFF_WO2 + L_*FF_*D_)

#define GEMM_SMEM 133120
#define ATTN_SMEM 55296

// ---------------- scratch ----------------
__device__ float g_h[T_ * D_];
__device__ float g_tmp[T_ * D_];
__device__ float g_cls[2 * 512];
__device__ float g_bqkv[L_ * NQKV];
__device__ int   g_gi[NB_ * 8];

__device__ __align__(128) __nv_bfloat16 g_whi[WTOT];
__device__ __align__(128) __nv_bfloat16 g_wlo[WTOT];
__device__ __align__(128) __nv_bfloat16 g_xhi[T_ * IN_];
__device__ __align__(128) __nv_bfloat16 g_xlo[T_ * IN_];
__device__ __align__(128) __nv_bfloat16 g_hhi[T_ * D_];
__device__ __align__(128) __nv_bfloat16 g_hlo[T_ * D_];
__device__ __align__(128) __nv_bfloat16 g_chi[T_ * D_];
__device__ __align__(128) __nv_bfloat16 g_clo[T_ * D_];
__device__ __align__(128) __nv_bfloat16 g_fhi[T_ * FF_];
__device__ __align__(128) __nv_bfloat16 g_flo[T_ * FF_];
__device__ __align__(128) __nv_bfloat16 g_qkvhi[T_ * NQKV];
__device__ __align__(128) __nv_bfloat16 g_qkvlo[T_ * NQKV];
__device__ float g_part[B_ * H_ * 2 * 8 * 64 * 66];

// ---------------- PTX helpers ----------------
__device__ __forceinline__ uint32_t s2u(const void* p) { return (uint32_t)__cvta_generic_to_shared(p); }
__device__ __forceinline__ void mbar_init(uint32_t a, uint32_t c) {
    asm volatile("mbarrier.init.shared.b64 [%0], %1;" :: "r"(a), "r"(c) : "memory");
}
__device__ __forceinline__ void mbar_expect(uint32_t a, uint32_t b) {
    asm volatile("mbarrier.arrive.expect_tx.shared.b64 _, [%0], %1;" :: "r"(a), "r"(b) : "memory");
}
__device__ __forceinline__ void mbar_wait(uint32_t a, uint32_t par) {
    asm volatile("{\n\t.reg .pred P;\n\tW_%=:\n\t"
                 "mbarrier.try_wait.parity.acquire.cta.shared::cta.b64 P, [%0], %1, 0x989680;\n\t"
                 "@P bra.uni D_%=;\n\tbra.uni W_%=;\n\tD_%=:\n\t}" :: "r"(a), "r"(par) : "memory");
}
__device__ __forceinline__ void tma2d(uint32_t dst, const void* tm, int x, int y, uint32_t mb) {
    asm volatile("cp.async.bulk.tensor.2d.shared::cta.global.tile.mbarrier::complete_tx::bytes "
                 "[%0], [%1, {%2, %3}], [%4];" :: "r"(dst), "l"(tm), "r"(x), "r"(y), "r"(mb) : "memory");
}
__device__ __forceinline__ void tma3d(uint32_t dst, const void* tm, int x, int y, int z, uint32_t mb) {
    asm volatile("cp.async.bulk.tensor.3d.shared::cta.global.tile.mbarrier::complete_tx::bytes "
                 "[%0], [%1, {%2, %3, %4}], [%5];" :: "r"(dst), "l"(tm), "r"(x), "r"(y), "r"(z), "r"(mb) : "memory");
}
__device__ __forceinline__ void ldsm4a(uint32_t* r, uint32_t a) {
    asm volatile("ldmatrix.sync.aligned.m8n8.x4.shared.b16 {%0,%1,%2,%3}, [%4];"
                 : "=r"(r[0]), "=r"(r[1]), "=r"(r[2]), "=r"(r[3]) : "r"(a));
}
__device__ __forceinline__ void ldsm4t(uint32_t* r, uint32_t a) {
    asm volatile("ldmatrix.sync.aligned.m8n8.x4.trans.shared.b16 {%0,%1,%2,%3}, [%4];"
                 : "=r"(r[0]), "=r"(r[1]), "=r"(r[2]), "=r"(r[3]) : "r"(a));
}
__device__ __forceinline__ void mma16816(float* d, const uint32_t* a, uint32_t b0, uint32_t b1) {
    asm volatile("mma.sync.aligned.m16n8k16.row.col.f32.bf16.bf16.f32 "
                 "{%0,%1,%2,%3}, {%4,%5,%6,%7}, {%8,%9}, {%0,%1,%2,%3};"
                 : "+f"(d[0]), "+f"(d[1]), "+f"(d[2]), "+f"(d[3])
                 : "r"(a[0]), "r"(a[1]), "r"(a[2]), "r"(a[3]), "r"(b0), "r"(b1));
}
__device__ __forceinline__ uint32_t packbf2(float lo_e, float hi_e) {
    __nv_bfloat162 t;
    t.x = __float2bfloat16(lo_e);
    t.y = __float2bfloat16(hi_e);
    return *(uint32_t*)&t;
}

// ---------------- prep kernels ----------------
__global__ void split_kernel(const float* __restrict__ s, __nv_bfloat16* __restrict__ hi,
                             __nv_bfloat16* __restrict__ lo, int n) {
    int i = blockIdx.x * blockDim.x + threadIdx.x;
    if (i >= n) return;
    float v = s[i];
    __nv_bfloat16 h = __float2bfloat16(v);
    hi[i] = h;
    lo[i] = __float2bfloat16(v - __bfloat162float(h));
}

__global__ void tsplit_kernel(const float* __restrict__ src, __nv_bfloat16* __restrict__ hi,
                              __nv_bfloat16* __restrict__ lo, int K, int N, int lstride) {
    __shared__ float t[32][33];
    const int l = blockIdx.z;
    const int n0 = blockIdx.x * 32, k0 = blockIdx.y * 32;
    const float* S = src + (size_t)l * K * N;
    const int tx = threadIdx.x, ty = threadIdx.y;
#pragma unroll
    for (int j = 0; j < 4; ++j)
        t[ty + j * 8][tx] = S[(size_t)(k0 + ty + j * 8) * N + n0 + tx];
    __syncthreads();
    __nv_bfloat16* Ht = hi + (size_t)l * lstride;
    __nv_bfloat16* Lt = lo + (size_t)l * lstride;
#pragma unroll
    for (int j = 0; j < 4; ++j) {
        int n = n0 + ty + j * 8;
        float v = t[tx][ty + j * 8];
        __nv_bfloat16 h = __float2bfloat16(v);
        Ht[(size_t)n * K + k0 + tx] = h;
        Lt[(size_t)n * K + k0 + tx] = __float2bfloat16(v - __bfloat162float(h));
    }
}

__global__ void build_gi_kernel(const int* __restrict__ rb) {
    int n = threadIdx.x;
    if (n < 1 || n >= NB_ - 1) return;
    int* p = g_gi + n * 8;
    p[0] = 0; p[1] = n - 1; p[2] = n; p[3] = n + 1; p[4] = NB_ - 1;
    p[5] = rb[n * 3 + 0]; p[6] = rb[n * 3 + 1]; p[7] = rb[n * 3 + 2];
}

__global__ void bcat_kernel(const float* __restrict__ bq, const float* __restrict__ bk,
                            const float* __restrict__ bv) {
    int i = blockIdx.x * blockDim.x + threadIdx.x;
    if (i >= L_ * NQKV) return;
    int l = i / NQKV, n = i % NQKV;
    float v = (n < 768) ? bq[l * 768 + n] : (n < 1536) ? bk[l * 768 + n - 768] : bv[l * 768 + n - 1536];
    g_bqkv[i] = v;
}

// ---------------- TMA + mma.sync bf16x3 GEMM, 128x128 CTA / 64x64 warp tiles ----------------
// 128 thr = 4 warps (2x2). Per ks: 16 ldsm.x4 for 96 HMMA (85 B smem per mma).
template<bool GELU, bool RES, bool SPLITOUT, bool WRITEF32>
__global__ __launch_bounds__(128, 1) void tgemm_kernel(
    const __grid_constant__ CUtensorMap tAh, const __grid_constant__ CUtensorMap tAl,
    const __grid_constant__ CUtensorMap tBh, const __grid_constant__ CUtensorMap tBl,
    const float* __restrict__ bias, const float* __restrict__ res,
    float* __restrict__ C, __nv_bfloat16* __restrict__ Chi, __nv_bfloat16* __restrict__ Clo,
    int N, int K, int layer)
{
    extern __shared__ char dsm[];
    const uint32_t ctl = s2u(dsm);
    const uint32_t tiles = (ctl + 64 + 1023) & ~1023u;
    const int tid = threadIdx.x;
    const int warp = tid >> 5, lane = tid & 31;
    const int wr = warp >> 1, wc = warp & 1;
    const int m0 = blockIdx.y * 128, n0 = blockIdx.x * 128;
    const int nch = K >> 6;

    if (tid == 0) {
        mbar_init(ctl, 1);
        mbar_init(ctl + 8, 1);
        asm volatile("fence.proxy.async.shared::cta;" ::: "memory");
    }
    __syncthreads();

    auto issue = [&](int i) {
        const int st = i & 1;
        const uint32_t mb = ctl + st * 8;
        const uint32_t tb = tiles + st * 65536;
        mbar_expect(mb, 65536);
        const int k0 = i << 6;
        tma2d(tb +     0, &tAh, k0, m0, mb);
        tma2d(tb + 16384, &tAl, k0, m0, mb);
        tma3d(tb + 32768, &tBh, k0, n0, layer, mb);
        tma3d(tb + 49152, &tBl, k0, n0, layer, mb);
    };
    const bool prod = (tid == 0);
    if (prod) { issue(0); issue(1); }

    float acc[4][8][4];
#pragma unroll
    for (int mi = 0; mi < 4; ++mi)
#pragma unroll
        for (int ni = 0; ni < 8; ++ni)
#pragma unroll
            for (int r = 0; r < 4; ++r) acc[mi][ni][r] = 0.f;

    const int lrow = lane & 15;
    const uint32_t hb16 = (lane >> 4) * 16;
    uint32_t arow[4], axr[4], brow[4], bxr[4];
#pragma unroll
    for (int mi = 0; mi < 4; ++mi) {
        int r = wr * 64 + mi * 16 + lrow;
        arow[mi] = r * 128; axr[mi] = (r & 7) * 16;
    }
#pragma unroll
    for (int np = 0; np < 4; ++np) {
        int r = wc * 64 + np * 16 + lrow;
        brow[np] = r * 128; bxr[np] = (r & 7) * 16;
    }

    for (int i = 0; i < nch; ++i) {
        const int st = i & 1;
        mbar_wait(ctl + st * 8, (i >> 1) & 1);
        const uint32_t bAh = tiles + st * 65536;
        const uint32_t bAl = bAh + 16384;
        const uint32_t bBh = bAh + 32768;
        const uint32_t bBl = bAh + 49152;
#pragma unroll
        for (int ks = 0; ks < 4; ++ks) {
            const uint32_t colb = ks * 32 + hb16;
            uint32_t ah[4][4], al[4][4];
#pragma unroll
            for (int mi = 0; mi < 4; ++mi) {
                ldsm4a(ah[mi], bAh + arow[mi] + (colb ^ axr[mi]));
                ldsm4a(al[mi], bAl + arow[mi] + (colb ^ axr[mi]));
            }
#pragma unroll
            for (int np = 0; np < 4; ++np) {
                uint32_t bh[4], bl[4];
                ldsm4a(bh, bBh + brow[np] + (colb ^ bxr[np]));
                ldsm4a(bl, bBl + brow[np] + (colb ^ bxr[np]));
#pragma unroll
                for (int j = 0; j < 2; ++j) {
                    const int ni = np * 2 + j;
#pragma unroll
                    for (int mi = 0; mi < 4; ++mi) {
                        mma16816(acc[mi][ni], ah[mi], bh[j], bh[j + 2]);
                        mma16816(acc[mi][ni], ah[mi], bl[j], bl[j + 2]);
                        mma16816(acc[mi][ni], al[mi], bh[j], bh[j + 2]);
                    }
                }
            }
        }
        __syncthreads();
        if (prod && i + 2 < nch) issue(i + 2);
    }

#pragma unroll
    for (int mi = 0; mi < 4; ++mi) {
        const int rbase = m0 + wr * 64 + mi * 16 + (lane >> 2);
#pragma unroll
        for (int ni = 0; ni < 8; ++ni) {
            const int cbase = n0 + wc * 64 + ni * 8 + (lane & 3) * 2;
            const float b0 = bias[cbase], b1 = bias[cbase + 1];
#pragma unroll
            for (int hr = 0; hr < 2; ++hr) {
                const int row = rbase + hr * 8;
                float v0 = acc[mi][ni][hr * 2 + 0] + b0;
                float v1 = acc[mi][ni][hr * 2 + 1] + b1;
                if (RES) {
                    v0 += res[(size_t)row * N + cbase];
                    v1 += res[(size_t)row * N + cbase + 1];
                }
                if (GELU) {
                    float u = v0;
                    v0 = 0.5f * u * (1.0f + tanhf(0.7978845608028654f * (u + 0.044715f * u * u * u)));
                    u = v1;
                    v1 = 0.5f * u * (1.0f + tanhf(0.7978845608028654f * (u + 0.044715f * u * u * u)));
                }
                const size_t idx = (size_t)row * N + cbase;
                if (WRITEF32) { C[idx] = v0; C[idx + 1] = v1; }
                if (SPLITOUT) {
                    __nv_bfloat16 h0 = __float2bfloat16(v0);
                    __nv_bfloat16 h1 = __float2bfloat16(v1);
                    Chi[idx] = h0; Chi[idx + 1] = h1;
                    Clo[idx]     = __float2bfloat16(v0 - __bfloat162float(h0));
                    Clo[idx + 1] = __float2bfloat16(v1 - __bfloat162float(h1));
                }
            }
        }
    }
}

// ---------------- LayerNorm ----------------
__global__ __launch_bounds__(256) void ln_kernel(
    const float* __restrict__ in, const float* __restrict__ gamma,
    const float* __restrict__ beta, float* __restrict__ out,
    __nv_bfloat16* __restrict__ ohi, __nv_bfloat16* __restrict__ olo,
    const float* __restrict__ pos, const float* __restrict__ tok)
{
    const int r = blockIdx.x, s = r % S_, t = threadIdx.x;
    const float* row = in + (size_t)r * D_;
    float x[3];
#pragma unroll
    for (int j = 0; j < 3; ++j) {
        int i = t + j * 256;
        float v = row[i];
        if (pos) v += pos[(size_t)s * D_ + i] + tok[i];
        x[j] = v;
    }
    float sum = x[0] + x[1] + x[2];
    float sq  = x[0] * x[0] + x[1] * x[1] + x[2] * x[2];
    __shared__ float rs[8], rq[8];
#pragma unroll
    for (int o = 16; o > 0; o >>= 1) {
        sum += __shfl_xor_sync(0xffffffffu, sum, o);
        sq  += __shfl_xor_sync(0xffffffffu, sq, o);
    }
    if ((t & 31) == 0) { rs[t >> 5] = sum; rq[t >> 5] = sq; }
    __syncthreads();
    if (t < 32) {
        float s2 = (t < 8) ? rs[t] : 0.f;
        float q2 = (t < 8) ? rq[t] : 0.f;
#pragma unroll
        for (int o = 4; o > 0; o >>= 1) {
            s2 += __shfl_xor_sync(0xffffffffu, s2, o);
            q2 += __shfl_xor_sync(0xffffffffu, q2, o);
        }
        if (t == 0) { rs[0] = s2; rq[0] = q2; }
    }
    __syncthreads();
    const float mean = rs[0] * (1.0f / 768.0f);
    float var = rq[0] * (1.0f / 768.0f) - mean * mean;
    const float rstd = rsqrtf(fmaxf(var, 0.f) + 1e-12f);
#pragma unroll
    for (int j = 0; j < 3; ++j) {
        int i = t + j * 256;
        float y = (x[j] - mean) * rstd * gamma[i] + beta[i];
        size_t idx = (size_t)r * D_ + i;
        out[idx] = y;
        __nv_bfloat16 h = __float2bfloat16(y);
        ohi[idx] = h;
        olo[idx] = __float2bfloat16(y - __bfloat162float(h));
    }
}

// ---------------- tensor-core block-sparse flash attention ----------------
__global__ __launch_bounds__(128, 3) void attn_tc_kernel(
    const __nv_bfloat16* __restrict__ qkvh, const __nv_bfloat16* __restrict__ qkvl,
    const float* __restrict__ mask)
{
    extern __shared__ char smraw[];
    const uint32_t su = s2u(smraw);
    const uint32_t QH = su, QL = su + 9216, KH = su + 18432, KL = su + 27648,
                   VH = su + 36864, VL = su + 46080;

    const int b = blockIdx.z, hh = blockIdx.y, ib = blockIdx.x;
    const int tid = threadIdx.x, warp = tid >> 5, lane = tid & 31;

    int qb, t0 = 0, e = 0, slice = 0;
    bool edge;
    if (ib < 62) { qb = ib + 1; edge = false; }
    else {
        edge = true;
        int xx = ib - 62;
        e = xx >> 3; slice = xx & 7;
        qb = e ? (NB_ - 1) : 0;
        t0 = slice * 8;
    }

    const int rrow = tid >> 1, half = tid & 1;
    {
        const size_t gq = (size_t)(b * S_ + qb * 64 + rrow) * NQKV + hh * 64 + half * 32;
        const uint4* s0 = (const uint4*)(qkvh + gq);
        const uint4* s1 = (const uint4*)(qkvl + gq);
        uint4* d0 = (uint4*)(smraw + rrow * 144 + half * 64);
        uint4* d1 = (uint4*)(smraw + 9216 + rrow * 144 + half * 64);
#pragma unroll
        for (int j = 0; j < 4; ++j) { d0[j] = s0[j]; d1[j] = s1[j]; }
    }

    float Sf[8][4], Of[8][4];
#pragma unroll
    for (int f = 0; f < 8; ++f)
#pragma unroll
        for (int r = 0; r < 4; ++r) Of[f][r] = 0.f;
    float m0 = -1e30f, m1 = -1e30f, l0 = 0.f, l1 = 0.f;

    const uint32_t lr15 = (lane & 15);
    const uint32_t hb = (lane >> 4);

    for (int kt = 0; kt < 8; ++kt) {
        const int kb = edge ? (t0 + kt) : g_gi[qb * 8 + kt];
        __syncthreads();
        {
            const size_t gk = (size_t)(b * S_ + kb * 64 + rrow) * NQKV + hh * 64 + half * 32;
            const uint4* kh = (const uint4*)(qkvh + gk + 768);
            const uint4* kl = (const uint4*)(qkvl + gk + 768);
            const uint4* vh = (const uint4*)(qkvh + gk + 1536);
            const uint4* vl = (const uint4*)(qkvl + gk + 1536);
            const int off = rrow * 144 + half * 64;
            uint4* dkh = (uint4*)(smraw + 18432 + off);
            uint4* dkl = (uint4*)(smraw + 27648 + off);
            uint4* dvh = (uint4*)(smraw + 36864 + off);
            uint4* dvl = (uint4*)(smraw + 46080 + off);
#pragma unroll
            for (int j = 0; j < 4; ++j) { dkh[j] = kh[j]; dkl[j] = kl[j]; dvh[j] = vh[j]; dvl[j] = vl[j]; }
        }
        __syncthreads();

#pragma unroll
        for (int f = 0; f < 8; ++f)
#pragma unroll
            for (int r = 0; r < 4; ++r) Sf[f][r] = 0.f;
#pragma unroll
        for (int ks = 0; ks < 4; ++ks) {
            const uint32_t colb = ks * 32 + hb * 16;
            const uint32_t qoff = (warp * 16 + lr15) * 144 + colb;
            uint32_t qh[4], ql[4];
            ldsm4a(qh, QH + qoff);
            ldsm4a(ql, QL + qoff);
#pragma unroll
            for (int np = 0; np < 4; ++np) {
                const uint32_t koff = (np * 16 + lr15) * 144 + colb;
                uint32_t kh[4], kl[4];
                ldsm4a(kh, KH + koff);
                ldsm4a(kl, KL + koff);
#pragma unroll
                for (int j = 0; j < 2; ++j) {
                    mma16816(Sf[np * 2 + j], qh, kh[j], kh[j + 2]);
                    mma16816(Sf[np * 2 + j], qh, kl[j], kl[j + 2]);
                    mma16816(Sf[np * 2 + j], ql, kh[j], kh[j + 2]);
                }
            }
        }

        const float* mrow = mask + (size_t)b * S_ + kb * 64;
        float t0m = -1e30f, t1m = -1e30f;
#pragma unroll
        for (int f = 0; f < 8; ++f) {
            const int c = f * 8 + 2 * (lane & 3);
            const float2 mk = *(const float2*)(mrow + c);
            Sf[f][0] = Sf[f][0] * 0.125f - 1e9f * (1.f - mk.x);
            Sf[f][1] = Sf[f][1] * 0.125f - 1e9f * (1.f - mk.y);
            Sf[f][2] = Sf[f][2] * 0.125f - 1e9f * (1.f - mk.x);
            Sf[f][3] = Sf[f][3] * 0.125f - 1e9f * (1.f - mk.y);
            t0m = fmaxf(t0m, fmaxf(Sf[f][0], Sf[f][1]));
            t1m = fmaxf(t1m, fmaxf(Sf[f][2], Sf[f][3]));
        }
        t0m = fmaxf(t0m, __shfl_xor_sync(0xffffffffu, t0m, 1));
        t0m = fmaxf(t0m, __shfl_xor_sync(0xffffffffu, t0m, 2));
        t1m = fmaxf(t1m, __shfl_xor_sync(0xffffffffu, t1m, 1));
        t1m = fmaxf(t1m, __shfl_xor_sync(0xffffffffu, t1m, 2));
        const float mn0 = fmaxf(m0, t0m), mn1 = fmaxf(m1, t1m);
        const float cr0 = __expf(m0 - mn0), cr1 = __expf(m1 - mn1);
        float ps0 = 0.f, ps1 = 0.f;
#pragma unroll
        for (int f = 0; f < 8; ++f) {
            Sf[f][0] = __expf(Sf[f][0] - mn0);
            Sf[f][1] = __expf(Sf[f][1] - mn0);
            Sf[f][2] = __expf(Sf[f][2] - mn1);
            Sf[f][3] = __expf(Sf[f][3] - mn1);
            ps0 += Sf[f][0] + Sf[f][1];
            ps1 += Sf[f][2] + Sf[f][3];
        }
        ps0 += __shfl_xor_sync(0xffffffffu, ps0, 1);
        ps0 += __shfl_xor_sync(0xffffffffu, ps0, 2);
        ps1 += __shfl_xor_sync(0xffffffffu, ps1, 1);
        ps1 += __shfl_xor_sync(0xffffffffu, ps1, 2);
        l0 = l0 * cr0 + ps0; m0 = mn0;
        l1 = l1 * cr1 + ps1; m1 = mn1;
#pragma unroll
        for (int f = 0; f < 8; ++f) {
            Of[f][0] *= cr0; Of[f][1] *= cr0; Of[f][2] *= cr1; Of[f][3] *= cr1;
        }

        uint32_t ph[4][4], pl[4][4];
#pragma unroll
        for (int j2 = 0; j2 < 4; ++j2) {
            const float* A = Sf[2 * j2];
            const float* Bq = Sf[2 * j2 + 1];
            float la, lb;
            __nv_bfloat162 t;
            t.x = __float2bfloat16(A[0]); t.y = __float2bfloat16(A[1]);
            la = A[0] - __bfloat162float(t.x); lb = A[1] - __bfloat162float(t.y);
            ph[j2][0] = *(uint32_t*)&t; pl[j2][0] = packbf2(la, lb);
            t.x = __float2bfloat16(A[2]); t.y = __float2bfloat16(A[3]);
            la = A[2] - __bfloat162float(t.x); lb = A[3] - __bfloat162float(t.y);
            ph[j2][1] = *(uint32_t*)&t; pl[j2][1] = packbf2(la, lb);
            t.x = __float2bfloat16(Bq[0]); t.y = __float2bfloat16(Bq[1]);
            la = Bq[0] - __bfloat162float(t.x); lb = Bq[1] - __bfloat162float(t.y);
            ph[j2][2] = *(uint32_t*)&t; pl[j2][2] = packbf2(la, lb);
            t.x = __float2bfloat16(Bq[2]); t.y = __float2bfloat16(Bq[3]);
            la = Bq[2] - __bfloat162float(t.x); lb = Bq[3] - __bfloat162float(t.y);
            ph[j2][3] = *(uint32_t*)&t; pl[j2][3] = packbf2(la, lb);
        }

#pragma unroll
        for (int ks2 = 0; ks2 < 4; ++ks2) {
#pragma unroll
            for (int g = 0; g < 4; ++g) {
                const uint32_t voff = (ks2 * 16 + lr15) * 144 + (g * 16 + hb * 8) * 2;
                uint32_t vh[4], vl[4];
                ldsm4t(vh, VH + voff);
                ldsm4t(vl, VL + voff);
#pragma unroll
                for (int j = 0; j < 2; ++j) {
                    mma16816(Of[g * 2 + j], ph[ks2], vh[2 * j], vh[2 * j + 1]);
                    mma16816(Of[g * 2 + j], ph[ks2], vl[2 * j], vl[2 * j + 1]);
                    mma16816(Of[g * 2 + j], pl[ks2], vh[2 * j], vh[2 * j + 1]);
                }
            }
        }
    }

    const int r0 = warp * 16 + (lane >> 2);
    if (!edge) {
        const float inv0 = 1.f / l0, inv1 = 1.f / l1;
        const size_t tk0 = (size_t)(b * S_ + qb * 64 + r0) * D_ + hh * 64;
        const size_t tk1 = tk0 + 8 * D_;
#pragma unroll
        for (int f = 0; f < 8; ++f) {
            const int c = f * 8 + 2 * (lane & 3);
            float v0 = Of[f][0] * inv0, v1 = Of[f][1] * inv0;
            float v2 = Of[f][2] * inv1, v3 = Of[f][3] * inv1;
            __nv_bfloat162 h01, h23, l01, l23;
            h01.x = __float2bfloat16(v0); h01.y = __float2bfloat16(v1);
            l01.x = __float2bfloat16(v0 - __bfloat162float(h01.x));
            l01.y = __float2bfloat16(v1 - __bfloat162float(h01.y));
            h23.x = __float2bfloat16(v2); h23.y = __float2bfloat16(v3);
            l23.x = __float2bfloat16(v2 - __bfloat162float(h23.x));
            l23.y = __float2bfloat16(v3 - __bfloat162float(h23.y));
            *(__nv_bfloat162*)(g_chi + tk0 + c) = h01;
            *(__nv_bfloat162*)(g_clo + tk0 + c) = l01;
            *(__nv_bfloat162*)(g_chi + tk1 + c) = h23;
            *(__nv_bfloat162*)(g_clo + tk1 + c) = l23;
        }
    } else {
        float* base = g_part + ((size_t)((((b * H_ + hh) * 2 + e) * 8 + slice) * 64)) * 66;
        float* pp0 = base + (size_t)r0 * 66;
        float* pp1 = base + (size_t)(r0 + 8) * 66;
#pragma unroll
        for (int f = 0; f < 8; ++f) {
            const int c = f * 8 + 2 * (lane & 3);
            pp0[c] = Of[f][0]; pp0[c + 1] = Of[f][1];
            pp1[c] = Of[f][2]; pp1[c + 1] = Of[f][3];
        }
        if ((lane & 3) == 0) {
            pp0[64] = m0; pp0[65] = l0;
            pp1[64] = m1; pp1[65] = l1;
        }
    }
}

__global__ __launch_bounds__(256) void merge_kernel() {
    const int e = blockIdx.x, hh = blockIdx.y, b = blockIdx.z;
    const int tid = threadIdx.x;
    const int r = tid >> 2, t4 = tid & 3;
    const size_t base = ((size_t)(((b * H_ + hh) * 2 + e) * 8)) * 64 * 66;

    float M = -1e30f;
#pragma unroll
    for (int s = 0; s < 8; ++s) M = fmaxf(M, g_part[base + ((size_t)s * 64 + r) * 66 + 64]);
    float L = 0.f, acc[16];
#pragma unroll
    for (int i = 0; i < 16; ++i) acc[i] = 0.f;
#pragma unroll
    for (int s = 0; s < 8; ++s) {
        const float* pp = g_part + base + ((size_t)s * 64 + r) * 66;
        const float w = __expf(pp[64] - M);
        L += pp[65] * w;
#pragma unroll
        for (int i = 0; i < 16; ++i) acc[i] += pp[t4 * 16 + i] * w;
    }
    const float inv = 1.0f / L;
    const int qb = e ? (NB_ - 1) : 0;
    const size_t idx = ((size_t)(b * S_ + qb * 64 + r)) * D_ + hh * 64 + t4 * 16;
#pragma unroll
    for (int i = 0; i < 16; ++i) {
        float vv = acc[i] * inv;
        __nv_bfloat16 h = __float2bfloat16(vv);
        g_chi[idx + i] = h;
        g_clo[idx + i] = __float2bfloat16(vv - __bfloat162float(h));
    }
}

// ---------------- classifier ----------------
__global__ void cls1_kernel(const float* __restrict__ h, const float* __restrict__ w,
                            const float* __restrict__ bias, float* __restrict__ out) {
    int gid = blockIdx.x * blockDim.x + threadIdx.x;
    if (gid >= 2 * 512) return;
    int b = gid >> 9, n = gid & 511;
    const float* hrow = h + (size_t)b * S_ * D_;
    float s = 0.f;
    for (int k2 = 0; k2 < D_; ++k2) s += hrow[k2] * w[(size_t)k2 * 512 + n];
    out[gid] = fmaxf(s + bias[n], 0.f);
}
__global__ void cls2_kernel(const float* __restrict__ rin, const float* __restrict__ w,
                            const float* __restrict__ bias, float* __restrict__ out) {
    int gid = blockIdx.x * blockDim.x + threadIdx.x;
    if (gid >= 2 * TGT_) return;
    int b = gid >> 10, n = gid & 1023;
    float s = 0.f;
    for (int k2 = 0; k2 < 512; ++k2) s += rin[b * 512 + k2] * w[(size_t)k2 * TGT_ + n];
    out[gid] = s + bias[n];
}

// ---------------- host ----------------
typedef CUresult (*EncFn)(CUtensorMap*, CUtensorMapDataType, cuuint32_t, void*,
                          const cuuint64_t*, const cuuint64_t*, const cuuint32_t*, const cuuint32_t*,
                          CUtensorMapInterleave, CUtensorMapSwizzle, CUtensorMapL2promotion,
                          CUtensorMapFloatOOBfill);

extern "C" void kernel_launch(void* const* d_in, const int* in_sizes, int n_in,
                              void* d_out, int out_size)
{
    const float* x        = (const float*)d_in[0];
    const float* mask     = (const float*)d_in[1];
    const float* proj_b   = (const float*)d_in[3];
    const float* pos_emb  = (const float*)d_in[4];
    const float* tok_emb  = (const float*)d_in[5];
    const float* emb_g    = (const float*)d_in[6];
    const float* emb_b    = (const float*)d_in[7];
    const float* bq_all   = (const float*)d_in[9];
    const float* bk_all   = (const float*)d_in[11];
    const float* bv_all   = (const float*)d_in[13];
    const float* bo_all   = (const float*)d_in[15];
    const float* ln1g_all = (const float*)d_in[16];
    const float* ln1b_all = (const float*)d_in[17];
    const float* bi_all   = (const float*)d_in[19];
    const float* bo2_all  = (const float*)d_in[21];
    const float* ln2g_all = (const float*)d_in[22];
    const float* ln2b_all = (const float*)d_in[23];
    const float* cls_w1   = (const float*)d_in[24];
    const float* cls_b1   = (const float*)d_in[25];
    const float* cls_w2   = (const float*)d_in[26];
    const float* cls_b2   = (const float*)d_in[27];
    const int*   rb       = (const int*)d_in[28];
    float* out = (float*)d_out;

    float *ph, *ptmp, *pcls, *pbqkv;
    __nv_bfloat16 *pwhi, *pwlo, *pxhi, *pxlo, *phhi, *phlo, *pchi, *pclo, *pfhi, *pflo, *pqvh, *pqvl;
    cudaGetSymbolAddress((void**)&ph,   g_h);
    cudaGetSymbolAddress((void**)&ptmp, g_tmp);
    cudaGetSymbolAddress((void**)&pcls, g_cls);
    cudaGetSymbolAddress((void**)&pbqkv, g_bqkv);
    cudaGetSymbolAddress((void**)&pwhi, g_whi);
    cudaGetSymbolAddress((void**)&pwlo, g_wlo);
    cudaGetSymbolAddress((void**)&pxhi, g_xhi);
    cudaGetSymbolAddress((void**)&pxlo, g_xlo);
    cudaGetSymbolAddress((void**)&phhi, g_hhi);
    cudaGetSymbolAddress((void**)&phlo, g_hlo);
    cudaGetSymbolAddress((void**)&pchi, g_chi);
    cudaGetSymbolAddress((void**)&pclo, g_clo);
    cudaGetSymbolAddress((void**)&pfhi, g_fhi);
    cudaGetSymbolAddress((void**)&pflo, g_flo);
    cudaGetSymbolAddress((void**)&pqvh, g_qkvhi);
    cudaGetSymbolAddress((void**)&pqvl, g_qkvlo);

    EncFn enc = nullptr;
    cudaDriverEntryPointQueryResult qr;
    cudaGetDriverEntryPointByVersion("cuTensorMapEncodeTiled", (void**)&enc, 12000,
                                     cudaEnableDefault, &qr);

    auto mk2 = [&](CUtensorMap* m, void* p, uint64_t K) {
        cuuint64_t d[2] = {K, T_};
        cuuint64_t st[1] = {K * 2};
        cuuint32_t bx[2] = {64, 128}, es[2] = {1, 1};
        enc(m, CU_TENSOR_MAP_DATA_TYPE_BFLOAT16, 2, p, d, st, bx, es,
            CU_TENSOR_MAP_INTERLEAVE_NONE, CU_TENSOR_MAP_SWIZZLE_128B,
            CU_TENSOR_MAP_L2_PROMOTION_L2_128B, CU_TENSOR_MAP_FLOAT_OOB_FILL_NONE);
    };
    auto mk3 = [&](CUtensorMap* m, void* p, uint64_t K, uint64_t N, uint64_t Lz) {
        cuuint64_t d[3] = {K, N, Lz};
        cuuint64_t st[2] = {K * 2, N * K * 2};
        cuuint32_t bx[3] = {64, 128, 1}, es[3] = {1, 1, 1};
        enc(m, CU_TENSOR_MAP_DATA_TYPE_BFLOAT16, 3, p, d, st, bx, es,
            CU_TENSOR_MAP_INTERLEAVE_NONE, CU_TENSOR_MAP_SWIZZLE_128B,
            CU_TENSOR_MAP_L2_PROMOTION_L2_128B, CU_TENSOR_MAP_FLOAT_OOB_FILL_NONE);
    };

    CUtensorMap mxh, mxl, mhh, mhl, mch, mcl, mfh, mfl;
    CUtensorMap mpjh, mpjl, mqkvh, mqkvl, moh, mol, mih, mil, m2h, m2l;
    mk2(&mxh, pxhi, IN_); mk2(&mxl, pxlo, IN_);
    mk2(&mhh, phhi, D_);  mk2(&mhl, phlo, D_);
    mk2(&mch, pchi, D_);  mk2(&mcl, pclo, D_);
    mk2(&mfh, pfhi, FF_); mk2(&mfl, pflo, FF_);
    mk3(&mpjh, pwhi + OFF_PROJ, IN_, D_, 1);   mk3(&mpjl, pwlo + OFF_PROJ, IN_, D_, 1);
    mk3(&mqkvh, pwhi + OFF_QKV, D_, NQKV, L_); mk3(&mqkvl, pwlo + OFF_QKV, D_, NQKV, L_);
    mk3(&moh, pwhi + OFF_WO, D_, D_, L_);      mk3(&mol, pwlo + OFF_WO, D_, D_, L_);
    mk3(&mih, pwhi + OFF_WI, D_, FF_, L_);     mk3(&mil, pwlo + OFF_WI, D_, FF_, L_);
    mk3(&m2h, pwhi + OFF_WO2, FF_, D_, L_);    mk3(&m2l, pwlo + OFF_WO2, FF_, D_, L_);

    cudaFuncSetAttribute(tgemm_kernel<false, false, false, true>,
                         cudaFuncAttributeMaxDynamicSharedMemorySize, GEMM_SMEM);
    cudaFuncSetAttribute(tgemm_kernel<false, false, true, false>,
                         cudaFuncAttributeMaxDynamicSharedMemorySize, GEMM_SMEM);
    cudaFuncSetAttribute(tgemm_kernel<false, true, false, true>,
                         cudaFuncAttributeMaxDynamicSharedMemorySize, GEMM_SMEM);
    cudaFuncSetAttribute(tgemm_kernel<true, false, true, false>,
                         cudaFuncAttributeMaxDynamicSharedMemorySize, GEMM_SMEM);
    cudaFuncSetAttribute(attn_tc_kernel,
                         cudaFuncAttributeMaxDynamicSharedMemorySize, ATTN_SMEM);

    // prep
    dim3 tb(32, 8);
    tsplit_kernel<<<dim3(D_ / 32, IN_ / 32, 1), tb>>>((const float*)d_in[2], pwhi + OFF_PROJ, pwlo + OFF_PROJ, IN_, D_, IN_ * D_);
    tsplit_kernel<<<dim3(D_ / 32, D_ / 32, L_), tb>>>((const float*)d_in[8],  pwhi + OFF_QKV,               pwlo + OFF_QKV,               D_, D_, NQKV * D_);
    tsplit_kernel<<<dim3(D_ / 32, D_ / 32, L_), tb>>>((const float*)d_in[10], pwhi + OFF_QKV + 768 * 768,   pwlo + OFF_QKV + 768 * 768,   D_, D_, NQKV * D_);
    tsplit_kernel<<<dim3(D_ / 32, D_ / 32, L_), tb>>>((const float*)d_in[12], pwhi + OFF_QKV + 2 * 768 * 768, pwlo + OFF_QKV + 2 * 768 * 768, D_, D_, NQKV * D_);
    tsplit_kernel<<<dim3(D_ / 32, D_ / 32, L_), tb>>>((const float*)d_in[14], pwhi + OFF_WO, pwlo + OFF_WO, D_, D_, D_ * D_);
    tsplit_kernel<<<dim3(FF_ / 32, D_ / 32, L_), tb>>>((const float*)d_in[18], pwhi + OFF_WI, pwlo + OFF_WI, D_, FF_, D_ * FF_);
    tsplit_kernel<<<dim3(D_ / 32, FF_ / 32, L_), tb>>>((const float*)d_in[20], pwhi + OFF_WO2, pwlo + OFF_WO2, FF_, D_, FF_ * D_);
    split_kernel<<<(T_ * IN_ + 255) / 256, 256>>>(x, pxhi, pxlo, T_ * IN_);
    build_gi_kernel<<<1, 64>>>(rb);
    bcat_kernel<<<(L_ * NQKV + 255) / 256, 256>>>(bq_all, bk_all, bv_all);

    const dim3 gD(D_ / 128, T_ / 128);
    const dim3 gQKV(NQKV / 128, T_ / 128);
    const dim3 gF(FF_ / 128, T_ / 128);
    const dim3 gA(78, H_, B_);
    const dim3 gM(2, H_, B_);

    tgemm_kernel<false, false, false, true><<<gD, 128, GEMM_SMEM>>>(
        mxh, mxl, mpjh, mpjl, proj_b, nullptr, ptmp, nullptr, nullptr, D_, IN_, 0);
    ln_kernel<<<T_, 256>>>(ptmp, emb_g, emb_b, ph, phhi, phlo, pos_emb, tok_emb);

    for (int l = 0; l < L_; ++l) {
        tgemm_kernel<false, false, true, false><<<gQKV, 128, GEMM_SMEM>>>(
            mhh, mhl, mqkvh, mqkvl, pbqkv + (size_t)l * NQKV, nullptr,
            nullptr, pqvh, pqvl, NQKV, D_, l);

        attn_tc_kernel<<<gA, 128, ATTN_SMEM>>>(pqvh, pqvl, mask);
        merge_kernel<<<gM, 256>>>();

        tgemm_kernel<false, true, false, true><<<gD, 128, GEMM_SMEM>>>(
            mch, mcl, moh, mol, bo_all + (size_t)l * D_, ph, ptmp, nullptr, nullptr, D_, D_, l);
        ln_kernel<<<T_, 256>>>(ptmp, ln1g_all + (size_t)l * D_, ln1b_all + (size_t)l * D_,
                               ph, phhi, phlo, nullptr, nullptr);

        tgemm_kernel<true, false, true, false><<<gF, 128, GEMM_SMEM>>>(
            mhh, mhl, mih, mil, bi_all + (size_t)l * FF_, nullptr, nullptr, pfhi, pflo, FF_, D_, l);
        tgemm_kernel<false, true, false, true><<<gD, 128, GEMM_SMEM>>>(
            mfh, mfl, m2h, m2l, bo2_all + (size_t)l * D_, ph, ptmp, nullptr, nullptr, D_, FF_, l);
        ln_kernel<<<T_, 256>>>(ptmp, ln2g_all + (size_t)l * D_, ln2b_all + (size_t)l * D_,
                               ph, phhi, phlo, nullptr, nullptr);
    }

    cls1_kernel<<<4, 256>>>(ph, cls_w1, cls_b1, pcls);
    cls2_kernel<<<8, 256>>>(pcls, cls_w2, cls_b2, out);
}

// round 9
// speedup vs baseline: 1.1517x; 1.1514x over previous
#include <cuda_runtime.h>
#include <cuda.h>
#include <cuda_bf16.h>
#include <math.h>
#include <stdint.h>

#define B_    2
#define S_    4096
#define T_    8192
#define IN_   1280
#define D_    768
#define H_    12
#define FF_   3072
#define L_    12
#define TGT_  1024
#define NB_   64
#define NQKV  2304

// weight arena (element offsets, [N,K] transposed planes)
#define OFF_PROJ 0
#define OFF_QKV  (IN_*D_)
#define OFF_WO   (OFF_QKV + L_*NQKV*D_)
#define OFF_WI   (OFF_WO + L_*D_*D_)
#define OFF_WO2  (OFF_WI + L_*D_*FF_)
#define WTOT     (OFF_WO2 + L_*FF_*D_)

#define GEMM_SMEM 133120
#define ATTN_SMEM 55296

// ---------------- scratch ----------------
__device__ float g_h[T_ * D_];
__device__ float g_tmp[T_ * D_];
__device__ float g_cls[2 * 512];
__device__ float g_bqkv[L_ * NQKV];
__device__ int   g_gi[NB_ * 8];

__device__ __align__(128) __nv_bfloat16 g_whi[WTOT];
__device__ __align__(128) __nv_bfloat16 g_wlo[WTOT];
__device__ __align__(128) __nv_bfloat16 g_xhi[T_ * IN_];
__device__ __align__(128) __nv_bfloat16 g_xlo[T_ * IN_];
__device__ __align__(128) __nv_bfloat16 g_hhi[T_ * D_];
__device__ __align__(128) __nv_bfloat16 g_hlo[T_ * D_];
__device__ __align__(128) __nv_bfloat16 g_chi[T_ * D_];
__device__ __align__(128) __nv_bfloat16 g_clo[T_ * D_];
__device__ __align__(128) __nv_bfloat16 g_fhi[T_ * FF_];
__device__ __align__(128) __nv_bfloat16 g_flo[T_ * FF_];
__device__ __align__(128) __nv_bfloat16 g_qkvhi[T_ * NQKV];
__device__ __align__(128) __nv_bfloat16 g_qkvlo[T_ * NQKV];
__device__ float g_part[B_ * H_ * 2 * 8 * 64 * 66];

// ---------------- PTX helpers ----------------
__device__ __forceinline__ uint32_t s2u(const void* p) { return (uint32_t)__cvta_generic_to_shared(p); }
__device__ __forceinline__ void mbar_init(uint32_t a, uint32_t c) {
    asm volatile("mbarrier.init.shared.b64 [%0], %1;" :: "r"(a), "r"(c) : "memory");
}
__device__ __forceinline__ void mbar_expect(uint32_t a, uint32_t b) {
    asm volatile("mbarrier.arrive.expect_tx.shared.b64 _, [%0], %1;" :: "r"(a), "r"(b) : "memory");
}
__device__ __forceinline__ void mbar_wait(uint32_t a, uint32_t par) {
    asm volatile("{\n\t.reg .pred P;\n\tW_%=:\n\t"
                 "mbarrier.try_wait.parity.acquire.cta.shared::cta.b64 P, [%0], %1, 0x989680;\n\t"
                 "@P bra.uni D_%=;\n\tbra.uni W_%=;\n\tD_%=:\n\t}" :: "r"(a), "r"(par) : "memory");
}
__device__ __forceinline__ void tma2d(uint32_t dst, const void* tm, int x, int y, uint32_t mb) {
    asm volatile("cp.async.bulk.tensor.2d.shared::cta.global.tile.mbarrier::complete_tx::bytes "
                 "[%0], [%1, {%2, %3}], [%4];" :: "r"(dst), "l"(tm), "r"(x), "r"(y), "r"(mb) : "memory");
}
__device__ __forceinline__ void tma3d(uint32_t dst, const void* tm, int x, int y, int z, uint32_t mb) {
    asm volatile("cp.async.bulk.tensor.3d.shared::cta.global.tile.mbarrier::complete_tx::bytes "
                 "[%0], [%1, {%2, %3, %4}], [%5];" :: "r"(dst), "l"(tm), "r"(x), "r"(y), "r"(z), "r"(mb) : "memory");
}
__device__ __forceinline__ void ldsm4a(uint32_t* r, uint32_t a) {
    asm volatile("ldmatrix.sync.aligned.m8n8.x4.shared.b16 {%0,%1,%2,%3}, [%4];"
                 : "=r"(r[0]), "=r"(r[1]), "=r"(r[2]), "=r"(r[3]) : "r"(a));
}
__device__ __forceinline__ void ldsm4t(uint32_t* r, uint32_t a) {
    asm volatile("ldmatrix.sync.aligned.m8n8.x4.trans.shared.b16 {%0,%1,%2,%3}, [%4];"
                 : "=r"(r[0]), "=r"(r[1]), "=r"(r[2]), "=r"(r[3]) : "r"(a));
}
__device__ __forceinline__ void mma16816(float* d, const uint32_t* a, uint32_t b0, uint32_t b1) {
    asm volatile("mma.sync.aligned.m16n8k16.row.col.f32.bf16.bf16.f32 "
                 "{%0,%1,%2,%3}, {%4,%5,%6,%7}, {%8,%9}, {%0,%1,%2,%3};"
                 : "+f"(d[0]), "+f"(d[1]), "+f"(d[2]), "+f"(d[3])
                 : "r"(a[0]), "r"(a[1]), "r"(a[2]), "r"(a[3]), "r"(b0), "r"(b1));
}
__device__ __forceinline__ uint32_t packbf2(float lo_e, float hi_e) {
    __nv_bfloat162 t;
    t.x = __float2bfloat16(lo_e);
    t.y = __float2bfloat16(hi_e);
    return *(uint32_t*)&t;
}

// ---------------- prep kernels ----------------
__global__ void split_kernel(const float* __restrict__ s, __nv_bfloat16* __restrict__ hi,
                             __nv_bfloat16* __restrict__ lo, int n) {
    int i = blockIdx.x * blockDim.x + threadIdx.x;
    if (i >= n) return;
    float v = s[i];
    __nv_bfloat16 h = __float2bfloat16(v);
    hi[i] = h;
    lo[i] = __float2bfloat16(v - __bfloat162float(h));
}

__global__ void tsplit_kernel(const float* __restrict__ src, __nv_bfloat16* __restrict__ hi,
                              __nv_bfloat16* __restrict__ lo, int K, int N, int lstride) {
    __shared__ float t[32][33];
    const int l = blockIdx.z;
    const int n0 = blockIdx.x * 32, k0 = blockIdx.y * 32;
    const float* S = src + (size_t)l * K * N;
    const int tx = threadIdx.x, ty = threadIdx.y;
#pragma unroll
    for (int j = 0; j < 4; ++j)
        t[ty + j * 8][tx] = S[(size_t)(k0 + ty + j * 8) * N + n0 + tx];
    __syncthreads();
    __nv_bfloat16* Ht = hi + (size_t)l * lstride;
    __nv_bfloat16* Lt = lo + (size_t)l * lstride;
#pragma unroll
    for (int j = 0; j < 4; ++j) {
        int n = n0 + ty + j * 8;
        float v = t[tx][ty + j * 8];
        __nv_bfloat16 h = __float2bfloat16(v);
        Ht[(size_t)n * K + k0 + tx] = h;
        Lt[(size_t)n * K + k0 + tx] = __float2bfloat16(v - __bfloat162float(h));
    }
}

__global__ void build_gi_kernel(const int* __restrict__ rb) {
    int n = threadIdx.x;
    if (n < 1 || n >= NB_ - 1) return;
    int* p = g_gi + n * 8;
    p[0] = 0; p[1] = n - 1; p[2] = n; p[3] = n + 1; p[4] = NB_ - 1;
    p[5] = rb[n * 3 + 0]; p[6] = rb[n * 3 + 1]; p[7] = rb[n * 3 + 2];
}

__global__ void bcat_kernel(const float* __restrict__ bq, const float* __restrict__ bk,
                            const float* __restrict__ bv) {
    int i = blockIdx.x * blockDim.x + threadIdx.x;
    if (i >= L_ * NQKV) return;
    int l = i / NQKV, n = i % NQKV;
    float v = (n < 768) ? bq[l * 768 + n] : (n < 1536) ? bk[l * 768 + n - 768] : bv[l * 768 + n - 1536];
    g_bqkv[i] = v;
}

// ---------------- TMA + mma.sync bf16 GEMM (3-plane or 2-plane) ----------------
// CTA 128x128, 256 thr = 8 warps (4x2 of 32x64). K64 chunks, double buffered.
template<bool GELU, bool RES, bool SPLITOUT, bool WRITEF32, bool THIRD>
__global__ __launch_bounds__(256, 1) void tgemm_kernel(
    const __grid_constant__ CUtensorMap tAh, const __grid_constant__ CUtensorMap tAl,
    const __grid_constant__ CUtensorMap tBh, const __grid_constant__ CUtensorMap tBl,
    const float* __restrict__ bias, const float* __restrict__ res,
    float* __restrict__ C, __nv_bfloat16* __restrict__ Chi, __nv_bfloat16* __restrict__ Clo,
    int N, int K, int layer)
{
    extern __shared__ char dsm[];
    const uint32_t ctl = s2u(dsm);
    const uint32_t tiles = (ctl + 64 + 1023) & ~1023u;
    const int tid = threadIdx.x;
    const int warp = tid >> 5, lane = tid & 31;
    const int wr = warp >> 1, wc = warp & 1;
    const int m0 = blockIdx.y * 128, n0 = blockIdx.x * 128;
    const int nch = K >> 6;

    if (tid == 0) {
        mbar_init(ctl, 1);
        mbar_init(ctl + 8, 1);
        asm volatile("fence.proxy.async.shared::cta;" ::: "memory");
    }
    __syncthreads();

    auto issue = [&](int i) {
        const int st = i & 1;
        const uint32_t mb = ctl + st * 8;
        const uint32_t tb = tiles + st * 65536;
        mbar_expect(mb, THIRD ? 65536 : 49152);
        const int k0 = i << 6;
        tma2d(tb +     0, &tAh, k0, m0, mb);
        if (THIRD) tma2d(tb + 16384, &tAl, k0, m0, mb);
        tma3d(tb + 32768, &tBh, k0, n0, layer, mb);
        tma3d(tb + 49152, &tBl, k0, n0, layer, mb);
    };
    const bool prod = (tid == 0);
    if (prod) { issue(0); issue(1); }

    float acc[2][8][4];
#pragma unroll
    for (int mi = 0; mi < 2; ++mi)
#pragma unroll
        for (int ni = 0; ni < 8; ++ni)
#pragma unroll
            for (int r = 0; r < 4; ++r) acc[mi][ni][r] = 0.f;

    const int lrow = lane & 15;
    const uint32_t hb16 = (lane >> 4) * 16;
    uint32_t arow[2], axr[2], brow[4], bxr[4];
#pragma unroll
    for (int mi = 0; mi < 2; ++mi) {
        int r = wr * 32 + mi * 16 + lrow;
        arow[mi] = r * 128; axr[mi] = (r & 7) * 16;
    }
#pragma unroll
    for (int np = 0; np < 4; ++np) {
        int r = wc * 64 + np * 16 + lrow;
        brow[np] = r * 128; bxr[np] = (r & 7) * 16;
    }

    for (int i = 0; i < nch; ++i) {
        const int st = i & 1;
        mbar_wait(ctl + st * 8, (i >> 1) & 1);
        const uint32_t bAh = tiles + st * 65536;
        const uint32_t bAl = bAh + 16384;
        const uint32_t bBh = bAh + 32768;
        const uint32_t bBl = bAh + 49152;
#pragma unroll
        for (int ks = 0; ks < 4; ++ks) {
            const uint32_t colb = ks * 32 + hb16;
            uint32_t ah[2][4], al[2][4];
#pragma unroll
            for (int mi = 0; mi < 2; ++mi) {
                ldsm4a(ah[mi], bAh + arow[mi] + (colb ^ axr[mi]));
                if (THIRD) ldsm4a(al[mi], bAl + arow[mi] + (colb ^ axr[mi]));
            }
#pragma unroll
            for (int np = 0; np < 4; ++np) {
                uint32_t bh[4], bl[4];
                ldsm4a(bh, bBh + brow[np] + (colb ^ bxr[np]));
                ldsm4a(bl, bBl + brow[np] + (colb ^ bxr[np]));
#pragma unroll
                for (int j = 0; j < 2; ++j) {
                    const int ni = np * 2 + j;
#pragma unroll
                    for (int mi = 0; mi < 2; ++mi) {
                        mma16816(acc[mi][ni], ah[mi], bh[j], bh[j + 2]);
                        mma16816(acc[mi][ni], ah[mi], bl[j], bl[j + 2]);
                        if (THIRD) mma16816(acc[mi][ni], al[mi], bh[j], bh[j + 2]);
                    }
                }
            }
        }
        __syncthreads();
        if (prod && i + 2 < nch) issue(i + 2);
    }

#pragma unroll
    for (int mi = 0; mi < 2; ++mi) {
        const int rbase = m0 + wr * 32 + mi * 16 + (lane >> 2);
#pragma unroll
        for (int ni = 0; ni < 8; ++ni) {
            const int cbase = n0 + wc * 64 + ni * 8 + (lane & 3) * 2;
            const float b0 = bias[cbase], b1 = bias[cbase + 1];
#pragma unroll
            for (int hr = 0; hr < 2; ++hr) {
                const int row = rbase + hr * 8;
                float v0 = acc[mi][ni][hr * 2 + 0] + b0;
                float v1 = acc[mi][ni][hr * 2 + 1] + b1;
                if (RES) {
                    v0 += res[(size_t)row * N + cbase];
                    v1 += res[(size_t)row * N + cbase + 1];
                }
                if (GELU) {
                    float u = v0;
                    v0 = 0.5f * u * (1.0f + tanhf(0.7978845608028654f * (u + 0.044715f * u * u * u)));
                    u = v1;
                    v1 = 0.5f * u * (1.0f + tanhf(0.7978845608028654f * (u + 0.044715f * u * u * u)));
                }
                const size_t idx = (size_t)row * N + cbase;
                if (WRITEF32) { C[idx] = v0; C[idx + 1] = v1; }
                if (SPLITOUT) {
                    __nv_bfloat16 h0 = __float2bfloat16(v0);
                    __nv_bfloat16 h1 = __float2bfloat16(v1);
                    Chi[idx] = h0; Chi[idx + 1] = h1;
                    Clo[idx]     = __float2bfloat16(v0 - __bfloat162float(h0));
                    Clo[idx + 1] = __float2bfloat16(v1 - __bfloat162float(h1));
                }
            }
        }
    }
}

// ---------------- LayerNorm ----------------
__global__ __launch_bounds__(256) void ln_kernel(
    const float* __restrict__ in, const float* __restrict__ gamma,
    const float* __restrict__ beta, float* __restrict__ out,
    __nv_bfloat16* __restrict__ ohi, __nv_bfloat16* __restrict__ olo,
    const float* __restrict__ pos, const float* __restrict__ tok)
{
    const int r = blockIdx.x, s = r % S_, t = threadIdx.x;
    const float* row = in + (size_t)r * D_;
    float x[3];
#pragma unroll
    for (int j = 0; j < 3; ++j) {
        int i = t + j * 256;
        float v = row[i];
        if (pos) v += pos[(size_t)s * D_ + i] + tok[i];
        x[j] = v;
    }
    float sum = x[0] + x[1] + x[2];
    float sq  = x[0] * x[0] + x[1] * x[1] + x[2] * x[2];
    __shared__ float rs[8], rq[8];
#pragma unroll
    for (int o = 16; o > 0; o >>= 1) {
        sum += __shfl_xor_sync(0xffffffffu, sum, o);
        sq  += __shfl_xor_sync(0xffffffffu, sq, o);
    }
    if ((t & 31) == 0) { rs[t >> 5] = sum; rq[t >> 5] = sq; }
    __syncthreads();
    if (t < 32) {
        float s2 = (t < 8) ? rs[t] : 0.f;
        float q2 = (t < 8) ? rq[t] : 0.f;
#pragma unroll
        for (int o = 4; o > 0; o >>= 1) {
            s2 += __shfl_xor_sync(0xffffffffu, s2, o);
            q2 += __shfl_xor_sync(0xffffffffu, q2, o);
        }
        if (t == 0) { rs[0] = s2; rq[0] = q2; }
    }
    __syncthreads();
    const float mean = rs[0] * (1.0f / 768.0f);
    float var = rq[0] * (1.0f / 768.0f) - mean * mean;
    const float rstd = rsqrtf(fmaxf(var, 0.f) + 1e-12f);
#pragma unroll
    for (int j = 0; j < 3; ++j) {
        int i = t + j * 256;
        float y = (x[j] - mean) * rstd * gamma[i] + beta[i];
        size_t idx = (size_t)r * D_ + i;
        out[idx] = y;
        __nv_bfloat16 h = __float2bfloat16(y);
        ohi[idx] = h;
        olo[idx] = __float2bfloat16(y - __bfloat162float(h));
    }
}

// ---------------- tensor-core block-sparse flash attention ----------------
__global__ __launch_bounds__(128, 3) void attn_tc_kernel(
    const __nv_bfloat16* __restrict__ qkvh, const __nv_bfloat16* __restrict__ qkvl,
    const float* __restrict__ mask)
{
    extern __shared__ char smraw[];
    const uint32_t su = s2u(smraw);
    const uint32_t QH = su, QL = su + 9216, KH = su + 18432, KL = su + 27648,
                   VH = su + 36864, VL = su + 46080;

    const int b = blockIdx.z, hh = blockIdx.y, ib = blockIdx.x;
    const int tid = threadIdx.x, warp = tid >> 5, lane = tid & 31;

    int qb, t0 = 0, e = 0, slice = 0;
    bool edge;
    if (ib < 62) { qb = ib + 1; edge = false; }
    else {
        edge = true;
        int xx = ib - 62;
        e = xx >> 3; slice = xx & 7;
        qb = e ? (NB_ - 1) : 0;
        t0 = slice * 8;
    }

    const int rrow = tid >> 1, half = tid & 1;
    {
        const size_t gq = (size_t)(b * S_ + qb * 64 + rrow) * NQKV + hh * 64 + half * 32;
        const uint4* s0 = (const uint4*)(qkvh + gq);
        const uint4* s1 = (const uint4*)(qkvl + gq);
        uint4* d0 = (uint4*)(smraw + rrow * 144 + half * 64);
        uint4* d1 = (uint4*)(smraw + 9216 + rrow * 144 + half * 64);
#pragma unroll
        for (int j = 0; j < 4; ++j) { d0[j] = s0[j]; d1[j] = s1[j]; }
    }

    float Sf[8][4], Of[8][4];
#pragma unroll
    for (int f = 0; f < 8; ++f)
#pragma unroll
        for (int r = 0; r < 4; ++r) Of[f][r] = 0.f;
    float m0 = -1e30f, m1 = -1e30f, l0 = 0.f, l1 = 0.f;

    const uint32_t lr15 = (lane & 15);
    const uint32_t hb = (lane >> 4);

    for (int kt = 0; kt < 8; ++kt) {
        const int kb = edge ? (t0 + kt) : g_gi[qb * 8 + kt];
        __syncthreads();
        {
            const size_t gk = (size_t)(b * S_ + kb * 64 + rrow) * NQKV + hh * 64 + half * 32;
            const uint4* kh = (const uint4*)(qkvh + gk + 768);
            const uint4* kl = (const uint4*)(qkvl + gk + 768);
            const uint4* vh = (const uint4*)(qkvh + gk + 1536);
            const uint4* vl = (const uint4*)(qkvl + gk + 1536);
            const int off = rrow * 144 + half * 64;
            uint4* dkh = (uint4*)(smraw + 18432 + off);
            uint4* dkl = (uint4*)(smraw + 27648 + off);
            uint4* dvh = (uint4*)(smraw + 36864 + off);
            uint4* dvl = (uint4*)(smraw + 46080 + off);
#pragma unroll
            for (int j = 0; j < 4; ++j) { dkh[j] = kh[j]; dkl[j] = kl[j]; dvh[j] = vh[j]; dvl[j] = vl[j]; }
        }
        __syncthreads();

#pragma unroll
        for (int f = 0; f < 8; ++f)
#pragma unroll
            for (int r = 0; r < 4; ++r) Sf[f][r] = 0.f;
#pragma unroll
        for (int ks = 0; ks < 4; ++ks) {
            const uint32_t colb = ks * 32 + hb * 16;
            const uint32_t qoff = (warp * 16 + lr15) * 144 + colb;
            uint32_t qh[4], ql[4];
            ldsm4a(qh, QH + qoff);
            ldsm4a(ql, QL + qoff);
#pragma unroll
            for (int np = 0; np < 4; ++np) {
                const uint32_t koff = (np * 16 + lr15) * 144 + colb;
                uint32_t kh[4], kl[4];
                ldsm4a(kh, KH + koff);
                ldsm4a(kl, KL + koff);
#pragma unroll
                for (int j = 0; j < 2; ++j) {
                    mma16816(Sf[np * 2 + j], qh, kh[j], kh[j + 2]);
                    mma16816(Sf[np * 2 + j], qh, kl[j], kl[j + 2]);
                    mma16816(Sf[np * 2 + j], ql, kh[j], kh[j + 2]);
                }
            }
        }

        const float* mrow = mask + (size_t)b * S_ + kb * 64;
        float t0m = -1e30f, t1m = -1e30f;
#pragma unroll
        for (int f = 0; f < 8; ++f) {
            const int c = f * 8 + 2 * (lane & 3);
            const float2 mk = *(const float2*)(mrow + c);
            Sf[f][0] = Sf[f][0] * 0.125f - 1e9f * (1.f - mk.x);
            Sf[f][1] = Sf[f][1] * 0.125f - 1e9f * (1.f - mk.y);
            Sf[f][2] = Sf[f][2] * 0.125f - 1e9f * (1.f - mk.x);
            Sf[f][3] = Sf[f][3] * 0.125f - 1e9f * (1.f - mk.y);
            t0m = fmaxf(t0m, fmaxf(Sf[f][0], Sf[f][1]));
            t1m = fmaxf(t1m, fmaxf(Sf[f][2], Sf[f][3]));
        }
        t0m = fmaxf(t0m, __shfl_xor_sync(0xffffffffu, t0m, 1));
        t0m = fmaxf(t0m, __shfl_xor_sync(0xffffffffu, t0m, 2));
        t1m = fmaxf(t1m, __shfl_xor_sync(0xffffffffu, t1m, 1));
        t1m = fmaxf(t1m, __shfl_xor_sync(0xffffffffu, t1m, 2));
        const float mn0 = fmaxf(m0, t0m), mn1 = fmaxf(m1, t1m);
        const float cr0 = __expf(m0 - mn0), cr1 = __expf(m1 - mn1);
        float ps0 = 0.f, ps1 = 0.f;
#pragma unroll
        for (int f = 0; f < 8; ++f) {
            Sf[f][0] = __expf(Sf[f][0] - mn0);
            Sf[f][1] = __expf(Sf[f][1] - mn0);
            Sf[f][2] = __expf(Sf[f][2] - mn1);
            Sf[f][3] = __expf(Sf[f][3] - mn1);
            ps0 += Sf[f][0] + Sf[f][1];
            ps1 += Sf[f][2] + Sf[f][3];
        }
        ps0 += __shfl_xor_sync(0xffffffffu, ps0, 1);
        ps0 += __shfl_xor_sync(0xffffffffu, ps0, 2);
        ps1 += __shfl_xor_sync(0xffffffffu, ps1, 1);
        ps1 += __shfl_xor_sync(0xffffffffu, ps1, 2);
        l0 = l0 * cr0 + ps0; m0 = mn0;
        l1 = l1 * cr1 + ps1; m1 = mn1;
#pragma unroll
        for (int f = 0; f < 8; ++f) {
            Of[f][0] *= cr0; Of[f][1] *= cr0; Of[f][2] *= cr1; Of[f][3] *= cr1;
        }

        uint32_t ph[4][4], pl[4][4];
#pragma unroll
        for (int j2 = 0; j2 < 4; ++j2) {
            const float* A = Sf[2 * j2];
            const float* Bq = Sf[2 * j2 + 1];
            float la, lb;
            __nv_bfloat162 t;
            t.x = __float2bfloat16(A[0]); t.y = __float2bfloat16(A[1]);
            la = A[0] - __bfloat162float(t.x); lb = A[1] - __bfloat162float(t.y);
            ph[j2][0] = *(uint32_t*)&t; pl[j2][0] = packbf2(la, lb);
            t.x = __float2bfloat16(A[2]); t.y = __float2bfloat16(A[3]);
            la = A[2] - __bfloat162float(t.x); lb = A[3] - __bfloat162float(t.y);
            ph[j2][1] = *(uint32_t*)&t; pl[j2][1] = packbf2(la, lb);
            t.x = __float2bfloat16(Bq[0]); t.y = __float2bfloat16(Bq[1]);
            la = Bq[0] - __bfloat162float(t.x); lb = Bq[1] - __bfloat162float(t.y);
            ph[j2][2] = *(uint32_t*)&t; pl[j2][2] = packbf2(la, lb);
            t.x = __float2bfloat16(Bq[2]); t.y = __float2bfloat16(Bq[3]);
            la = Bq[2] - __bfloat162float(t.x); lb = Bq[3] - __bfloat162float(t.y);
            ph[j2][3] = *(uint32_t*)&t; pl[j2][3] = packbf2(la, lb);
        }

#pragma unroll
        for (int ks2 = 0; ks2 < 4; ++ks2) {
#pragma unroll
            for (int g = 0; g < 4; ++g) {
                const uint32_t voff = (ks2 * 16 + lr15) * 144 + (g * 16 + hb * 8) * 2;
                uint32_t vh[4], vl[4];
                ldsm4t(vh, VH + voff);
                ldsm4t(vl, VL + voff);
#pragma unroll
                for (int j = 0; j < 2; ++j) {
                    mma16816(Of[g * 2 + j], ph[ks2], vh[2 * j], vh[2 * j + 1]);
                    mma16816(Of[g * 2 + j], ph[ks2], vl[2 * j], vl[2 * j + 1]);
                    mma16816(Of[g * 2 + j], pl[ks2], vh[2 * j], vh[2 * j + 1]);
                }
            }
        }
    }

    const int r0 = warp * 16 + (lane >> 2);
    if (!edge) {
        const float inv0 = 1.f / l0, inv1 = 1.f / l1;
        const size_t tk0 = (size_t)(b * S_ + qb * 64 + r0) * D_ + hh * 64;
        const size_t tk1 = tk0 + 8 * D_;
#pragma unroll
        for (int f = 0; f < 8; ++f) {
            const int c = f * 8 + 2 * (lane & 3);
            float v0 = Of[f][0] * inv0, v1 = Of[f][1] * inv0;
            float v2 = Of[f][2] * inv1, v3 = Of[f][3] * inv1;
            __nv_bfloat162 h01, h23, l01, l23;
            h01.x = __float2bfloat16(v0); h01.y = __float2bfloat16(v1);
            l01.x = __float2bfloat16(v0 - __bfloat162float(h01.x));
            l01.y = __float2bfloat16(v1 - __bfloat162float(h01.y));
            h23.x = __float2bfloat16(v2); h23.y = __float2bfloat16(v3);
            l23.x = __float2bfloat16(v2 - __bfloat162float(h23.x));
            l23.y = __float2bfloat16(v3 - __bfloat162float(h23.y));
            *(__nv_bfloat162*)(g_chi + tk0 + c) = h01;
            *(__nv_bfloat162*)(g_clo + tk0 + c) = l01;
            *(__nv_bfloat162*)(g_chi + tk1 + c) = h23;
            *(__nv_bfloat162*)(g_clo + tk1 + c) = l23;
        }
    } else {
        float* base = g_part + ((size_t)((((b * H_ + hh) * 2 + e) * 8 + slice) * 64)) * 66;
        float* pp0 = base + (size_t)r0 * 66;
        float* pp1 = base + (size_t)(r0 + 8) * 66;
#pragma unroll
        for (int f = 0; f < 8; ++f) {
            const int c = f * 8 + 2 * (lane & 3);
            pp0[c] = Of[f][0]; pp0[c + 1] = Of[f][1];
            pp1[c] = Of[f][2]; pp1[c + 1] = Of[f][3];
        }
        if ((lane & 3) == 0) {
            pp0[64] = m0; pp0[65] = l0;
            pp1[64] = m1; pp1[65] = l1;
        }
    }
}

__global__ __launch_bounds__(256) void merge_kernel() {
    const int e = blockIdx.x, hh = blockIdx.y, b = blockIdx.z;
    const int tid = threadIdx.x;
    const int r = tid >> 2, t4 = tid & 3;
    const size_t base = ((size_t)(((b * H_ + hh) * 2 + e) * 8)) * 64 * 66;

    float M = -1e30f;
#pragma unroll
    for (int s = 0; s < 8; ++s) M = fmaxf(M, g_part[base + ((size_t)s * 64 + r) * 66 + 64]);
    float L = 0.f, acc[16];
#pragma unroll
    for (int i = 0; i < 16; ++i) acc[i] = 0.f;
#pragma unroll
    for (int s = 0; s < 8; ++s) {
        const float* pp = g_part + base + ((size_t)s * 64 + r) * 66;
        const float w = __expf(pp[64] - M);
        L += pp[65] * w;
#pragma unroll
        for (int i = 0; i < 16; ++i) acc[i] += pp[t4 * 16 + i] * w;
    }
    const float inv = 1.0f / L;
    const int qb = e ? (NB_ - 1) : 0;
    const size_t idx = ((size_t)(b * S_ + qb * 64 + r)) * D_ + hh * 64 + t4 * 16;
#pragma unroll
    for (int i = 0; i < 16; ++i) {
        float vv = acc[i] * inv;
        __nv_bfloat16 h = __float2bfloat16(vv);
        g_chi[idx + i] = h;
        g_clo[idx + i] = __float2bfloat16(vv - __bfloat162float(h));
    }
}

// ---------------- classifier ----------------
__global__ void cls1_kernel(const float* __restrict__ h, const float* __restrict__ w,
                            const float* __restrict__ bias, float* __restrict__ out) {
    int gid = blockIdx.x * blockDim.x + threadIdx.x;
    if (gid >= 2 * 512) return;
    int b = gid >> 9, n = gid & 511;
    const float* hrow = h + (size_t)b * S_ * D_;
    float s = 0.f;
    for (int k2 = 0; k2 < D_; ++k2) s += hrow[k2] * w[(size_t)k2 * 512 + n];
    out[gid] = fmaxf(s + bias[n], 0.f);
}
__global__ void cls2_kernel(const float* __restrict__ rin, const float* __restrict__ w,
                            const float* __restrict__ bias, float* __restrict__ out) {
    int gid = blockIdx.x * blockDim.x + threadIdx.x;
    if (gid >= 2 * TGT_) return;
    int b = gid >> 10, n = gid & 1023;
    float s = 0.f;
    for (int k2 = 0; k2 < 512; ++k2) s += rin[b * 512 + k2] * w[(size_t)k2 * TGT_ + n];
    out[gid] = s + bias[n];
}

// ---------------- host ----------------
typedef CUresult (*EncFn)(CUtensorMap*, CUtensorMapDataType, cuuint32_t, void*,
                          const cuuint64_t*, const cuuint64_t*, const cuuint32_t*, const cuuint32_t*,
                          CUtensorMapInterleave, CUtensorMapSwizzle, CUtensorMapL2promotion,
                          CUtensorMapFloatOOBfill);

extern "C" void kernel_launch(void* const* d_in, const int* in_sizes, int n_in,
                              void* d_out, int out_size)
{
    const float* x        = (const float*)d_in[0];
    const float* mask     = (const float*)d_in[1];
    const float* proj_b   = (const float*)d_in[3];
    const float* pos_emb  = (const float*)d_in[4];
    const float* tok_emb  = (const float*)d_in[5];
    const float* emb_g    = (const float*)d_in[6];
    const float* emb_b    = (const float*)d_in[7];
    const float* bq_all   = (const float*)d_in[9];
    const float* bk_all   = (const float*)d_in[11];
    const float* bv_all   = (const float*)d_in[13];
    const float* bo_all   = (const float*)d_in[15];
    const float* ln1g_all = (const float*)d_in[16];
    const float* ln1b_all = (const float*)d_in[17];
    const float* bi_all   = (const float*)d_in[19];
    const float* bo2_all  = (const float*)d_in[21];
    const float* ln2g_all = (const float*)d_in[22];
    const float* ln2b_all = (const float*)d_in[23];
    const float* cls_w1   = (const float*)d_in[24];
    const float* cls_b1   = (const float*)d_in[25];
    const float* cls_w2   = (const float*)d_in[26];
    const float* cls_b2   = (const float*)d_in[27];
    const int*   rb       = (const int*)d_in[28];
    float* out = (float*)d_out;

    float *ph, *ptmp, *pcls, *pbqkv;
    __nv_bfloat16 *pwhi, *pwlo, *pxhi, *pxlo, *phhi, *phlo, *pchi, *pclo, *pfhi, *pflo, *pqvh, *pqvl;
    cudaGetSymbolAddress((void**)&ph,   g_h);
    cudaGetSymbolAddress((void**)&ptmp, g_tmp);
    cudaGetSymbolAddress((void**)&pcls, g_cls);
    cudaGetSymbolAddress((void**)&pbqkv, g_bqkv);
    cudaGetSymbolAddress((void**)&pwhi, g_whi);
    cudaGetSymbolAddress((void**)&pwlo, g_wlo);
    cudaGetSymbolAddress((void**)&pxhi, g_xhi);
    cudaGetSymbolAddress((void**)&pxlo, g_xlo);
    cudaGetSymbolAddress((void**)&phhi, g_hhi);
    cudaGetSymbolAddress((void**)&phlo, g_hlo);
    cudaGetSymbolAddress((void**)&pchi, g_chi);
    cudaGetSymbolAddress((void**)&pclo, g_clo);
    cudaGetSymbolAddress((void**)&pfhi, g_fhi);
    cudaGetSymbolAddress((void**)&pflo, g_flo);
    cudaGetSymbolAddress((void**)&pqvh, g_qkvhi);
    cudaGetSymbolAddress((void**)&pqvl, g_qkvlo);

    EncFn enc = nullptr;
    cudaDriverEntryPointQueryResult qr;
    cudaGetDriverEntryPointByVersion("cuTensorMapEncodeTiled", (void**)&enc, 12000,
                                     cudaEnableDefault, &qr);

    auto mk2 = [&](CUtensorMap* m, void* p, uint64_t K) {
        cuuint64_t d[2] = {K, T_};
        cuuint64_t st[1] = {K * 2};
        cuuint32_t bx[2] = {64, 128}, es[2] = {1, 1};
        enc(m, CU_TENSOR_MAP_DATA_TYPE_BFLOAT16, 2, p, d, st, bx, es,
            CU_TENSOR_MAP_INTERLEAVE_NONE, CU_TENSOR_MAP_SWIZZLE_128B,
            CU_TENSOR_MAP_L2_PROMOTION_L2_128B, CU_TENSOR_MAP_FLOAT_OOB_FILL_NONE);
    };
    auto mk3 = [&](CUtensorMap* m, void* p, uint64_t K, uint64_t N, uint64_t Lz) {
        cuuint64_t d[3] = {K, N, Lz};
        cuuint64_t st[2] = {K * 2, N * K * 2};
        cuuint32_t bx[3] = {64, 128, 1}, es[3] = {1, 1, 1};
        enc(m, CU_TENSOR_MAP_DATA_TYPE_BFLOAT16, 3, p, d, st, bx, es,
            CU_TENSOR_MAP_INTERLEAVE_NONE, CU_TENSOR_MAP_SWIZZLE_128B,
            CU_TENSOR_MAP_L2_PROMOTION_L2_128B, CU_TENSOR_MAP_FLOAT_OOB_FILL_NONE);
    };

    CUtensorMap mxh, mxl, mhh, mhl, mch, mcl, mfh, mfl;
    CUtensorMap mpjh, mpjl, mqkvh, mqkvl, moh, mol, mih, mil, m2h, m2l;
    mk2(&mxh, pxhi, IN_); mk2(&mxl, pxlo, IN_);
    mk2(&mhh, phhi, D_);  mk2(&mhl, phlo, D_);
    mk2(&mch, pchi, D_);  mk2(&mcl, pclo, D_);
    mk2(&mfh, pfhi, FF_); mk2(&mfl, pflo, FF_);
    mk3(&mpjh, pwhi + OFF_PROJ, IN_, D_, 1);   mk3(&mpjl, pwlo + OFF_PROJ, IN_, D_, 1);
    mk3(&mqkvh, pwhi + OFF_QKV, D_, NQKV, L_); mk3(&mqkvl, pwlo + OFF_QKV, D_, NQKV, L_);
    mk3(&moh, pwhi + OFF_WO, D_, D_, L_);      mk3(&mol, pwlo + OFF_WO, D_, D_, L_);
    mk3(&mih, pwhi + OFF_WI, D_, FF_, L_);     mk3(&mil, pwlo + OFF_WI, D_, FF_, L_);
    mk3(&m2h, pwhi + OFF_WO2, FF_, D_, L_);    mk3(&m2l, pwlo + OFF_WO2, FF_, D_, L_);

    cudaFuncSetAttribute(tgemm_kernel<false, false, false, true, true>,
                         cudaFuncAttributeMaxDynamicSharedMemorySize, GEMM_SMEM);
    cudaFuncSetAttribute(tgemm_kernel<false, false, true, false, false>,
                         cudaFuncAttributeMaxDynamicSharedMemorySize, GEMM_SMEM);
    cudaFuncSetAttribute(tgemm_kernel<false, true, false, true, true>,
                         cudaFuncAttributeMaxDynamicSharedMemorySize, GEMM_SMEM);
    cudaFuncSetAttribute(tgemm_kernel<true, false, true, false, true>,
                         cudaFuncAttributeMaxDynamicSharedMemorySize, GEMM_SMEM);
    cudaFuncSetAttribute(attn_tc_kernel,
                         cudaFuncAttributeMaxDynamicSharedMemorySize, ATTN_SMEM);

    // prep
    dim3 tb(32, 8);
    tsplit_kernel<<<dim3(D_ / 32, IN_ / 32, 1), tb>>>((const float*)d_in[2], pwhi + OFF_PROJ, pwlo + OFF_PROJ, IN_, D_, IN_ * D_);
    tsplit_kernel<<<dim3(D_ / 32, D_ / 32, L_), tb>>>((const float*)d_in[8],  pwhi + OFF_QKV,               pwlo + OFF_QKV,               D_, D_, NQKV * D_);
    tsplit_kernel<<<dim3(D_ / 32, D_ / 32, L_), tb>>>((const float*)d_in[10], pwhi + OFF_QKV + 768 * 768,   pwlo + OFF_QKV + 768 * 768,   D_, D_, NQKV * D_);
    tsplit_kernel<<<dim3(D_ / 32, D_ / 32, L_), tb>>>((const float*)d_in[12], pwhi + OFF_QKV + 2 * 768 * 768, pwlo + OFF_QKV + 2 * 768 * 768, D_, D_, NQKV * D_);
    tsplit_kernel<<<dim3(D_ / 32, D_ / 32, L_), tb>>>((const float*)d_in[14], pwhi + OFF_WO, pwlo + OFF_WO, D_, D_, D_ * D_);
    tsplit_kernel<<<dim3(FF_ / 32, D_ / 32, L_), tb>>>((const float*)d_in[18], pwhi + OFF_WI, pwlo + OFF_WI, D_, FF_, D_ * FF_);
    tsplit_kernel<<<dim3(D_ / 32, FF_ / 32, L_), tb>>>((const float*)d_in[20], pwhi + OFF_WO2, pwlo + OFF_WO2, FF_, D_, FF_ * D_);
    split_kernel<<<(T_ * IN_ + 255) / 256, 256>>>(x, pxhi, pxlo, T_ * IN_);
    build_gi_kernel<<<1, 64>>>(rb);
    bcat_kernel<<<(L_ * NQKV + 255) / 256, 256>>>(bq_all, bk_all, bv_all);

    const dim3 gD(D_ / 128, T_ / 128);
    const dim3 gQKV(NQKV / 128, T_ / 128);
    const dim3 gF(FF_ / 128, T_ / 128);
    const dim3 gA(78, H_, B_);
    const dim3 gM(2, H_, B_);

    tgemm_kernel<false, false, false, true, true><<<gD, 256, GEMM_SMEM>>>(
        mxh, mxl, mpjh, mpjl, proj_b, nullptr, ptmp, nullptr, nullptr, D_, IN_, 0);
    ln_kernel<<<T_, 256>>>(ptmp, emb_g, emb_b, ph, phhi, phlo, pos_emb, tok_emb);

    for (int l = 0; l < L_; ++l) {
        // QKV projection: 2-plane (drops alo*bhi term; Q/K/V tolerate ~2^-9 rel err)
        tgemm_kernel<false, false, true, false, false><<<gQKV, 256, GEMM_SMEM>>>(
            mhh, mhl, mqkvh, mqkvl, pbqkv + (size_t)l * NQKV, nullptr,
            nullptr, pqvh, pqvl, NQKV, D_, l);

        attn_tc_kernel<<<gA, 128, ATTN_SMEM>>>(pqvh, pqvl, mask);
        merge_kernel<<<gM, 256>>>();

        tgemm_kernel<false, true, false, true, true><<<gD, 256, GEMM_SMEM>>>(
            mch, mcl, moh, mol, bo_all + (size_t)l * D_, ph, ptmp, nullptr, nullptr, D_, D_, l);
        ln_kernel<<<T_, 256>>>(ptmp, ln1g_all + (size_t)l * D_, ln1b_all + (size_t)l * D_,
                               ph, phhi, phlo, nullptr, nullptr);

        tgemm_kernel<true, false, true, false, true><<<gF, 256, GEMM_SMEM>>>(
            mhh, mhl, mih, mil, bi_all + (size_t)l * FF_, nullptr, nullptr, pfhi, pflo, FF_, D_, l);
        tgemm_kernel<false, true, false, true, true><<<gD, 256, GEMM_SMEM>>>(
            mfh, mfl, m2h, m2l, bo2_all + (size_t)l * D_, ph, ptmp, nullptr, nullptr, D_, FF_, l);
        ln_kernel<<<T_, 256>>>(ptmp, ln2g_all + (size_t)l * D_, ln2b_all + (size_t)l * D_,
                               ph, phhi, phlo, nullptr, nullptr);
    }

    cls1_kernel<<<4, 256>>>(ph, cls_w1, cls_b1, pcls);
    cls2_kernel<<<8, 256>>>(pcls, cls_w2, cls_b2, out);
}

// round 13
// speedup vs baseline: 1.1519x; 1.0002x over previous
#include <cuda_runtime.h>
#include <cuda.h>
#include <cuda_bf16.h>
#include <math.h>
#include <stdint.h>

#define B_    2
#define S_    4096
#define T_    8192
#define IN_   1280
#define D_    768
#define H_    12
#define FF_   3072
#define L_    12
#define TGT_  1024
#define NB_   64
#define NQKV  2304

#define OFF_PROJ 0
#define OFF_QKV  (IN_*D_)
#define OFF_WO   (OFF_QKV + L_*NQKV*D_)
#define OFF_WI   (OFF_WO + L_*D_*D_)
#define OFF_WO2  (OFF_WI + L_*D_*FF_)
#define WTOT     (OFF_WO2 + L_*FF_*D_)

#define GEMM_SMEM (1024 + 3*65536)
#define ATTN_SMEM 55296

// ---------------- scratch ----------------
__device__ float g_h[T_ * D_];
__device__ float g_tmp[T_ * D_];
__device__ float g_cls[2 * 512];
__device__ float g_bqkv[L_ * NQKV];
__device__ int   g_gi[NB_ * 8];

__device__ __align__(128) __nv_bfloat16 g_whi[WTOT];
__device__ __align__(128) __nv_bfloat16 g_wlo[WTOT];
__device__ __align__(128) __nv_bfloat16 g_xhi[T_ * IN_];
__device__ __align__(128) __nv_bfloat16 g_xlo[T_ * IN_];
__device__ __align__(128) __nv_bfloat16 g_hhi[T_ * D_];
__device__ __align__(128) __nv_bfloat16 g_hlo[T_ * D_];
__device__ __align__(128) __nv_bfloat16 g_chi[T_ * D_];
__device__ __align__(128) __nv_bfloat16 g_clo[T_ * D_];
__device__ __align__(128) __nv_bfloat16 g_fhi[T_ * FF_];
__device__ __align__(128) __nv_bfloat16 g_flo[T_ * FF_];
__device__ __align__(128) __nv_bfloat16 g_qkvhi[T_ * NQKV];
__device__ __align__(128) __nv_bfloat16 g_qkvlo[T_ * NQKV];
__device__ float g_part[B_ * H_ * 2 * 8 * 64 * 66];

// ---------------- PTX helpers ----------------
__device__ __forceinline__ uint32_t s2u(const void* p) { return (uint32_t)__cvta_generic_to_shared(p); }
__device__ __forceinline__ void mbar_init(uint32_t a, uint32_t c) {
    asm volatile("mbarrier.init.shared.b64 [%0], %1;" :: "r"(a), "r"(c) : "memory");
}
__device__ __forceinline__ void mbar_expect(uint32_t a, uint32_t b) {
    asm volatile("mbarrier.arrive.expect_tx.shared.b64 _, [%0], %1;" :: "r"(a), "r"(b) : "memory");
}
__device__ __forceinline__ void mbar_wait(uint32_t a, uint32_t par) {
    asm volatile("{\n\t.reg .pred P;\n\tW_%=:\n\t"
                 "mbarrier.try_wait.parity.acquire.cta.shared::cta.b64 P, [%0], %1, 0x989680;\n\t"
                 "@P bra.uni D_%=;\n\tbra.uni W_%=;\n\tD_%=:\n\t}" :: "r"(a), "r"(par) : "memory");
}
__device__ __forceinline__ void tma2d(uint32_t dst, const void* tm, int x, int y, uint32_t mb) {
    asm volatile("cp.async.bulk.tensor.2d.shared::cta.global.tile.mbarrier::complete_tx::bytes "
                 "[%0], [%1, {%2, %3}], [%4];" :: "r"(dst), "l"(tm), "r"(x), "r"(y), "r"(mb) : "memory");
}
__device__ __forceinline__ void tma3d(uint32_t dst, const void* tm, int x, int y, int z, uint32_t mb) {
    asm volatile("cp.async.bulk.tensor.3d.shared::cta.global.tile.mbarrier::complete_tx::bytes "
                 "[%0], [%1, {%2, %3, %4}], [%5];" :: "r"(dst), "l"(tm), "r"(x), "r"(y), "r"(z), "r"(mb) : "memory");
}
__device__ __forceinline__ void ldsm4a(uint32_t* r, uint32_t a) {
    asm volatile("ldmatrix.sync.aligned.m8n8.x4.shared.b16 {%0,%1,%2,%3}, [%4];"
                 : "=r"(r[0]), "=r"(r[1]), "=r"(r[2]), "=r"(r[3]) : "r"(a));
}
__device__ __forceinline__ void ldsm4t(uint32_t* r, uint32_t a) {
    asm volatile("ldmatrix.sync.aligned.m8n8.x4.trans.shared.b16 {%0,%1,%2,%3}, [%4];"
                 : "=r"(r[0]), "=r"(r[1]), "=r"(r[2]), "=r"(r[3]) : "r"(a));
}
__device__ __forceinline__ void mma16816(float* d, const uint32_t* a, uint32_t b0, uint32_t b1) {
    asm volatile("mma.sync.aligned.m16n8k16.row.col.f32.bf16.bf16.f32 "
                 "{%0,%1,%2,%3}, {%4,%5,%6,%7}, {%8,%9}, {%0,%1,%2,%3};"
                 : "+f"(d[0]), "+f"(d[1]), "+f"(d[2]), "+f"(d[3])
                 : "r"(a[0]), "r"(a[1]), "r"(a[2]), "r"(a[3]), "r"(b0), "r"(b1));
}
__device__ __forceinline__ uint32_t packbf2(float lo_e, float hi_e) {
    __nv_bfloat162 t;
    t.x = __float2bfloat16(lo_e);
    t.y = __float2bfloat16(hi_e);
    return *(uint32_t*)&t;
}

// ---------------- prep kernels ----------------
__global__ void split_kernel(const float* __restrict__ s, __nv_bfloat16* __restrict__ hi,
                             __nv_bfloat16* __restrict__ lo, int n) {
    int i = blockIdx.x * blockDim.x + threadIdx.x;
    if (i >= n) return;
    float v = s[i];
    __nv_bfloat16 h = __float2bfloat16(v);
    hi[i] = h;
    lo[i] = __float2bfloat16(v - __bfloat162float(h));
}

__global__ void tsplit_kernel(const float* __restrict__ src, __nv_bfloat16* __restrict__ hi,
                              __nv_bfloat16* __restrict__ lo, int K, int N, int lstride) {
    __shared__ float t[32][33];
    const int l = blockIdx.z;
    const int n0 = blockIdx.x * 32, k0 = blockIdx.y * 32;
    const float* S = src + (size_t)l * K * N;
    const int tx = threadIdx.x, ty = threadIdx.y;
#pragma unroll
    for (int j = 0; j < 4; ++j)
        t[ty + j * 8][tx] = S[(size_t)(k0 + ty + j * 8) * N + n0 + tx];
    __syncthreads();
    __nv_bfloat16* Ht = hi + (size_t)l * lstride;
    __nv_bfloat16* Lt = lo + (size_t)l * lstride;
#pragma unroll
    for (int j = 0; j < 4; ++j) {
        int n = n0 + ty + j * 8;
        float v = t[tx][ty + j * 8];
        __nv_bfloat16 h = __float2bfloat16(v);
        Ht[(size_t)n * K + k0 + tx] = h;
        Lt[(size_t)n * K + k0 + tx] = __float2bfloat16(v - __bfloat162float(h));
    }
}

__global__ void build_gi_kernel(const int* __restrict__ rb) {
    int n = threadIdx.x;
    if (n < 1 || n >= NB_ - 1) return;
    int* p = g_gi + n * 8;
    p[0] = 0; p[1] = n - 1; p[2] = n; p[3] = n + 1; p[4] = NB_ - 1;
    p[5] = rb[n * 3 + 0]; p[6] = rb[n * 3 + 1]; p[7] = rb[n * 3 + 2];
}

__global__ void bcat_kernel(const float* __restrict__ bq, const float* __restrict__ bk,
                            const float* __restrict__ bv) {
    int i = blockIdx.x * blockDim.x + threadIdx.x;
    if (i >= L_ * NQKV) return;
    int l = i / NQKV, n = i % NQKV;
    float v = (n < 768) ? bq[l * 768 + n] : (n < 1536) ? bk[l * 768 + n - 768] : bv[l * 768 + n - 1536];
    g_bqkv[i] = v;
}

// ---------------- TMA + mma.sync bf16 GEMM (2/3-plane), 3-stage pipeline ----------------
template<bool GELU, bool RES, bool SPLITOUT, bool WRITEF32, bool THIRD>
__global__ __launch_bounds__(256, 1) void tgemm_kernel(
    const __grid_constant__ CUtensorMap tAh, const __grid_constant__ CUtensorMap tAl,
    const __grid_constant__ CUtensorMap tBh, const __grid_constant__ CUtensorMap tBl,
    const float* __restrict__ bias, const float* __restrict__ res,
    float* __restrict__ C, __nv_bfloat16* __restrict__ Chi, __nv_bfloat16* __restrict__ Clo,
    int N, int K, int layer)
{
    extern __shared__ char dsm[];
    const uint32_t ctl = s2u(dsm);
    const uint32_t tiles = (ctl + 64 + 1023) & ~1023u;
    const int tid = threadIdx.x;
    const int warp = tid >> 5, lane = tid & 31;
    const int wr = warp >> 1, wc = warp & 1;
    const int m0 = blockIdx.y * 128, n0 = blockIdx.x * 128;
    const int nch = K >> 6;

    if (tid == 0) {
        mbar_init(ctl, 1);
        mbar_init(ctl + 8, 1);
        mbar_init(ctl + 16, 1);
        asm volatile("fence.proxy.async.shared::cta;" ::: "memory");
    }
    __syncthreads();

    auto issue = [&](int i) {
        const int st = i % 3;
        const uint32_t mb = ctl + st * 8;
        const uint32_t tb = tiles + st * 65536;
        mbar_expect(mb, THIRD ? 65536 : 49152);
        const int k0 = i << 6;
        tma2d(tb +     0, &tAh, k0, m0, mb);
        if (THIRD) tma2d(tb + 16384, &tAl, k0, m0, mb);
        tma3d(tb + 32768, &tBh, k0, n0, layer, mb);
        tma3d(tb + 49152, &tBl, k0, n0, layer, mb);
    };
    const bool prod = (tid == 0);
    if (prod) {
        issue(0);
        if (nch > 1) issue(1);
        if (nch > 2) issue(2);
    }

    float acc[2][8][4];
#pragma unroll
    for (int mi = 0; mi < 2; ++mi)
#pragma unroll
        for (int ni = 0; ni < 8; ++ni)
#pragma unroll
            for (int r = 0; r < 4; ++r) acc[mi][ni][r] = 0.f;

    const int lrow = lane & 15;
    const uint32_t hb16 = (lane >> 4) * 16;
    uint32_t arow[2], axr[2], brow[4], bxr[4];
#pragma unroll
    for (int mi = 0; mi < 2; ++mi) {
        int r = wr * 32 + mi * 16 + lrow;
        arow[mi] = r * 128; axr[mi] = (r & 7) * 16;
    }
#pragma unroll
    for (int np = 0; np < 4; ++np) {
        int r = wc * 64 + np * 16 + lrow;
        brow[np] = r * 128; bxr[np] = (r & 7) * 16;
    }

    for (int i = 0; i < nch; ++i) {
        const int st = i % 3;
        mbar_wait(ctl + st * 8, (i / 3) & 1);
        const uint32_t bAh = tiles + st * 65536;
        const uint32_t bAl = bAh + 16384;
        const uint32_t bBh = bAh + 32768;
        const uint32_t bBl = bAh + 49152;
#pragma unroll
        for (int ks = 0; ks < 4; ++ks) {
            const uint32_t colb = ks * 32 + hb16;
            uint32_t ah[2][4], al[2][4];
#pragma unroll
            for (int mi = 0; mi < 2; ++mi) {
                ldsm4a(ah[mi], bAh + arow[mi] + (colb ^ axr[mi]));
                if (THIRD) ldsm4a(al[mi], bAl + arow[mi] + (colb ^ axr[mi]));
            }
#pragma unroll
            for (int np = 0; np < 4; ++np) {
                uint32_t bh[4], bl[4];
                ldsm4a(bh, bBh + brow[np] + (colb ^ bxr[np]));
                ldsm4a(bl, bBl + brow[np] + (colb ^ bxr[np]));
#pragma unroll
                for (int j = 0; j < 2; ++j) {
                    const int ni = np * 2 + j;
#pragma unroll
                    for (int mi = 0; mi < 2; ++mi) {
                        mma16816(acc[mi][ni], ah[mi], bh[j], bh[j + 2]);
                        mma16816(acc[mi][ni], ah[mi], bl[j], bl[j + 2]);
                        if (THIRD) mma16816(acc[mi][ni], al[mi], bh[j], bh[j + 2]);
                    }
                }
            }
        }
        __syncthreads();
        if (prod && i + 3 < nch) issue(i + 3);
    }

#pragma unroll
    for (int mi = 0; mi < 2; ++mi) {
        const int rbase = m0 + wr * 32 + mi * 16 + (lane >> 2);
#pragma unroll
        for (int ni = 0; ni < 8; ++ni) {
            const int cbase = n0 + wc * 64 + ni * 8 + (lane & 3) * 2;
            const float b0 = bias[cbase], b1 = bias[cbase + 1];
#pragma unroll
            for (int hr = 0; hr < 2; ++hr) {
                const int row = rbase + hr * 8;
                float v0 = acc[mi][ni][hr * 2 + 0] + b0;
                float v1 = acc[mi][ni][hr * 2 + 1] + b1;
                if (RES) {
                    v0 += res[(size_t)row * N + cbase];
                    v1 += res[(size_t)row * N + cbase + 1];
                }
                if (GELU) {
                    float u = v0;
                    v0 = 0.5f * u * (1.0f + tanhf(0.7978845608028654f * (u + 0.044715f * u * u * u)));
                    u = v1;
                    v1 = 0.5f * u * (1.0f + tanhf(0.7978845608028654f * (u + 0.044715f * u * u * u)));
                }
                const size_t idx = (size_t)row * N + cbase;
                if (WRITEF32) { C[idx] = v0; C[idx + 1] = v1; }
                if (SPLITOUT) {
                    __nv_bfloat16 h0 = __float2bfloat16(v0);
                    __nv_bfloat16 h1 = __float2bfloat16(v1);
                    Chi[idx] = h0; Chi[idx + 1] = h1;
                    Clo[idx]     = __float2bfloat16(v0 - __bfloat162float(h0));
                    Clo[idx + 1] = __float2bfloat16(v1 - __bfloat162float(h1));
                }
            }
        }
    }
}

// ---------------- LayerNorm (f32 + bf16 hi/lo out) ----------------
__global__ __launch_bounds__(256) void ln_kernel(
    const float* __restrict__ in, const float* __restrict__ gamma,
    const float* __restrict__ beta, float* __restrict__ out,
    __nv_bfloat16* __restrict__ ohi, __nv_bfloat16* __restrict__ olo,
    const float* __restrict__ pos, const float* __restrict__ tok)
{
    const int r = blockIdx.x, s = r % S_, t = threadIdx.x;
    const float* row = in + (size_t)r * D_;
    float x[3];
#pragma unroll
    for (int j = 0; j < 3; ++j) {
        int i = t + j * 256;
        float v = row[i];
        if (pos) v += pos[(size_t)s * D_ + i] + tok[i];
        x[j] = v;
    }
    float sum = x[0] + x[1] + x[2];
    float sq  = x[0] * x[0] + x[1] * x[1] + x[2] * x[2];
    __shared__ float rs[8], rq[8];
#pragma unroll
    for (int o = 16; o > 0; o >>= 1) {
        sum += __shfl_xor_sync(0xffffffffu, sum, o);
        sq  += __shfl_xor_sync(0xffffffffu, sq, o);
    }
    if ((t & 31) == 0) { rs[t >> 5] = sum; rq[t >> 5] = sq; }
    __syncthreads();
    if (t < 32) {
        float s2 = (t < 8) ? rs[t] : 0.f;
        float q2 = (t < 8) ? rq[t] : 0.f;
#pragma unroll
        for (int o = 4; o > 0; o >>= 1) {
            s2 += __shfl_xor_sync(0xffffffffu, s2, o);
            q2 += __shfl_xor_sync(0xffffffffu, q2, o);
        }
        if (t == 0) { rs[0] = s2; rq[0] = q2; }
    }
    __syncthreads();
    const float mean = rs[0] * (1.0f / 768.0f);
    float var = rq[0] * (1.0f / 768.0f) - mean * mean;
    const float rstd = rsqrtf(fmaxf(var, 0.f) + 1e-12f);
#pragma unroll
    for (int j = 0; j < 3; ++j) {
        int i = t + j * 256;
        float y = (x[j] - mean) * rstd * gamma[i] + beta[i];
        size_t idx = (size_t)r * D_ + i;
        out[idx] = y;
        __nv_bfloat16 h = __float2bfloat16(y);
        ohi[idx] = h;
        olo[idx] = __float2bfloat16(y - __bfloat162float(h));
    }
}

// ---------------- tensor-core block-sparse flash attention ----------------
__global__ __launch_bounds__(128, 3) void attn_tc_kernel(
    const __nv_bfloat16* __restrict__ qkvh, const __nv_bfloat16* __restrict__ qkvl,
    const float* __restrict__ mask)
{
    extern __shared__ char smraw[];
    const uint32_t su = s2u(smraw);
    const uint32_t QH = su, QL = su + 9216, KH = su + 18432, KL = su + 27648,
                   VH = su + 36864, VL = su + 46080;

    const int b = blockIdx.z, hh = blockIdx.y, ib = blockIdx.x;
    const int tid = threadIdx.x, warp = tid >> 5, lane = tid & 31;

    int qb, t0 = 0, e = 0, slice = 0;
    bool edge;
    if (ib < 62) { qb = ib + 1; edge = false; }
    else {
        edge = true;
        int xx = ib - 62;
        e = xx >> 3; slice = xx & 7;
        qb = e ? (NB_ - 1) : 0;
        t0 = slice * 8;
    }

    const int rrow = tid >> 1, half = tid & 1;
    {
        const size_t gq = (size_t)(b * S_ + qb * 64 + rrow) * NQKV + hh * 64 + half * 32;
        const uint4* s0 = (const uint4*)(qkvh + gq);
        const uint4* s1 = (const uint4*)(qkvl + gq);
        uint4* d0 = (uint4*)(smraw + rrow * 144 + half * 64);
        uint4* d1 = (uint4*)(smraw + 9216 + rrow * 144 + half * 64);
#pragma unroll
        for (int j = 0; j < 4; ++j) { d0[j] = s0[j]; d1[j] = s1[j]; }
    }

    float Sf[8][4], Of[8][4];
#pragma unroll
    for (int f = 0; f < 8; ++f)
#pragma unroll
        for (int r = 0; r < 4; ++r) Of[f][r] = 0.f;
    float m0 = -1e30f, m1 = -1e30f, l0 = 0.f, l1 = 0.f;

    const uint32_t lr15 = (lane & 15);
    const uint32_t hb = (lane >> 4);

    for (int kt = 0; kt < 8; ++kt) {
        const int kb = edge ? (t0 + kt) : g_gi[qb * 8 + kt];
        __syncthreads();
        {
            const size_t gk = (size_t)(b * S_ + kb * 64 + rrow) * NQKV + hh * 64 + half * 32;
            const uint4* kh = (const uint4*)(qkvh + gk + 768);
            const uint4* kl = (const uint4*)(qkvl + gk + 768);
            const uint4* vh = (const uint4*)(qkvh + gk + 1536);
            const uint4* vl = (const uint4*)(qkvl + gk + 1536);
            const int off = rrow * 144 + half * 64;
            uint4* dkh = (uint4*)(smraw + 18432 + off);
            uint4* dkl = (uint4*)(smraw + 27648 + off);
            uint4* dvh = (uint4*)(smraw + 36864 + off);
            uint4* dvl = (uint4*)(smraw + 46080 + off);
#pragma unroll
            for (int j = 0; j < 4; ++j) { dkh[j] = kh[j]; dkl[j] = kl[j]; dvh[j] = vh[j]; dvl[j] = vl[j]; }
        }
        __syncthreads();

#pragma unroll
        for (int f = 0; f < 8; ++f)
#pragma unroll
            for (int r = 0; r < 4; ++r) Sf[f][r] = 0.f;
#pragma unroll
        for (int ks = 0; ks < 4; ++ks) {
            const uint32_t colb = ks * 32 + hb * 16;
            const uint32_t qoff = (warp * 16 + lr15) * 144 + colb;
            uint32_t qh[4], ql[4];
            ldsm4a(qh, QH + qoff);
            ldsm4a(ql, QL + qoff);
#pragma unroll
            for (int np = 0; np < 4; ++np) {
                const uint32_t koff = (np * 16 + lr15) * 144 + colb;
                uint32_t kh[4], kl[4];
                ldsm4a(kh, KH + koff);
                ldsm4a(kl, KL + koff);
#pragma unroll
                for (int j = 0; j < 2; ++j) {
                    mma16816(Sf[np * 2 + j], qh, kh[j], kh[j + 2]);
                    mma16816(Sf[np * 2 + j], qh, kl[j], kl[j + 2]);
                    mma16816(Sf[np * 2 + j], ql, kh[j], kh[j + 2]);
                }
            }
        }

        const float* mrow = mask + (size_t)b * S_ + kb * 64;
        float t0m = -1e30f, t1m = -1e30f;
#pragma unroll
        for (int f = 0; f < 8; ++f) {
            const int c = f * 8 + 2 * (lane & 3);
            const float2 mk = *(const float2*)(mrow + c);
            Sf[f][0] = Sf[f][0] * 0.125f - 1e9f * (1.f - mk.x);
            Sf[f][1] = Sf[f][1] * 0.125f - 1e9f * (1.f - mk.y);
            Sf[f][2] = Sf[f][2] * 0.125f - 1e9f * (1.f - mk.x);
            Sf[f][3] = Sf[f][3] * 0.125f - 1e9f * (1.f - mk.y);
            t0m = fmaxf(t0m, fmaxf(Sf[f][0], Sf[f][1]));
            t1m = fmaxf(t1m, fmaxf(Sf[f][2], Sf[f][3]));
        }
        t0m = fmaxf(t0m, __shfl_xor_sync(0xffffffffu, t0m, 1));
        t0m = fmaxf(t0m, __shfl_xor_sync(0xffffffffu, t0m, 2));
        t1m = fmaxf(t1m, __shfl_xor_sync(0xffffffffu, t1m, 1));
        t1m = fmaxf(t1m, __shfl_xor_sync(0xffffffffu, t1m, 2));
        const float mn0 = fmaxf(m0, t0m), mn1 = fmaxf(m1, t1m);
        const float cr0 = __expf(m0 - mn0), cr1 = __expf(m1 - mn1);
        float ps0 = 0.f, ps1 = 0.f;
#pragma unroll
        for (int f = 0; f < 8; ++f) {
            Sf[f][0] = __expf(Sf[f][0] - mn0);
            Sf[f][1] = __expf(Sf[f][1] - mn0);
            Sf[f][2] = __expf(Sf[f][2] - mn1);
            Sf[f][3] = __expf(Sf[f][3] - mn1);
            ps0 += Sf[f][0] + Sf[f][1];
            ps1 += Sf[f][2] + Sf[f][3];
        }
        ps0 += __shfl_xor_sync(0xffffffffu, ps0, 1);
        ps0 += __shfl_xor_sync(0xffffffffu, ps0, 2);
        ps1 += __shfl_xor_sync(0xffffffffu, ps1, 1);
        ps1 += __shfl_xor_sync(0xffffffffu, ps1, 2);
        l0 = l0 * cr0 + ps0; m0 = mn0;
        l1 = l1 * cr1 + ps1; m1 = mn1;
#pragma unroll
        for (int f = 0; f < 8; ++f) {
            Of[f][0] *= cr0; Of[f][1] *= cr0; Of[f][2] *= cr1; Of[f][3] *= cr1;
        }

        uint32_t ph[4][4], pl[4][4];
#pragma unroll
        for (int j2 = 0; j2 < 4; ++j2) {
            const float* A = Sf[2 * j2];
            const float* Bq = Sf[2 * j2 + 1];
            float la, lb;
            __nv_bfloat162 t;
            t.x = __float2bfloat16(A[0]); t.y = __float2bfloat16(A[1]);
            la = A[0] - __bfloat162float(t.x); lb = A[1] - __bfloat162float(t.y);
            ph[j2][0] = *(uint32_t*)&t; pl[j2][0] = packbf2(la, lb);
            t.x = __float2bfloat16(A[2]); t.y = __float2bfloat16(A[3]);
            la = A[2] - __bfloat162float(t.x); lb = A[3] - __bfloat162float(t.y);
            ph[j2][1] = *(uint32_t*)&t; pl[j2][1] = packbf2(la, lb);
            t.x = __float2bfloat16(Bq[0]); t.y = __float2bfloat16(Bq[1]);
            la = Bq[0] - __bfloat162float(t.x); lb = Bq[1] - __bfloat162float(t.y);
            ph[j2][2] = *(uint32_t*)&t; pl[j2][2] = packbf2(la, lb);
            t.x = __float2bfloat16(Bq[2]); t.y = __float2bfloat16(Bq[3]);
            la = Bq[2] - __bfloat162float(t.x); lb = Bq[3] - __bfloat162float(t.y);
            ph[j2][3] = *(uint32_t*)&t; pl[j2][3] = packbf2(la, lb);
        }

#pragma unroll
        for (int ks2 = 0; ks2 < 4; ++ks2) {
#pragma unroll
            for (int g = 0; g < 4; ++g) {
                const uint32_t voff = (ks2 * 16 + lr15) * 144 + (g * 16 + hb * 8) * 2;
                uint32_t vh[4], vl[4];
                ldsm4t(vh, VH + voff);
                ldsm4t(vl, VL + voff);
#pragma unroll
                for (int j = 0; j < 2; ++j) {
                    mma16816(Of[g * 2 + j], ph[ks2], vh[2 * j], vh[2 * j + 1]);
                    mma16816(Of[g * 2 + j], ph[ks2], vl[2 * j], vl[2 * j + 1]);
                    mma16816(Of[g * 2 + j], pl[ks2], vh[2 * j], vh[2 * j + 1]);
                }
            }
        }
    }

    const int r0 = warp * 16 + (lane >> 2);
    if (!edge) {
        const float inv0 = 1.f / l0, inv1 = 1.f / l1;
        const size_t tk0 = (size_t)(b * S_ + qb * 64 + r0) * D_ + hh * 64;
        const size_t tk1 = tk0 + 8 * D_;
#pragma unroll
        for (int f = 0; f < 8; ++f) {
            const int c = f * 8 + 2 * (lane & 3);
            float v0 = Of[f][0] * inv0, v1 = Of[f][1] * inv0;
            float v2 = Of[f][2] * inv1, v3 = Of[f][3] * inv1;
            __nv_bfloat162 h01, h23, l01, l23;
            h01.x = __float2bfloat16(v0); h01.y = __float2bfloat16(v1);
            l01.x = __float2bfloat16(v0 - __bfloat162float(h01.x));
            l01.y = __float2bfloat16(v1 - __bfloat162float(h01.y));
            h23.x = __float2bfloat16(v2); h23.y = __float2bfloat16(v3);
            l23.x = __float2bfloat16(v2 - __bfloat162float(h23.x));
            l23.y = __float2bfloat16(v3 - __bfloat162float(h23.y));
            *(__nv_bfloat162*)(g_chi + tk0 + c) = h01;
            *(__nv_bfloat162*)(g_clo + tk0 + c) = l01;
            *(__nv_bfloat162*)(g_chi + tk1 + c) = h23;
            *(__nv_bfloat162*)(g_clo + tk1 + c) = l23;
        }
    } else {
        float* base = g_part + ((size_t)((((b * H_ + hh) * 2 + e) * 8 + slice) * 64)) * 66;
        float* pp0 = base + (size_t)r0 * 66;
        float* pp1 = base + (size_t)(r0 + 8) * 66;
#pragma unroll
        for (int f = 0; f < 8; ++f) {
            const int c = f * 8 + 2 * (lane & 3);
            pp0[c] = Of[f][0]; pp0[c + 1] = Of[f][1];
            pp1[c] = Of[f][2]; pp1[c + 1] = Of[f][3];
        }
        if ((lane & 3) == 0) {
            pp0[64] = m0; pp0[65] = l0;
            pp1[64] = m1; pp1[65] = l1;
        }
    }
}

__global__ __launch_bounds__(256) void merge_kernel() {
    const int e = blockIdx.x, hh = blockIdx.y, b = blockIdx.z;
    const int tid = threadIdx.x;
    const int r = tid >> 2, t4 = tid & 3;
    const size_t base = ((size_t)(((b * H_ + hh) * 2 + e) * 8)) * 64 * 66;

    float M = -1e30f;
#pragma unroll
    for (int s = 0; s < 8; ++s) M = fmaxf(M, g_part[base + ((size_t)s * 64 + r) * 66 + 64]);
    float L = 0.f, acc[16];
#pragma unroll
    for (int i = 0; i < 16; ++i) acc[i] = 0.f;
#pragma unroll
    for (int s = 0; s < 8; ++s) {
        const float* pp = g_part + base + ((size_t)s * 64 + r) * 66;
        const float w = __expf(pp[64] - M);
        L += pp[65] * w;
#pragma unroll
        for (int i = 0; i < 16; ++i) acc[i] += pp[t4 * 16 + i] * w;
    }
    const float inv = 1.0f / L;
    const int qb = e ? (NB_ - 1) : 0;
    const size_t idx = ((size_t)(b * S_ + qb * 64 + r)) * D_ + hh * 64 + t4 * 16;
#pragma unroll
    for (int i = 0; i < 16; ++i) {
        float vv = acc[i] * inv;
        __nv_bfloat16 h = __float2bfloat16(vv);
        g_chi[idx + i] = h;
        g_clo[idx + i] = __float2bfloat16(vv - __bfloat162float(h));
    }
}

// ---------------- classifier ----------------
__global__ void cls1_kernel(const float* __restrict__ h, const float* __restrict__ w,
                            const float* __restrict__ bias, float* __restrict__ out) {
    int gid = blockIdx.x * blockDim.x + threadIdx.x;
    if (gid >= 2 * 512) return;
    int b = gid >> 9, n = gid & 511;
    const float* hrow = h + (size_t)b * S_ * D_;
    float s = 0.f;
    for (int k2 = 0; k2 < D_; ++k2) s += hrow[k2] * w[(size_t)k2 * 512 + n];
    out[gid] = fmaxf(s + bias[n], 0.f);
}
__global__ void cls2_kernel(const float* __restrict__ rin, const float* __restrict__ w,
                            const float* __restrict__ bias, float* __restrict__ out) {
    int gid = blockIdx.x * blockDim.x + threadIdx.x;
    if (gid >= 2 * TGT_) return;
    int b = gid >> 10, n = gid & 1023;
    float s = 0.f;
    for (int k2 = 0; k2 < 512; ++k2) s += rin[b * 512 + k2] * w[(size_t)k2 * TGT_ + n];
    out[gid] = s + bias[n];
}

// ---------------- host ----------------
typedef CUresult (*EncFn)(CUtensorMap*, CUtensorMapDataType, cuuint32_t, void*,
                          const cuuint64_t*, const cuuint64_t*, const cuuint32_t*, const cuuint32_t*,
                          CUtensorMapInterleave, CUtensorMapSwizzle, CUtensorMapL2promotion,
                          CUtensorMapFloatOOBfill);

extern "C" void kernel_launch(void* const* d_in, const int* in_sizes, int n_in,
                              void* d_out, int out_size)
{
    const float* x        = (const float*)d_in[0];
    const float* mask     = (const float*)d_in[1];
    const float* proj_b   = (const float*)d_in[3];
    const float* pos_emb  = (const float*)d_in[4];
    const float* tok_emb  = (const float*)d_in[5];
    const float* emb_g    = (const float*)d_in[6];
    const float* emb_b    = (const float*)d_in[7];
    const float* bq_all   = (const float*)d_in[9];
    const float* bk_all   = (const float*)d_in[11];
    const float* bv_all   = (const float*)d_in[13];
    const float* bo_all   = (const float*)d_in[15];
    const float* ln1g_all = (const float*)d_in[16];
    const float* ln1b_all = (const float*)d_in[17];
    const float* bi_all   = (const float*)d_in[19];
    const float* bo2_all  = (const float*)d_in[21];
    const float* ln2g_all = (const float*)d_in[22];
    const float* ln2b_all = (const float*)d_in[23];
    const float* cls_w1   = (const float*)d_in[24];
    const float* cls_b1   = (const float*)d_in[25];
    const float* cls_w2   = (const float*)d_in[26];
    const float* cls_b2   = (const float*)d_in[27];
    const int*   rb       = (const int*)d_in[28];
    float* out = (float*)d_out;

    float *ph, *ptmp, *pcls, *pbqkv;
    __nv_bfloat16 *pwhi, *pwlo, *pxhi, *pxlo, *phhi, *phlo, *pchi, *pclo, *pfhi, *pflo, *pqvh, *pqvl;
    cudaGetSymbolAddress((void**)&ph,   g_h);
    cudaGetSymbolAddress((void**)&ptmp, g_tmp);
    cudaGetSymbolAddress((void**)&pcls, g_cls);
    cudaGetSymbolAddress((void**)&pbqkv, g_bqkv);
    cudaGetSymbolAddress((void**)&pwhi, g_whi);
    cudaGetSymbolAddress((void**)&pwlo, g_wlo);
    cudaGetSymbolAddress((void**)&pxhi, g_xhi);
    cudaGetSymbolAddress((void**)&pxlo, g_xlo);
    cudaGetSymbolAddress((void**)&phhi, g_hhi);
    cudaGetSymbolAddress((void**)&phlo, g_hlo);
    cudaGetSymbolAddress((void**)&pchi, g_chi);
    cudaGetSymbolAddress((void**)&pclo, g_clo);
    cudaGetSymbolAddress((void**)&pfhi, g_fhi);
    cudaGetSymbolAddress((void**)&pflo, g_flo);
    cudaGetSymbolAddress((void**)&pqvh, g_qkvhi);
    cudaGetSymbolAddress((void**)&pqvl, g_qkvlo);

    EncFn enc = nullptr;
    cudaDriverEntryPointQueryResult qr;
    cudaGetDriverEntryPointByVersion("cuTensorMapEncodeTiled", (void**)&enc, 12000,
                                     cudaEnableDefault, &qr);

    auto mk2 = [&](CUtensorMap* m, void* p, uint64_t K) {
        cuuint64_t d[2] = {K, T_};
        cuuint64_t st[1] = {K * 2};
        cuuint32_t bx[2] = {64, 128}, es[2] = {1, 1};
        enc(m, CU_TENSOR_MAP_DATA_TYPE_BFLOAT16, 2, p, d, st, bx, es,
            CU_TENSOR_MAP_INTERLEAVE_NONE, CU_TENSOR_MAP_SWIZZLE_128B,
            CU_TENSOR_MAP_L2_PROMOTION_L2_128B, CU_TENSOR_MAP_FLOAT_OOB_FILL_NONE);
    };
    auto mk3 = [&](CUtensorMap* m, void* p, uint64_t K, uint64_t N, uint64_t Lz) {
        cuuint64_t d[3] = {K, N, Lz};
        cuuint64_t st[2] = {K * 2, N * K * 2};
        cuuint32_t bx[3] = {64, 128, 1}, es[3] = {1, 1, 1};
        enc(m, CU_TENSOR_MAP_DATA_TYPE_BFLOAT16, 3, p, d, st, bx, es,
            CU_TENSOR_MAP_INTERLEAVE_NONE, CU_TENSOR_MAP_SWIZZLE_128B,
            CU_TENSOR_MAP_L2_PROMOTION_L2_128B, CU_TENSOR_MAP_FLOAT_OOB_FILL_NONE);
    };

    CUtensorMap mxh, mxl, mhh, mhl, mch, mcl, mfh, mfl;
    CUtensorMap mpjh, mpjl, mqkvh, mqkvl, moh, mol, mih, mil, m2h, m2l;
    mk2(&mxh, pxhi, IN_); mk2(&mxl, pxlo, IN_);
    mk2(&mhh, phhi, D_);  mk2(&mhl, phlo, D_);
    mk2(&mch, pchi, D_);  mk2(&mcl, pclo, D_);
    mk2(&mfh, pfhi, FF_); mk2(&mfl, pflo, FF_);
    mk3(&mpjh, pwhi + OFF_PROJ, IN_, D_, 1);   mk3(&mpjl, pwlo + OFF_PROJ, IN_, D_, 1);
    mk3(&mqkvh, pwhi + OFF_QKV, D_, NQKV, L_); mk3(&mqkvl, pwlo + OFF_QKV, D_, NQKV, L_);
    mk3(&moh, pwhi + OFF_WO, D_, D_, L_);      mk3(&mol, pwlo + OFF_WO, D_, D_, L_);
    mk3(&mih, pwhi + OFF_WI, D_, FF_, L_);     mk3(&mil, pwlo + OFF_WI, D_, FF_, L_);
    mk3(&m2h, pwhi + OFF_WO2, FF_, D_, L_);    mk3(&m2l, pwlo + OFF_WO2, FF_, D_, L_);

    cudaFuncSetAttribute(tgemm_kernel<false, false, false, true, true>,
                         cudaFuncAttributeMaxDynamicSharedMemorySize, GEMM_SMEM);
    cudaFuncSetAttribute(tgemm_kernel<false, false, true, false, false>,
                         cudaFuncAttributeMaxDynamicSharedMemorySize, GEMM_SMEM);
    cudaFuncSetAttribute(tgemm_kernel<false, true, false, true, true>,
                         cudaFuncAttributeMaxDynamicSharedMemorySize, GEMM_SMEM);
    cudaFuncSetAttribute(tgemm_kernel<true, false, true, false, true>,
                         cudaFuncAttributeMaxDynamicSharedMemorySize, GEMM_SMEM);
    cudaFuncSetAttribute(attn_tc_kernel,
                         cudaFuncAttributeMaxDynamicSharedMemorySize, ATTN_SMEM);

    // prep
    dim3 tb(32, 8);
    tsplit_kernel<<<dim3(D_ / 32, IN_ / 32, 1), tb>>>((const float*)d_in[2], pwhi + OFF_PROJ, pwlo + OFF_PROJ, IN_, D_, IN_ * D_);
    tsplit_kernel<<<dim3(D_ / 32, D_ / 32, L_), tb>>>((const float*)d_in[8],  pwhi + OFF_QKV,               pwlo + OFF_QKV,               D_, D_, NQKV * D_);
    tsplit_kernel<<<dim3(D_ / 32, D_ / 32, L_), tb>>>((const float*)d_in[10], pwhi + OFF_QKV + 768 * 768,   pwlo + OFF_QKV + 768 * 768,   D_, D_, NQKV * D_);
    tsplit_kernel<<<dim3(D_ / 32, D_ / 32, L_), tb>>>((const float*)d_in[12], pwhi + OFF_QKV + 2 * 768 * 768, pwlo + OFF_QKV + 2 * 768 * 768, D_, D_, NQKV * D_);
    tsplit_kernel<<<dim3(D_ / 32, D_ / 32, L_), tb>>>((const float*)d_in[14], pwhi + OFF_WO, pwlo + OFF_WO, D_, D_, D_ * D_);
    tsplit_kernel<<<dim3(FF_ / 32, D_ / 32, L_), tb>>>((const float*)d_in[18], pwhi + OFF_WI, pwlo + OFF_WI, D_, FF_, D_ * FF_);
    tsplit_kernel<<<dim3(D_ / 32, FF_ / 32, L_), tb>>>((const float*)d_in[20], pwhi + OFF_WO2, pwlo + OFF_WO2, FF_, D_, FF_ * D_);
    split_kernel<<<(T_ * IN_ + 255) / 256, 256>>>(x, pxhi, pxlo, T_ * IN_);
    build_gi_kernel<<<1, 64>>>(rb);
    bcat_kernel<<<(L_ * NQKV + 255) / 256, 256>>>(bq_all, bk_all, bv_all);

    const dim3 gD(D_ / 128, T_ / 128);
    const dim3 gQKV(NQKV / 128, T_ / 128);
    const dim3 gF(FF_ / 128, T_ / 128);
    const dim3 gA(78, H_, B_);
    const dim3 gM(2, H_, B_);

    // embedding proj: 3-plane
    tgemm_kernel<false, false, false, true, true><<<gD, 256, GEMM_SMEM>>>(
        mxh, mxl, mpjh, mpjl, proj_b, nullptr, ptmp, nullptr, nullptr, D_, IN_, 0);
    ln_kernel<<<T_, 256>>>(ptmp, emb_g, emb_b, ph, phhi, phlo, pos_emb, tok_emb);

    for (int l = 0; l < L_; ++l) {
        // QKV: 2-plane (measured safe), hi+lo split output
        tgemm_kernel<false, false, true, false, false><<<gQKV, 256, GEMM_SMEM>>>(
            mhh, mhh, mqkvh, mqkvl, pbqkv + (size_t)l * NQKV, nullptr,
            nullptr, pqvh, pqvl, NQKV, D_, l);

        attn_tc_kernel<<<gA, 128, ATTN_SMEM>>>(pqvh, pqvl, mask);
        merge_kernel<<<gM, 256>>>();

        // wo: 3-plane, residual, f32 out
        tgemm_kernel<false, true, false, true, true><<<gD, 256, GEMM_SMEM>>>(
            mch, mcl, moh, mol, bo_all + (size_t)l * D_, ph, ptmp, nullptr, nullptr, D_, D_, l);
        ln_kernel<<<T_, 256>>>(ptmp, ln1g_all + (size_t)l * D_, ln1b_all + (size_t)l * D_,
                               ph, phhi, phlo, nullptr, nullptr);

        // wi: 3-plane with CORRECT A-lo plane (mhl), GELU, hi+lo split output
        tgemm_kernel<true, false, true, false, true><<<gF, 256, GEMM_SMEM>>>(
            mhh, mhl, mih, mil, bi_all + (size_t)l * FF_, nullptr, nullptr, pfhi, pflo, FF_, D_, l);
        // wo2: 3-plane, residual, f32 out
        tgemm_kernel<false, true, false, true, true><<<gD, 256, GEMM_SMEM>>>(
            mfh, mfl, m2h, m2l, bo2_all + (size_t)l * D_, ph, ptmp, nullptr, nullptr, D_, FF_, l);
        ln_kernel<<<T_, 256>>>(ptmp, ln2g_all + (size_t)l * D_, ln2b_all + (size_t)l * D_,
                               ph, phhi, phlo, nullptr, nullptr);
    }

    cls1_kernel<<<4, 256>>>(ph, cls_w1, cls_b1, pcls);
    cls2_kernel<<<8, 256>>>(pcls, cls_w2, cls_b2, out);
}

// round 14
// speedup vs baseline: 1.4645x; 1.2714x over previous
#include <cuda_runtime.h>
#include <cuda.h>
#include <cuda_fp16.h>
#include <math.h>
#include <stdint.h>

#define B_    2
#define S_    4096
#define T_    8192
#define IN_   1280
#define D_    768
#define H_    12
#define FF_   3072
#define L_    12
#define TGT_  1024
#define NB_   64
#define NQKV  2304

#define OFF_PROJ 0
#define OFF_QKV  (IN_*D_)
#define OFF_WO   (OFF_QKV + L_*NQKV*D_)
#define OFF_WI   (OFF_WO + L_*D_*D_)
#define OFF_WO2  (OFF_WI + L_*D_*FF_)
#define WTOT     (OFF_WO2 + L_*FF_*D_)

#define GEMM_SMEM (1024 + 3*65536)
#define ATTN_SMEM 55296

// ---------------- scratch ----------------
__device__ float g_h[T_ * D_];
__device__ float g_tmp[T_ * D_];
__device__ float g_cls[2 * 512];
__device__ float g_bqkv[L_ * NQKV];
__device__ int   g_gi[NB_ * 8];

__device__ __align__(128) __half g_whi[WTOT];
__device__ __align__(128) __half g_wlo[WTOT];
__device__ __align__(128) __half g_xhi[T_ * IN_];
__device__ __align__(128) __half g_xlo[T_ * IN_];
__device__ __align__(128) __half g_hhi[T_ * D_];
__device__ __align__(128) __half g_chi[T_ * D_];
__device__ __align__(128) __half g_fhi[T_ * FF_];
__device__ __align__(128) __half g_qkvhi[T_ * NQKV];
__device__ __align__(128) __half g_qkvlo[T_ * NQKV];
__device__ float g_part[B_ * H_ * 2 * 8 * 64 * 66];

// ---------------- PTX helpers ----------------
__device__ __forceinline__ uint32_t s2u(const void* p) { return (uint32_t)__cvta_generic_to_shared(p); }
__device__ __forceinline__ void mbar_init(uint32_t a, uint32_t c) {
    asm volatile("mbarrier.init.shared.b64 [%0], %1;" :: "r"(a), "r"(c) : "memory");
}
__device__ __forceinline__ void mbar_expect(uint32_t a, uint32_t b) {
    asm volatile("mbarrier.arrive.expect_tx.shared.b64 _, [%0], %1;" :: "r"(a), "r"(b) : "memory");
}
__device__ __forceinline__ void mbar_wait(uint32_t a, uint32_t par) {
    asm volatile("{\n\t.reg .pred P;\n\tW_%=:\n\t"
                 "mbarrier.try_wait.parity.acquire.cta.shared::cta.b64 P, [%0], %1, 0x989680;\n\t"
                 "@P bra.uni D_%=;\n\tbra.uni W_%=;\n\tD_%=:\n\t}" :: "r"(a), "r"(par) : "memory");
}
__device__ __forceinline__ void tma2d(uint32_t dst, const void* tm, int x, int y, uint32_t mb) {
    asm volatile("cp.async.bulk.tensor.2d.shared::cta.global.tile.mbarrier::complete_tx::bytes "
                 "[%0], [%1, {%2, %3}], [%4];" :: "r"(dst), "l"(tm), "r"(x), "r"(y), "r"(mb) : "memory");
}
__device__ __forceinline__ void tma3d(uint32_t dst, const void* tm, int x, int y, int z, uint32_t mb) {
    asm volatile("cp.async.bulk.tensor.3d.shared::cta.global.tile.mbarrier::complete_tx::bytes "
                 "[%0], [%1, {%2, %3, %4}], [%5];" :: "r"(dst), "l"(tm), "r"(x), "r"(y), "r"(z), "r"(mb) : "memory");
}
__device__ __forceinline__ void ldsm4a(uint32_t* r, uint32_t a) {
    asm volatile("ldmatrix.sync.aligned.m8n8.x4.shared.b16 {%0,%1,%2,%3}, [%4];"
                 : "=r"(r[0]), "=r"(r[1]), "=r"(r[2]), "=r"(r[3]) : "r"(a));
}
__device__ __forceinline__ void ldsm4t(uint32_t* r, uint32_t a) {
    asm volatile("ldmatrix.sync.aligned.m8n8.x4.trans.shared.b16 {%0,%1,%2,%3}, [%4];"
                 : "=r"(r[0]), "=r"(r[1]), "=r"(r[2]), "=r"(r[3]) : "r"(a));
}
__device__ __forceinline__ void mma16816(float* d, const uint32_t* a, uint32_t b0, uint32_t b1) {
    asm volatile("mma.sync.aligned.m16n8k16.row.col.f32.f16.f16.f32 "
                 "{%0,%1,%2,%3}, {%4,%5,%6,%7}, {%8,%9}, {%0,%1,%2,%3};"
                 : "+f"(d[0]), "+f"(d[1]), "+f"(d[2]), "+f"(d[3])
                 : "r"(a[0]), "r"(a[1]), "r"(a[2]), "r"(a[3]), "r"(b0), "r"(b1));
}
__device__ __forceinline__ uint32_t packh2(float a, float b) {
    __half2 t;
    t.x = __float2half(a);
    t.y = __float2half(b);
    return *(uint32_t*)&t;
}

// ---------------- prep kernels ----------------
__global__ void split_kernel(const float* __restrict__ s, __half* __restrict__ hi,
                             __half* __restrict__ lo, int n) {
    int i = blockIdx.x * blockDim.x + threadIdx.x;
    if (i >= n) return;
    float v = s[i];
    __half h = __float2half(v);
    hi[i] = h;
    lo[i] = __float2half(v - __half2float(h));
}

__global__ void tsplit_kernel(const float* __restrict__ src, __half* __restrict__ hi,
                              __half* __restrict__ lo, int K, int N, int lstride) {
    __shared__ float t[32][33];
    const int l = blockIdx.z;
    const int n0 = blockIdx.x * 32, k0 = blockIdx.y * 32;
    const float* S = src + (size_t)l * K * N;
    const int tx = threadIdx.x, ty = threadIdx.y;
#pragma unroll
    for (int j = 0; j < 4; ++j)
        t[ty + j * 8][tx] = S[(size_t)(k0 + ty + j * 8) * N + n0 + tx];
    __syncthreads();
    __half* Ht = hi + (size_t)l * lstride;
    __half* Lt = lo + (size_t)l * lstride;
#pragma unroll
    for (int j = 0; j < 4; ++j) {
        int n = n0 + ty + j * 8;
        float v = t[tx][ty + j * 8];
        __half h = __float2half(v);
        Ht[(size_t)n * K + k0 + tx] = h;
        Lt[(size_t)n * K + k0 + tx] = __float2half(v - __half2float(h));
    }
}

__global__ void build_gi_kernel(const int* __restrict__ rb) {
    int n = threadIdx.x;
    if (n < 1 || n >= NB_ - 1) return;
    int* p = g_gi + n * 8;
    p[0] = 0; p[1] = n - 1; p[2] = n; p[3] = n + 1; p[4] = NB_ - 1;
    p[5] = rb[n * 3 + 0]; p[6] = rb[n * 3 + 1]; p[7] = rb[n * 3 + 2];
}

__global__ void bcat_kernel(const float* __restrict__ bq, const float* __restrict__ bk,
                            const float* __restrict__ bv) {
    int i = blockIdx.x * blockDim.x + threadIdx.x;
    if (i >= L_ * NQKV) return;
    int l = i / NQKV, n = i % NQKV;
    float v = (n < 768) ? bq[l * 768 + n] : (n < 1536) ? bk[l * 768 + n - 768] : bv[l * 768 + n - 1536];
    g_bqkv[i] = v;
}

// ---------------- TMA + mma.sync fp16 GEMM (2/3-plane), 3-stage pipeline ----------------
// CTA 128x128, 256 thr = 8 warps (4x2 of 32x64). K64 chunks, triple buffered.
// 2-plane: C = Ahi*(Bhi+Blo)  (A truncated to fp16; err ~2^-11, calibrated safe at fp16)
template<bool GELU, bool RES, bool SPLITOUT, bool WRITEF32, bool THIRD, bool LOOUT>
__global__ __launch_bounds__(256, 1) void tgemm_kernel(
    const __grid_constant__ CUtensorMap tAh, const __grid_constant__ CUtensorMap tAl,
    const __grid_constant__ CUtensorMap tBh, const __grid_constant__ CUtensorMap tBl,
    const float* __restrict__ bias, const float* __restrict__ res,
    float* __restrict__ C, __half* __restrict__ Chi, __half* __restrict__ Clo,
    int N, int K, int layer)
{
    extern __shared__ char dsm[];
    const uint32_t ctl = s2u(dsm);
    const uint32_t tiles = (ctl + 64 + 1023) & ~1023u;
    const int tid = threadIdx.x;
    const int warp = tid >> 5, lane = tid & 31;
    const int wr = warp >> 1, wc = warp & 1;
    const int m0 = blockIdx.y * 128, n0 = blockIdx.x * 128;
    const int nch = K >> 6;

    if (tid == 0) {
        mbar_init(ctl, 1);
        mbar_init(ctl + 8, 1);
        mbar_init(ctl + 16, 1);
        asm volatile("fence.proxy.async.shared::cta;" ::: "memory");
    }
    __syncthreads();

    auto issue = [&](int i) {
        const int st = i % 3;
        const uint32_t mb = ctl + st * 8;
        const uint32_t tb = tiles + st * 65536;
        mbar_expect(mb, THIRD ? 65536 : 49152);
        const int k0 = i << 6;
        tma2d(tb +     0, &tAh, k0, m0, mb);
        if (THIRD) tma2d(tb + 16384, &tAl, k0, m0, mb);
        tma3d(tb + 32768, &tBh, k0, n0, layer, mb);
        tma3d(tb + 49152, &tBl, k0, n0, layer, mb);
    };
    const bool prod = (tid == 0);
    if (prod) {
        issue(0);
        if (nch > 1) issue(1);
        if (nch > 2) issue(2);
    }

    float acc[2][8][4];
#pragma unroll
    for (int mi = 0; mi < 2; ++mi)
#pragma unroll
        for (int ni = 0; ni < 8; ++ni)
#pragma unroll
            for (int r = 0; r < 4; ++r) acc[mi][ni][r] = 0.f;

    const int lrow = lane & 15;
    const uint32_t hb16 = (lane >> 4) * 16;
    uint32_t arow[2], axr[2], brow[4], bxr[4];
#pragma unroll
    for (int mi = 0; mi < 2; ++mi) {
        int r = wr * 32 + mi * 16 + lrow;
        arow[mi] = r * 128; axr[mi] = (r & 7) * 16;
    }
#pragma unroll
    for (int np = 0; np < 4; ++np) {
        int r = wc * 64 + np * 16 + lrow;
        brow[np] = r * 128; bxr[np] = (r & 7) * 16;
    }

    for (int i = 0; i < nch; ++i) {
        const int st = i % 3;
        mbar_wait(ctl + st * 8, (i / 3) & 1);
        const uint32_t bAh = tiles + st * 65536;
        const uint32_t bAl = bAh + 16384;
        const uint32_t bBh = bAh + 32768;
        const uint32_t bBl = bAh + 49152;
#pragma unroll
        for (int ks = 0; ks < 4; ++ks) {
            const uint32_t colb = ks * 32 + hb16;
            uint32_t ah[2][4], al[2][4];
#pragma unroll
            for (int mi = 0; mi < 2; ++mi) {
                ldsm4a(ah[mi], bAh + arow[mi] + (colb ^ axr[mi]));
                if (THIRD) ldsm4a(al[mi], bAl + arow[mi] + (colb ^ axr[mi]));
            }
#pragma unroll
            for (int np = 0; np < 4; ++np) {
                uint32_t bh[4], bl[4];
                ldsm4a(bh, bBh + brow[np] + (colb ^ bxr[np]));
                ldsm4a(bl, bBl + brow[np] + (colb ^ bxr[np]));
#pragma unroll
                for (int j = 0; j < 2; ++j) {
                    const int ni = np * 2 + j;
#pragma unroll
                    for (int mi = 0; mi < 2; ++mi) {
                        mma16816(acc[mi][ni], ah[mi], bh[j], bh[j + 2]);
                        mma16816(acc[mi][ni], ah[mi], bl[j], bl[j + 2]);
                        if (THIRD) mma16816(acc[mi][ni], al[mi], bh[j], bh[j + 2]);
                    }
                }
            }
        }
        __syncthreads();
        if (prod && i + 3 < nch) issue(i + 3);
    }

#pragma unroll
    for (int mi = 0; mi < 2; ++mi) {
        const int rbase = m0 + wr * 32 + mi * 16 + (lane >> 2);
#pragma unroll
        for (int ni = 0; ni < 8; ++ni) {
            const int cbase = n0 + wc * 64 + ni * 8 + (lane & 3) * 2;
            const float b0 = bias[cbase], b1 = bias[cbase + 1];
#pragma unroll
            for (int hr = 0; hr < 2; ++hr) {
                const int row = rbase + hr * 8;
                float v0 = acc[mi][ni][hr * 2 + 0] + b0;
                float v1 = acc[mi][ni][hr * 2 + 1] + b1;
                if (RES) {
                    v0 += res[(size_t)row * N + cbase];
                    v1 += res[(size_t)row * N + cbase + 1];
                }
                if (GELU) {
                    float u = v0;
                    v0 = 0.5f * u * (1.0f + tanhf(0.7978845608028654f * (u + 0.044715f * u * u * u)));
                    u = v1;
                    v1 = 0.5f * u * (1.0f + tanhf(0.7978845608028654f * (u + 0.044715f * u * u * u)));
                }
                const size_t idx = (size_t)row * N + cbase;
                if (WRITEF32) { C[idx] = v0; C[idx + 1] = v1; }
                if (SPLITOUT) {
                    __half h0 = __float2half(v0);
                    __half h1 = __float2half(v1);
                    Chi[idx] = h0; Chi[idx + 1] = h1;
                    if (LOOUT) {
                        Clo[idx]     = __float2half(v0 - __half2float(h0));
                        Clo[idx + 1] = __float2half(v1 - __half2float(h1));
                    }
                }
            }
        }
    }
}

// ---------------- LayerNorm (f32 + fp16-hi out) ----------------
__global__ __launch_bounds__(256) void ln_kernel(
    const float* __restrict__ in, const float* __restrict__ gamma,
    const float* __restrict__ beta, float* __restrict__ out,
    __half* __restrict__ ohi,
    const float* __restrict__ pos, const float* __restrict__ tok)
{
    const int r = blockIdx.x, s = r % S_, t = threadIdx.x;
    const float* row = in + (size_t)r * D_;
    float x[3];
#pragma unroll
    for (int j = 0; j < 3; ++j) {
        int i = t + j * 256;
        float v = row[i];
        if (pos) v += pos[(size_t)s * D_ + i] + tok[i];
        x[j] = v;
    }
    float sum = x[0] + x[1] + x[2];
    float sq  = x[0] * x[0] + x[1] * x[1] + x[2] * x[2];
    __shared__ float rs[8], rq[8];
#pragma unroll
    for (int o = 16; o > 0; o >>= 1) {
        sum += __shfl_xor_sync(0xffffffffu, sum, o);
        sq  += __shfl_xor_sync(0xffffffffu, sq, o);
    }
    if ((t & 31) == 0) { rs[t >> 5] = sum; rq[t >> 5] = sq; }
    __syncthreads();
    if (t < 32) {
        float s2 = (t < 8) ? rs[t] : 0.f;
        float q2 = (t < 8) ? rq[t] : 0.f;
#pragma unroll
        for (int o = 4; o > 0; o >>= 1) {
            s2 += __shfl_xor_sync(0xffffffffu, s2, o);
            q2 += __shfl_xor_sync(0xffffffffu, q2, o);
        }
        if (t == 0) { rs[0] = s2; rq[0] = q2; }
    }
    __syncthreads();
    const float mean = rs[0] * (1.0f / 768.0f);
    float var = rq[0] * (1.0f / 768.0f) - mean * mean;
    const float rstd = rsqrtf(fmaxf(var, 0.f) + 1e-12f);
#pragma unroll
    for (int j = 0; j < 3; ++j) {
        int i = t + j * 256;
        float y = (x[j] - mean) * rstd * gamma[i] + beta[i];
        size_t idx = (size_t)r * D_ + i;
        out[idx] = y;
        ohi[idx] = __float2half(y);
    }
}

// ---------------- tensor-core block-sparse flash attention (fp16x3) ----------------
__global__ __launch_bounds__(128, 3) void attn_tc_kernel(
    const __half* __restrict__ qkvh, const __half* __restrict__ qkvl,
    const float* __restrict__ mask)
{
    extern __shared__ char smraw[];
    const uint32_t su = s2u(smraw);
    const uint32_t QH = su, QL = su + 9216, KH = su + 18432, KL = su + 27648,
                   VH = su + 36864, VL = su + 46080;

    const int b = blockIdx.z, hh = blockIdx.y, ib = blockIdx.x;
    const int tid = threadIdx.x, warp = tid >> 5, lane = tid & 31;

    int qb, t0 = 0, e = 0, slice = 0;
    bool edge;
    if (ib < 62) { qb = ib + 1; edge = false; }
    else {
        edge = true;
        int xx = ib - 62;
        e = xx >> 3; slice = xx & 7;
        qb = e ? (NB_ - 1) : 0;
        t0 = slice * 8;
    }

    const int rrow = tid >> 1, half = tid & 1;
    {
        const size_t gq = (size_t)(b * S_ + qb * 64 + rrow) * NQKV + hh * 64 + half * 32;
        const uint4* s0 = (const uint4*)(qkvh + gq);
        const uint4* s1 = (const uint4*)(qkvl + gq);
        uint4* d0 = (uint4*)(smraw + rrow * 144 + half * 64);
        uint4* d1 = (uint4*)(smraw + 9216 + rrow * 144 + half * 64);
#pragma unroll
        for (int j = 0; j < 4; ++j) { d0[j] = s0[j]; d1[j] = s1[j]; }
    }

    float Sf[8][4], Of[8][4];
#pragma unroll
    for (int f = 0; f < 8; ++f)
#pragma unroll
        for (int r = 0; r < 4; ++r) Of[f][r] = 0.f;
    float m0 = -1e30f, m1 = -1e30f, l0 = 0.f, l1 = 0.f;

    const uint32_t lr15 = (lane & 15);
    const uint32_t hb = (lane >> 4);

    for (int kt = 0; kt < 8; ++kt) {
        const int kb = edge ? (t0 + kt) : g_gi[qb * 8 + kt];
        __syncthreads();
        {
            const size_t gk = (size_t)(b * S_ + kb * 64 + rrow) * NQKV + hh * 64 + half * 32;
            const uint4* kh = (const uint4*)(qkvh + gk + 768);
            const uint4* kl = (const uint4*)(qkvl + gk + 768);
            const uint4* vh = (const uint4*)(qkvh + gk + 1536);
            const uint4* vl = (const uint4*)(qkvl + gk + 1536);
            const int off = rrow * 144 + half * 64;
            uint4* dkh = (uint4*)(smraw + 18432 + off);
            uint4* dkl = (uint4*)(smraw + 27648 + off);
            uint4* dvh = (uint4*)(smraw + 36864 + off);
            uint4* dvl = (uint4*)(smraw + 46080 + off);
#pragma unroll
            for (int j = 0; j < 4; ++j) { dkh[j] = kh[j]; dkl[j] = kl[j]; dvh[j] = vh[j]; dvl[j] = vl[j]; }
        }
        __syncthreads();

#pragma unroll
        for (int f = 0; f < 8; ++f)
#pragma unroll
            for (int r = 0; r < 4; ++r) Sf[f][r] = 0.f;
#pragma unroll
        for (int ks = 0; ks < 4; ++ks) {
            const uint32_t colb = ks * 32 + hb * 16;
            const uint32_t qoff = (warp * 16 + lr15) * 144 + colb;
            uint32_t qh[4], ql[4];
            ldsm4a(qh, QH + qoff);
            ldsm4a(ql, QL + qoff);
#pragma unroll
            for (int np = 0; np < 4; ++np) {
                const uint32_t koff = (np * 16 + lr15) * 144 + colb;
                uint32_t kh[4], kl[4];
                ldsm4a(kh, KH + koff);
                ldsm4a(kl, KL + koff);
#pragma unroll
                for (int j = 0; j < 2; ++j) {
                    mma16816(Sf[np * 2 + j], qh, kh[j], kh[j + 2]);
                    mma16816(Sf[np * 2 + j], qh, kl[j], kl[j + 2]);
                    mma16816(Sf[np * 2 + j], ql, kh[j], kh[j + 2]);
                }
            }
        }

        const float* mrow = mask + (size_t)b * S_ + kb * 64;
        float t0m = -1e30f, t1m = -1e30f;
#pragma unroll
        for (int f = 0; f < 8; ++f) {
            const int c = f * 8 + 2 * (lane & 3);
            const float2 mk = *(const float2*)(mrow + c);
            Sf[f][0] = Sf[f][0] * 0.125f - 1e9f * (1.f - mk.x);
            Sf[f][1] = Sf[f][1] * 0.125f - 1e9f * (1.f - mk.y);
            Sf[f][2] = Sf[f][2] * 0.125f - 1e9f * (1.f - mk.x);
            Sf[f][3] = Sf[f][3] * 0.125f - 1e9f * (1.f - mk.y);
            t0m = fmaxf(t0m, fmaxf(Sf[f][0], Sf[f][1]));
            t1m = fmaxf(t1m, fmaxf(Sf[f][2], Sf[f][3]));
        }
        t0m = fmaxf(t0m, __shfl_xor_sync(0xffffffffu, t0m, 1));
        t0m = fmaxf(t0m, __shfl_xor_sync(0xffffffffu, t0m, 2));
        t1m = fmaxf(t1m, __shfl_xor_sync(0xffffffffu, t1m, 1));
        t1m = fmaxf(t1m, __shfl_xor_sync(0xffffffffu, t1m, 2));
        const float mn0 = fmaxf(m0, t0m), mn1 = fmaxf(m1, t1m);
        const float cr0 = __expf(m0 - mn0), cr1 = __expf(m1 - mn1);
        float ps0 = 0.f, ps1 = 0.f;
#pragma unroll
        for (int f = 0; f < 8; ++f) {
            Sf[f][0] = __expf(Sf[f][0] - mn0);
            Sf[f][1] = __expf(Sf[f][1] - mn0);
            Sf[f][2] = __expf(Sf[f][2] - mn1);
            Sf[f][3] = __expf(Sf[f][3] - mn1);
            ps0 += Sf[f][0] + Sf[f][1];
            ps1 += Sf[f][2] + Sf[f][3];
        }
        ps0 += __shfl_xor_sync(0xffffffffu, ps0, 1);
        ps0 += __shfl_xor_sync(0xffffffffu, ps0, 2);
        ps1 += __shfl_xor_sync(0xffffffffu, ps1, 1);
        ps1 += __shfl_xor_sync(0xffffffffu, ps1, 2);
        l0 = l0 * cr0 + ps0; m0 = mn0;
        l1 = l1 * cr1 + ps1; m1 = mn1;
#pragma unroll
        for (int f = 0; f < 8; ++f) {
            Of[f][0] *= cr0; Of[f][1] *= cr0; Of[f][2] *= cr1; Of[f][3] *= cr1;
        }

        uint32_t ph[4][4], pl[4][4];
#pragma unroll
        for (int j2 = 0; j2 < 4; ++j2) {
            const float* A = Sf[2 * j2];
            const float* Bq = Sf[2 * j2 + 1];
#pragma unroll
            for (int q2 = 0; q2 < 2; ++q2) {
                const float* src = q2 ? Bq : A;
                __half2 t;
                t.x = __float2half(src[0]); t.y = __float2half(src[1]);
                ph[j2][q2 * 2 + 0] = *(uint32_t*)&t;
                pl[j2][q2 * 2 + 0] = packh2(src[0] - __half2float(t.x), src[1] - __half2float(t.y));
                t.x = __float2half(src[2]); t.y = __float2half(src[3]);
                ph[j2][q2 * 2 + 1] = *(uint32_t*)&t;
                pl[j2][q2 * 2 + 1] = packh2(src[2] - __half2float(t.x), src[3] - __half2float(t.y));
            }
        }

#pragma unroll
        for (int ks2 = 0; ks2 < 4; ++ks2) {
#pragma unroll
            for (int g = 0; g < 4; ++g) {
                const uint32_t voff = (ks2 * 16 + lr15) * 144 + (g * 16 + hb * 8) * 2;
                uint32_t vh[4], vl[4];
                ldsm4t(vh, VH + voff);
                ldsm4t(vl, VL + voff);
#pragma unroll
                for (int j = 0; j < 2; ++j) {
                    mma16816(Of[g * 2 + j], ph[ks2], vh[2 * j], vh[2 * j + 1]);
                    mma16816(Of[g * 2 + j], ph[ks2], vl[2 * j], vl[2 * j + 1]);
                    mma16816(Of[g * 2 + j], pl[ks2], vh[2 * j], vh[2 * j + 1]);
                }
            }
        }
    }

    const int r0 = warp * 16 + (lane >> 2);
    if (!edge) {
        const float inv0 = 1.f / l0, inv1 = 1.f / l1;
        const size_t tk0 = (size_t)(b * S_ + qb * 64 + r0) * D_ + hh * 64;
        const size_t tk1 = tk0 + 8 * D_;
#pragma unroll
        for (int f = 0; f < 8; ++f) {
            const int c = f * 8 + 2 * (lane & 3);
            __half2 h01, h23;
            h01.x = __float2half(Of[f][0] * inv0);
            h01.y = __float2half(Of[f][1] * inv0);
            h23.x = __float2half(Of[f][2] * inv1);
            h23.y = __float2half(Of[f][3] * inv1);
            *(__half2*)(g_chi + tk0 + c) = h01;
            *(__half2*)(g_chi + tk1 + c) = h23;
        }
    } else {
        float* base = g_part + ((size_t)((((b * H_ + hh) * 2 + e) * 8 + slice) * 64)) * 66;
        float* pp0 = base + (size_t)r0 * 66;
        float* pp1 = base + (size_t)(r0 + 8) * 66;
#pragma unroll
        for (int f = 0; f < 8; ++f) {
            const int c = f * 8 + 2 * (lane & 3);
            pp0[c] = Of[f][0]; pp0[c + 1] = Of[f][1];
            pp1[c] = Of[f][2]; pp1[c + 1] = Of[f][3];
        }
        if ((lane & 3) == 0) {
            pp0[64] = m0; pp0[65] = l0;
            pp1[64] = m1; pp1[65] = l1;
        }
    }
}

__global__ __launch_bounds__(256) void merge_kernel() {
    const int e = blockIdx.x, hh = blockIdx.y, b = blockIdx.z;
    const int tid = threadIdx.x;
    const int r = tid >> 2, t4 = tid & 3;
    const size_t base = ((size_t)(((b * H_ + hh) * 2 + e) * 8)) * 64 * 66;

    float M = -1e30f;
#pragma unroll
    for (int s = 0; s < 8; ++s) M = fmaxf(M, g_part[base + ((size_t)s * 64 + r) * 66 + 64]);
    float L = 0.f, acc[16];
#pragma unroll
    for (int i = 0; i < 16; ++i) acc[i] = 0.f;
#pragma unroll
    for (int s = 0; s < 8; ++s) {
        const float* pp = g_part + base + ((size_t)s * 64 + r) * 66;
        const float w = __expf(pp[64] - M);
        L += pp[65] * w;
#pragma unroll
        for (int i = 0; i < 16; ++i) acc[i] += pp[t4 * 16 + i] * w;
    }
    const float inv = 1.0f / L;
    const int qb = e ? (NB_ - 1) : 0;
    const size_t idx = ((size_t)(b * S_ + qb * 64 + r)) * D_ + hh * 64 + t4 * 16;
#pragma unroll
    for (int i = 0; i < 16; ++i)
        g_chi[idx + i] = __float2half(acc[i] * inv);
}

// ---------------- classifier ----------------
__global__ void cls1_kernel(const float* __restrict__ h, const float* __restrict__ w,
                            const float* __restrict__ bias, float* __restrict__ out) {
    int gid = blockIdx.x * blockDim.x + threadIdx.x;
    if (gid >= 2 * 512) return;
    int b = gid >> 9, n = gid & 511;
    const float* hrow = h + (size_t)b * S_ * D_;
    float s = 0.f;
    for (int k2 = 0; k2 < D_; ++k2) s += hrow[k2] * w[(size_t)k2 * 512 + n];
    out[gid] = fmaxf(s + bias[n], 0.f);
}
__global__ void cls2_kernel(const float* __restrict__ rin, const float* __restrict__ w,
                            const float* __restrict__ bias, float* __restrict__ out) {
    int gid = blockIdx.x * blockDim.x + threadIdx.x;
    if (gid >= 2 * TGT_) return;
    int b = gid >> 10, n = gid & 1023;
    float s = 0.f;
    for (int k2 = 0; k2 < 512; ++k2) s += rin[b * 512 + k2] * w[(size_t)k2 * TGT_ + n];
    out[gid] = s + bias[n];
}

// ---------------- host ----------------
typedef CUresult (*EncFn)(CUtensorMap*, CUtensorMapDataType, cuuint32_t, void*,
                          const cuuint64_t*, const cuuint64_t*, const cuuint32_t*, const cuuint32_t*,
                          CUtensorMapInterleave, CUtensorMapSwizzle, CUtensorMapL2promotion,
                          CUtensorMapFloatOOBfill);

extern "C" void kernel_launch(void* const* d_in, const int* in_sizes, int n_in,
                              void* d_out, int out_size)
{
    const float* x        = (const float*)d_in[0];
    const float* mask     = (const float*)d_in[1];
    const float* proj_b   = (const float*)d_in[3];
    const float* pos_emb  = (const float*)d_in[4];
    const float* tok_emb  = (const float*)d_in[5];
    const float* emb_g    = (const float*)d_in[6];
    const float* emb_b    = (const float*)d_in[7];
    const float* bq_all   = (const float*)d_in[9];
    const float* bk_all   = (const float*)d_in[11];
    const float* bv_all   = (const float*)d_in[13];
    const float* bo_all   = (const float*)d_in[15];
    const float* ln1g_all = (const float*)d_in[16];
    const float* ln1b_all = (const float*)d_in[17];
    const float* bi_all   = (const float*)d_in[19];
    const float* bo2_all  = (const float*)d_in[21];
    const float* ln2g_all = (const float*)d_in[22];
    const float* ln2b_all = (const float*)d_in[23];
    const float* cls_w1   = (const float*)d_in[24];
    const float* cls_b1   = (const float*)d_in[25];
    const float* cls_w2   = (const float*)d_in[26];
    const float* cls_b2   = (const float*)d_in[27];
    const int*   rb       = (const int*)d_in[28];
    float* out = (float*)d_out;

    float *ph, *ptmp, *pcls, *pbqkv;
    __half *pwhi, *pwlo, *pxhi, *pxlo, *phhi, *pchi, *pfhi, *pqvh, *pqvl;
    cudaGetSymbolAddress((void**)&ph,   g_h);
    cudaGetSymbolAddress((void**)&ptmp, g_tmp);
    cudaGetSymbolAddress((void**)&pcls, g_cls);
    cudaGetSymbolAddress((void**)&pbqkv, g_bqkv);
    cudaGetSymbolAddress((void**)&pwhi, g_whi);
    cudaGetSymbolAddress((void**)&pwlo, g_wlo);
    cudaGetSymbolAddress((void**)&pxhi, g_xhi);
    cudaGetSymbolAddress((void**)&pxlo, g_xlo);
    cudaGetSymbolAddress((void**)&phhi, g_hhi);
    cudaGetSymbolAddress((void**)&pchi, g_chi);
    cudaGetSymbolAddress((void**)&pfhi, g_fhi);
    cudaGetSymbolAddress((void**)&pqvh, g_qkvhi);
    cudaGetSymbolAddress((void**)&pqvl, g_qkvlo);

    EncFn enc = nullptr;
    cudaDriverEntryPointQueryResult qr;
    cudaGetDriverEntryPointByVersion("cuTensorMapEncodeTiled", (void**)&enc, 12000,
                                     cudaEnableDefault, &qr);

    auto mk2 = [&](CUtensorMap* m, void* p, uint64_t K) {
        cuuint64_t d[2] = {K, T_};
        cuuint64_t st[1] = {K * 2};
        cuuint32_t bx[2] = {64, 128}, es[2] = {1, 1};
        enc(m, CU_TENSOR_MAP_DATA_TYPE_FLOAT16, 2, p, d, st, bx, es,
            CU_TENSOR_MAP_INTERLEAVE_NONE, CU_TENSOR_MAP_SWIZZLE_128B,
            CU_TENSOR_MAP_L2_PROMOTION_L2_128B, CU_TENSOR_MAP_FLOAT_OOB_FILL_NONE);
    };
    auto mk3 = [&](CUtensorMap* m, void* p, uint64_t K, uint64_t N, uint64_t Lz) {
        cuuint64_t d[3] = {K, N, Lz};
        cuuint64_t st[2] = {K * 2, N * K * 2};
        cuuint32_t bx[3] = {64, 128, 1}, es[3] = {1, 1, 1};
        enc(m, CU_TENSOR_MAP_DATA_TYPE_FLOAT16, 3, p, d, st, bx, es,
            CU_TENSOR_MAP_INTERLEAVE_NONE, CU_TENSOR_MAP_SWIZZLE_128B,
            CU_TENSOR_MAP_L2_PROMOTION_L2_128B, CU_TENSOR_MAP_FLOAT_OOB_FILL_NONE);
    };

    CUtensorMap mxh, mxl, mhh, mch, mfh;
    CUtensorMap mpjh, mpjl, mqkvh, mqkvl, moh, mol, mih, mil, m2h, m2l;
    mk2(&mxh, pxhi, IN_); mk2(&mxl, pxlo, IN_);
    mk2(&mhh, phhi, D_);
    mk2(&mch, pchi, D_);
    mk2(&mfh, pfhi, FF_);
    mk3(&mpjh, pwhi + OFF_PROJ, IN_, D_, 1);   mk3(&mpjl, pwlo + OFF_PROJ, IN_, D_, 1);
    mk3(&mqkvh, pwhi + OFF_QKV, D_, NQKV, L_); mk3(&mqkvl, pwlo + OFF_QKV, D_, NQKV, L_);
    mk3(&moh, pwhi + OFF_WO, D_, D_, L_);      mk3(&mol, pwlo + OFF_WO, D_, D_, L_);
    mk3(&mih, pwhi + OFF_WI, D_, FF_, L_);     mk3(&mil, pwlo + OFF_WI, D_, FF_, L_);
    mk3(&m2h, pwhi + OFF_WO2, FF_, D_, L_);    mk3(&m2l, pwlo + OFF_WO2, FF_, D_, L_);

    cudaFuncSetAttribute(tgemm_kernel<false, false, false, true, true, false>,
                         cudaFuncAttributeMaxDynamicSharedMemorySize, GEMM_SMEM);
    cudaFuncSetAttribute(tgemm_kernel<false, false, true, false, false, true>,
                         cudaFuncAttributeMaxDynamicSharedMemorySize, GEMM_SMEM);
    cudaFuncSetAttribute(tgemm_kernel<false, true, false, true, false, false>,
                         cudaFuncAttributeMaxDynamicSharedMemorySize, GEMM_SMEM);
    cudaFuncSetAttribute(tgemm_kernel<true, false, true, false, false, false>,
                         cudaFuncAttributeMaxDynamicSharedMemorySize, GEMM_SMEM);
    cudaFuncSetAttribute(attn_tc_kernel,
                         cudaFuncAttributeMaxDynamicSharedMemorySize, ATTN_SMEM);

    // prep
    dim3 tb(32, 8);
    tsplit_kernel<<<dim3(D_ / 32, IN_ / 32, 1), tb>>>((const float*)d_in[2], pwhi + OFF_PROJ, pwlo + OFF_PROJ, IN_, D_, IN_ * D_);
    tsplit_kernel<<<dim3(D_ / 32, D_ / 32, L_), tb>>>((const float*)d_in[8],  pwhi + OFF_QKV,               pwlo + OFF_QKV,               D_, D_, NQKV * D_);
    tsplit_kernel<<<dim3(D_ / 32, D_ / 32, L_), tb>>>((const float*)d_in[10], pwhi + OFF_QKV + 768 * 768,   pwlo + OFF_QKV + 768 * 768,   D_, D_, NQKV * D_);
    tsplit_kernel<<<dim3(D_ / 32, D_ / 32, L_), tb>>>((const float*)d_in[12], pwhi + OFF_QKV + 2 * 768 * 768, pwlo + OFF_QKV + 2 * 768 * 768, D_, D_, NQKV * D_);
    tsplit_kernel<<<dim3(D_ / 32, D_ / 32, L_), tb>>>((const float*)d_in[14], pwhi + OFF_WO, pwlo + OFF_WO, D_, D_, D_ * D_);
    tsplit_kernel<<<dim3(FF_ / 32, D_ / 32, L_), tb>>>((const float*)d_in[18], pwhi + OFF_WI, pwlo + OFF_WI, D_, FF_, D_ * FF_);
    tsplit_kernel<<<dim3(D_ / 32, FF_ / 32, L_), tb>>>((const float*)d_in[20], pwhi + OFF_WO2, pwlo + OFF_WO2, FF_, D_, FF_ * D_);
    split_kernel<<<(T_ * IN_ + 255) / 256, 256>>>(x, pxhi, pxlo, T_ * IN_);
    build_gi_kernel<<<1, 64>>>(rb);
    bcat_kernel<<<(L_ * NQKV + 255) / 256, 256>>>(bq_all, bk_all, bv_all);

    const dim3 gD(D_ / 128, T_ / 128);
    const dim3 gQKV(NQKV / 128, T_ / 128);
    const dim3 gF(FF_ / 128, T_ / 128);
    const dim3 gA(78, H_, B_);
    const dim3 gM(2, H_, B_);

    // embedding proj: 3-plane fp16
    tgemm_kernel<false, false, false, true, true, false><<<gD, 256, GEMM_SMEM>>>(
        mxh, mxl, mpjh, mpjl, proj_b, nullptr, ptmp, nullptr, nullptr, D_, IN_, 0);
    ln_kernel<<<T_, 256>>>(ptmp, emb_g, emb_b, ph, phhi, pos_emb, tok_emb);

    for (int l = 0; l < L_; ++l) {
        // QKV: 2-plane fp16, hi+lo split output for attention
        tgemm_kernel<false, false, true, false, false, true><<<gQKV, 256, GEMM_SMEM>>>(
            mhh, mhh, mqkvh, mqkvl, pbqkv + (size_t)l * NQKV, nullptr,
            nullptr, pqvh, pqvl, NQKV, D_, l);

        attn_tc_kernel<<<gA, 128, ATTN_SMEM>>>(pqvh, pqvl, mask);
        merge_kernel<<<gM, 256>>>();

        // wo: 2-plane fp16 (ctx hi), residual, f32 out
        tgemm_kernel<false, true, false, true, false, false><<<gD, 256, GEMM_SMEM>>>(
            mch, mch, moh, mol, bo_all + (size_t)l * D_, ph, ptmp, nullptr, nullptr, D_, D_, l);
        ln_kernel<<<T_, 256>>>(ptmp, ln1g_all + (size_t)l * D_, ln1b_all + (size_t)l * D_,
                               ph, phhi, nullptr, nullptr);

        // wi: 2-plane fp16 (h hi), GELU, hi-only split output
        tgemm_kernel<true, false, true, false, false, false><<<gF, 256, GEMM_SMEM>>>(
            mhh, mhh, mih, mil, bi_all + (size_t)l * FF_, nullptr, nullptr, pfhi, nullptr, FF_, D_, l);
        // wo2: 2-plane fp16 (f hi), residual, f32 out
        tgemm_kernel<false, true, false, true, false, false><<<gD, 256, GEMM_SMEM>>>(
            mfh, mfh, m2h, m2l, bo2_all + (size_t)l * D_, ph, ptmp, nullptr, nullptr, D_, FF_, l);
        ln_kernel<<<T_, 256>>>(ptmp, ln2g_all + (size_t)l * D_, ln2b_all + (size_t)l * D_,
                               ph, phhi, nullptr, nullptr);
    }

    cls1_kernel<<<4, 256>>>(ph, cls_w1, cls_b1, pcls);
    cls2_kernel<<<8, 256>>>(pcls, cls_w2, cls_b2, out);
}

// round 15
// speedup vs baseline: 1.7842x; 1.2183x over previous
#include <cuda_runtime.h>
#include <cuda.h>
#include <cuda_fp16.h>
#include <math.h>
#include <stdint.h>

#define B_    2
#define S_    4096
#define T_    8192
#define IN_   1280
#define D_    768
#define H_    12
#define FF_   3072
#define L_    12
#define TGT_  1024
#define NB_   64
#define NQKV  2304

#define OFF_PROJ 0
#define OFF_QKV  (IN_*D_)
#define OFF_WO   (OFF_QKV + L_*NQKV*D_)
#define OFF_WI   (OFF_WO + L_*D_*D_)
#define OFF_WO2  (OFF_WI + L_*D_*FF_)
#define WTOT     (OFF_WO2 + L_*FF_*D_)

#define GEMM_SMEM (1024 + 3*65536)
#define ATTN_SMEM 55296

// ---------------- scratch ----------------
__device__ float g_h[T_ * D_];
__device__ float g_tmp[T_ * D_];
__device__ float g_cls[2 * 512];
__device__ float g_bqkv[L_ * NQKV];
__device__ int   g_gi[NB_ * 8];

__device__ __align__(128) __half g_whi[WTOT];
__device__ __align__(128) __half g_wlo[WTOT];
__device__ __align__(128) __half g_xhi[T_ * IN_];
__device__ __align__(128) __half g_xlo[T_ * IN_];
__device__ __align__(128) __half g_hhi[T_ * D_];
__device__ __align__(128) __half g_chi[T_ * D_];
__device__ __align__(128) __half g_fhi[T_ * FF_];
__device__ __align__(128) __half g_qkvhi[T_ * NQKV];
__device__ __align__(128) __half g_qkvlo[T_ * NQKV];
__device__ float g_part[B_ * H_ * 2 * 8 * 64 * 66];

// ---------------- PTX helpers ----------------
__device__ __forceinline__ uint32_t s2u(const void* p) { return (uint32_t)__cvta_generic_to_shared(p); }
__device__ __forceinline__ void mbar_init(uint32_t a, uint32_t c) {
    asm volatile("mbarrier.init.shared.b64 [%0], %1;" :: "r"(a), "r"(c) : "memory");
}
__device__ __forceinline__ void mbar_expect(uint32_t a, uint32_t b) {
    asm volatile("mbarrier.arrive.expect_tx.shared.b64 _, [%0], %1;" :: "r"(a), "r"(b) : "memory");
}
__device__ __forceinline__ void mbar_wait(uint32_t a, uint32_t par) {
    asm volatile("{\n\t.reg .pred P;\n\tW_%=:\n\t"
                 "mbarrier.try_wait.parity.acquire.cta.shared::cta.b64 P, [%0], %1, 0x989680;\n\t"
                 "@P bra.uni D_%=;\n\tbra.uni W_%=;\n\tD_%=:\n\t}" :: "r"(a), "r"(par) : "memory");
}
__device__ __forceinline__ void tma2d(uint32_t dst, const void* tm, int x, int y, uint32_t mb) {
    asm volatile("cp.async.bulk.tensor.2d.shared::cta.global.tile.mbarrier::complete_tx::bytes "
                 "[%0], [%1, {%2, %3}], [%4];" :: "r"(dst), "l"(tm), "r"(x), "r"(y), "r"(mb) : "memory");
}
__device__ __forceinline__ void tma3d(uint32_t dst, const void* tm, int x, int y, int z, uint32_t mb) {
    asm volatile("cp.async.bulk.tensor.3d.shared::cta.global.tile.mbarrier::complete_tx::bytes "
                 "[%0], [%1, {%2, %3, %4}], [%5];" :: "r"(dst), "l"(tm), "r"(x), "r"(y), "r"(z), "r"(mb) : "memory");
}
__device__ __forceinline__ void ldsm4a(uint32_t* r, uint32_t a) {
    asm volatile("ldmatrix.sync.aligned.m8n8.x4.shared.b16 {%0,%1,%2,%3}, [%4];"
                 : "=r"(r[0]), "=r"(r[1]), "=r"(r[2]), "=r"(r[3]) : "r"(a));
}
__device__ __forceinline__ void ldsm4t(uint32_t* r, uint32_t a) {
    asm volatile("ldmatrix.sync.aligned.m8n8.x4.trans.shared.b16 {%0,%1,%2,%3}, [%4];"
                 : "=r"(r[0]), "=r"(r[1]), "=r"(r[2]), "=r"(r[3]) : "r"(a));
}
__device__ __forceinline__ void mma16816(float* d, const uint32_t* a, uint32_t b0, uint32_t b1) {
    asm volatile("mma.sync.aligned.m16n8k16.row.col.f32.f16.f16.f32 "
                 "{%0,%1,%2,%3}, {%4,%5,%6,%7}, {%8,%9}, {%0,%1,%2,%3};"
                 : "+f"(d[0]), "+f"(d[1]), "+f"(d[2]), "+f"(d[3])
                 : "r"(a[0]), "r"(a[1]), "r"(a[2]), "r"(a[3]), "r"(b0), "r"(b1));
}

// ---------------- prep kernels ----------------
__global__ void split_kernel(const float* __restrict__ s, __half* __restrict__ hi,
                             __half* __restrict__ lo, int n) {
    int i = blockIdx.x * blockDim.x + threadIdx.x;
    if (i >= n) return;
    float v = s[i];
    __half h = __float2half(v);
    hi[i] = h;
    lo[i] = __float2half(v - __half2float(h));
}

__global__ void tsplit_kernel(const float* __restrict__ src, __half* __restrict__ hi,
                              __half* __restrict__ lo, int K, int N, int lstride) {
    __shared__ float t[32][33];
    const int l = blockIdx.z;
    const int n0 = blockIdx.x * 32, k0 = blockIdx.y * 32;
    const float* S = src + (size_t)l * K * N;
    const int tx = threadIdx.x, ty = threadIdx.y;
#pragma unroll
    for (int j = 0; j < 4; ++j)
        t[ty + j * 8][tx] = S[(size_t)(k0 + ty + j * 8) * N + n0 + tx];
    __syncthreads();
    __half* Ht = hi + (size_t)l * lstride;
    __half* Lt = lo + (size_t)l * lstride;
#pragma unroll
    for (int j = 0; j < 4; ++j) {
        int n = n0 + ty + j * 8;
        float v = t[tx][ty + j * 8];
        __half h = __float2half(v);
        Ht[(size_t)n * K + k0 + tx] = h;
        Lt[(size_t)n * K + k0 + tx] = __float2half(v - __half2float(h));
    }
}

__global__ void build_gi_kernel(const int* __restrict__ rb) {
    int n = threadIdx.x;
    if (n < 1 || n >= NB_ - 1) return;
    int* p = g_gi + n * 8;
    p[0] = 0; p[1] = n - 1; p[2] = n; p[3] = n + 1; p[4] = NB_ - 1;
    p[5] = rb[n * 3 + 0]; p[6] = rb[n * 3 + 1]; p[7] = rb[n * 3 + 2];
}

__global__ void bcat_kernel(const float* __restrict__ bq, const float* __restrict__ bk,
                            const float* __restrict__ bv) {
    int i = blockIdx.x * blockDim.x + threadIdx.x;
    if (i >= L_ * NQKV) return;
    int l = i / NQKV, n = i % NQKV;
    float v = (n < 768) ? bq[l * 768 + n] : (n < 1536) ? bk[l * 768 + n - 768] : bv[l * 768 + n - 1536];
    g_bqkv[i] = v;
}

// ---------------- TMA + mma.sync fp16 GEMM (1/2/3-plane), 3-stage pipeline ----------------
// ALO: use A-lo plane (alo*bhi term). BLO: use B-lo plane (ahi*blo term).
template<bool GELU, bool RES, bool SPLITOUT, bool WRITEF32, bool ALO, bool BLO, bool LOOUT>
__global__ __launch_bounds__(256, 1) void tgemm_kernel(
    const __grid_constant__ CUtensorMap tAh, const __grid_constant__ CUtensorMap tAl,
    const __grid_constant__ CUtensorMap tBh, const __grid_constant__ CUtensorMap tBl,
    const float* __restrict__ bias, const float* __restrict__ res,
    float* __restrict__ C, __half* __restrict__ Chi, __half* __restrict__ Clo,
    int N, int K, int layer)
{
    extern __shared__ char dsm[];
    const uint32_t ctl = s2u(dsm);
    const uint32_t tiles = (ctl + 64 + 1023) & ~1023u;
    const int tid = threadIdx.x;
    const int warp = tid >> 5, lane = tid & 31;
    const int wr = warp >> 1, wc = warp & 1;
    const int m0 = blockIdx.y * 128, n0 = blockIdx.x * 128;
    const int nch = K >> 6;

    if (tid == 0) {
        mbar_init(ctl, 1);
        mbar_init(ctl + 8, 1);
        mbar_init(ctl + 16, 1);
        asm volatile("fence.proxy.async.shared::cta;" ::: "memory");
    }
    __syncthreads();

    auto issue = [&](int i) {
        const int st = i % 3;
        const uint32_t mb = ctl + st * 8;
        const uint32_t tb = tiles + st * 65536;
        mbar_expect(mb, 16384u * (2 + (ALO ? 1 : 0) + (BLO ? 1 : 0)));
        const int k0 = i << 6;
        tma2d(tb +     0, &tAh, k0, m0, mb);
        if (ALO) tma2d(tb + 16384, &tAl, k0, m0, mb);
        tma3d(tb + 32768, &tBh, k0, n0, layer, mb);
        if (BLO) tma3d(tb + 49152, &tBl, k0, n0, layer, mb);
    };
    const bool prod = (tid == 0);
    if (prod) {
        issue(0);
        if (nch > 1) issue(1);
        if (nch > 2) issue(2);
    }

    float acc[2][8][4];
#pragma unroll
    for (int mi = 0; mi < 2; ++mi)
#pragma unroll
        for (int ni = 0; ni < 8; ++ni)
#pragma unroll
            for (int r = 0; r < 4; ++r) acc[mi][ni][r] = 0.f;

    const int lrow = lane & 15;
    const uint32_t hb16 = (lane >> 4) * 16;
    uint32_t arow[2], axr[2], brow[4], bxr[4];
#pragma unroll
    for (int mi = 0; mi < 2; ++mi) {
        int r = wr * 32 + mi * 16 + lrow;
        arow[mi] = r * 128; axr[mi] = (r & 7) * 16;
    }
#pragma unroll
    for (int np = 0; np < 4; ++np) {
        int r = wc * 64 + np * 16 + lrow;
        brow[np] = r * 128; bxr[np] = (r & 7) * 16;
    }

    for (int i = 0; i < nch; ++i) {
        const int st = i % 3;
        mbar_wait(ctl + st * 8, (i / 3) & 1);
        const uint32_t bAh = tiles + st * 65536;
        const uint32_t bAl = bAh + 16384;
        const uint32_t bBh = bAh + 32768;
        const uint32_t bBl = bAh + 49152;
#pragma unroll
        for (int ks = 0; ks < 4; ++ks) {
            const uint32_t colb = ks * 32 + hb16;
            uint32_t ah[2][4], al[2][4];
#pragma unroll
            for (int mi = 0; mi < 2; ++mi) {
                ldsm4a(ah[mi], bAh + arow[mi] + (colb ^ axr[mi]));
                if (ALO) ldsm4a(al[mi], bAl + arow[mi] + (colb ^ axr[mi]));
            }
#pragma unroll
            for (int np = 0; np < 4; ++np) {
                uint32_t bh[4], bl[4];
                ldsm4a(bh, bBh + brow[np] + (colb ^ bxr[np]));
                if (BLO) ldsm4a(bl, bBl + brow[np] + (colb ^ bxr[np]));
#pragma unroll
                for (int j = 0; j < 2; ++j) {
                    const int ni = np * 2 + j;
#pragma unroll
                    for (int mi = 0; mi < 2; ++mi) {
                        mma16816(acc[mi][ni], ah[mi], bh[j], bh[j + 2]);
                        if (BLO) mma16816(acc[mi][ni], ah[mi], bl[j], bl[j + 2]);
                        if (ALO) mma16816(acc[mi][ni], al[mi], bh[j], bh[j + 2]);
                    }
                }
            }
        }
        __syncthreads();
        if (prod && i + 3 < nch) issue(i + 3);
    }

#pragma unroll
    for (int mi = 0; mi < 2; ++mi) {
        const int rbase = m0 + wr * 32 + mi * 16 + (lane >> 2);
#pragma unroll
        for (int ni = 0; ni < 8; ++ni) {
            const int cbase = n0 + wc * 64 + ni * 8 + (lane & 3) * 2;
            const float b0 = bias[cbase], b1 = bias[cbase + 1];
#pragma unroll
            for (int hr = 0; hr < 2; ++hr) {
                const int row = rbase + hr * 8;
                float v0 = acc[mi][ni][hr * 2 + 0] + b0;
                float v1 = acc[mi][ni][hr * 2 + 1] + b1;
                if (RES) {
                    v0 += res[(size_t)row * N + cbase];
                    v1 += res[(size_t)row * N + cbase + 1];
                }
                if (GELU) {
                    float u = v0;
                    v0 = 0.5f * u * (1.0f + tanhf(0.7978845608028654f * (u + 0.044715f * u * u * u)));
                    u = v1;
                    v1 = 0.5f * u * (1.0f + tanhf(0.7978845608028654f * (u + 0.044715f * u * u * u)));
                }
                const size_t idx = (size_t)row * N + cbase;
                if (WRITEF32) { C[idx] = v0; C[idx + 1] = v1; }
                if (SPLITOUT) {
                    __half h0 = __float2half(v0);
                    __half h1 = __float2half(v1);
                    Chi[idx] = h0; Chi[idx + 1] = h1;
                    if (LOOUT) {
                        Clo[idx]     = __float2half(v0 - __half2float(h0));
                        Clo[idx + 1] = __float2half(v1 - __half2float(h1));
                    }
                }
            }
        }
    }
}

// ---------------- LayerNorm (f32 + fp16-hi out) ----------------
__global__ __launch_bounds__(256) void ln_kernel(
    const float* __restrict__ in, const float* __restrict__ gamma,
    const float* __restrict__ beta, float* __restrict__ out,
    __half* __restrict__ ohi,
    const float* __restrict__ pos, const float* __restrict__ tok)
{
    const int r = blockIdx.x, s = r % S_, t = threadIdx.x;
    const float* row = in + (size_t)r * D_;
    float x[3];
#pragma unroll
    for (int j = 0; j < 3; ++j) {
        int i = t + j * 256;
        float v = row[i];
        if (pos) v += pos[(size_t)s * D_ + i] + tok[i];
        x[j] = v;
    }
    float sum = x[0] + x[1] + x[2];
    float sq  = x[0] * x[0] + x[1] * x[1] + x[2] * x[2];
    __shared__ float rs[8], rq[8];
#pragma unroll
    for (int o = 16; o > 0; o >>= 1) {
        sum += __shfl_xor_sync(0xffffffffu, sum, o);
        sq  += __shfl_xor_sync(0xffffffffu, sq, o);
    }
    if ((t & 31) == 0) { rs[t >> 5] = sum; rq[t >> 5] = sq; }
    __syncthreads();
    if (t < 32) {
        float s2 = (t < 8) ? rs[t] : 0.f;
        float q2 = (t < 8) ? rq[t] : 0.f;
#pragma unroll
        for (int o = 4; o > 0; o >>= 1) {
            s2 += __shfl_xor_sync(0xffffffffu, s2, o);
            q2 += __shfl_xor_sync(0xffffffffu, q2, o);
        }
        if (t == 0) { rs[0] = s2; rq[0] = q2; }
    }
    __syncthreads();
    const float mean = rs[0] * (1.0f / 768.0f);
    float var = rq[0] * (1.0f / 768.0f) - mean * mean;
    const float rstd = rsqrtf(fmaxf(var, 0.f) + 1e-12f);
#pragma unroll
    for (int j = 0; j < 3; ++j) {
        int i = t + j * 256;
        float y = (x[j] - mean) * rstd * gamma[i] + beta[i];
        size_t idx = (size_t)r * D_ + i;
        out[idx] = y;
        ohi[idx] = __float2half(y);
    }
}

// ---------------- tensor-core block-sparse flash attention (fp16x2) ----------------
// S = Qhi*(Khi+Klo); O += Phi*(Vhi+Vlo). 2 mma per fragment pair.
__global__ __launch_bounds__(128, 3) void attn_tc_kernel(
    const __half* __restrict__ qkvh, const __half* __restrict__ qkvl,
    const float* __restrict__ mask)
{
    extern __shared__ char smraw[];
    const uint32_t su = s2u(smraw);
    const uint32_t QH = su, KH = su + 18432, KL = su + 27648,
                   VH = su + 36864, VL = su + 46080;

    const int b = blockIdx.z, hh = blockIdx.y, ib = blockIdx.x;
    const int tid = threadIdx.x, warp = tid >> 5, lane = tid & 31;

    int qb, t0 = 0, e = 0, slice = 0;
    bool edge;
    if (ib < 62) { qb = ib + 1; edge = false; }
    else {
        edge = true;
        int xx = ib - 62;
        e = xx >> 3; slice = xx & 7;
        qb = e ? (NB_ - 1) : 0;
        t0 = slice * 8;
    }

    const int rrow = tid >> 1, half = tid & 1;
    {
        const size_t gq = (size_t)(b * S_ + qb * 64 + rrow) * NQKV + hh * 64 + half * 32;
        const uint4* s0 = (const uint4*)(qkvh + gq);
        uint4* d0 = (uint4*)(smraw + rrow * 144 + half * 64);
#pragma unroll
        for (int j = 0; j < 4; ++j) d0[j] = s0[j];
    }

    float Sf[8][4], Of[8][4];
#pragma unroll
    for (int f = 0; f < 8; ++f)
#pragma unroll
        for (int r = 0; r < 4; ++r) Of[f][r] = 0.f;
    float m0 = -1e30f, m1 = -1e30f, l0 = 0.f, l1 = 0.f;

    const uint32_t lr15 = (lane & 15);
    const uint32_t hb = (lane >> 4);

    for (int kt = 0; kt < 8; ++kt) {
        const int kb = edge ? (t0 + kt) : g_gi[qb * 8 + kt];
        __syncthreads();
        {
            const size_t gk = (size_t)(b * S_ + kb * 64 + rrow) * NQKV + hh * 64 + half * 32;
            const uint4* kh = (const uint4*)(qkvh + gk + 768);
            const uint4* kl = (const uint4*)(qkvl + gk + 768);
            const uint4* vh = (const uint4*)(qkvh + gk + 1536);
            const uint4* vl = (const uint4*)(qkvl + gk + 1536);
            const int off = rrow * 144 + half * 64;
            uint4* dkh = (uint4*)(smraw + 18432 + off);
            uint4* dkl = (uint4*)(smraw + 27648 + off);
            uint4* dvh = (uint4*)(smraw + 36864 + off);
            uint4* dvl = (uint4*)(smraw + 46080 + off);
#pragma unroll
            for (int j = 0; j < 4; ++j) { dkh[j] = kh[j]; dkl[j] = kl[j]; dvh[j] = vh[j]; dvl[j] = vl[j]; }
        }
        __syncthreads();

#pragma unroll
        for (int f = 0; f < 8; ++f)
#pragma unroll
            for (int r = 0; r < 4; ++r) Sf[f][r] = 0.f;
#pragma unroll
        for (int ks = 0; ks < 4; ++ks) {
            const uint32_t colb = ks * 32 + hb * 16;
            const uint32_t qoff = (warp * 16 + lr15) * 144 + colb;
            uint32_t qh[4];
            ldsm4a(qh, QH + qoff);
#pragma unroll
            for (int np = 0; np < 4; ++np) {
                const uint32_t koff = (np * 16 + lr15) * 144 + colb;
                uint32_t kh[4], kl[4];
                ldsm4a(kh, KH + koff);
                ldsm4a(kl, KL + koff);
#pragma unroll
                for (int j = 0; j < 2; ++j) {
                    mma16816(Sf[np * 2 + j], qh, kh[j], kh[j + 2]);
                    mma16816(Sf[np * 2 + j], qh, kl[j], kl[j + 2]);
                }
            }
        }

        const float* mrow = mask + (size_t)b * S_ + kb * 64;
        float t0m = -1e30f, t1m = -1e30f;
#pragma unroll
        for (int f = 0; f < 8; ++f) {
            const int c = f * 8 + 2 * (lane & 3);
            const float2 mk = *(const float2*)(mrow + c);
            Sf[f][0] = Sf[f][0] * 0.125f - 1e9f * (1.f - mk.x);
            Sf[f][1] = Sf[f][1] * 0.125f - 1e9f * (1.f - mk.y);
            Sf[f][2] = Sf[f][2] * 0.125f - 1e9f * (1.f - mk.x);
            Sf[f][3] = Sf[f][3] * 0.125f - 1e9f * (1.f - mk.y);
            t0m = fmaxf(t0m, fmaxf(Sf[f][0], Sf[f][1]));
            t1m = fmaxf(t1m, fmaxf(Sf[f][2], Sf[f][3]));
        }
        t0m = fmaxf(t0m, __shfl_xor_sync(0xffffffffu, t0m, 1));
        t0m = fmaxf(t0m, __shfl_xor_sync(0xffffffffu, t0m, 2));
        t1m = fmaxf(t1m, __shfl_xor_sync(0xffffffffu, t1m, 1));
        t1m = fmaxf(t1m, __shfl_xor_sync(0xffffffffu, t1m, 2));
        const float mn0 = fmaxf(m0, t0m), mn1 = fmaxf(m1, t1m);
        const float cr0 = __expf(m0 - mn0), cr1 = __expf(m1 - mn1);
        float ps0 = 0.f, ps1 = 0.f;
#pragma unroll
        for (int f = 0; f < 8; ++f) {
            Sf[f][0] = __expf(Sf[f][0] - mn0);
            Sf[f][1] = __expf(Sf[f][1] - mn0);
            Sf[f][2] = __expf(Sf[f][2] - mn1);
            Sf[f][3] = __expf(Sf[f][3] - mn1);
            ps0 += Sf[f][0] + Sf[f][1];
            ps1 += Sf[f][2] + Sf[f][3];
        }
        ps0 += __shfl_xor_sync(0xffffffffu, ps0, 1);
        ps0 += __shfl_xor_sync(0xffffffffu, ps0, 2);
        ps1 += __shfl_xor_sync(0xffffffffu, ps1, 1);
        ps1 += __shfl_xor_sync(0xffffffffu, ps1, 2);
        l0 = l0 * cr0 + ps0; m0 = mn0;
        l1 = l1 * cr1 + ps1; m1 = mn1;
#pragma unroll
        for (int f = 0; f < 8; ++f) {
            Of[f][0] *= cr0; Of[f][1] *= cr0; Of[f][2] *= cr1; Of[f][3] *= cr1;
        }

        uint32_t ph[4][4];
#pragma unroll
        for (int j2 = 0; j2 < 4; ++j2) {
            const float* A = Sf[2 * j2];
            const float* Bq = Sf[2 * j2 + 1];
            __half2 t;
            t.x = __float2half(A[0]);  t.y = __float2half(A[1]);  ph[j2][0] = *(uint32_t*)&t;
            t.x = __float2half(A[2]);  t.y = __float2half(A[3]);  ph[j2][1] = *(uint32_t*)&t;
            t.x = __float2half(Bq[0]); t.y = __float2half(Bq[1]); ph[j2][2] = *(uint32_t*)&t;
            t.x = __float2half(Bq[2]); t.y = __float2half(Bq[3]); ph[j2][3] = *(uint32_t*)&t;
        }

#pragma unroll
        for (int ks2 = 0; ks2 < 4; ++ks2) {
#pragma unroll
            for (int g = 0; g < 4; ++g) {
                const uint32_t voff = (ks2 * 16 + lr15) * 144 + (g * 16 + hb * 8) * 2;
                uint32_t vh[4], vl[4];
                ldsm4t(vh, VH + voff);
                ldsm4t(vl, VL + voff);
#pragma unroll
                for (int j = 0; j < 2; ++j) {
                    mma16816(Of[g * 2 + j], ph[ks2], vh[2 * j], vh[2 * j + 1]);
                    mma16816(Of[g * 2 + j], ph[ks2], vl[2 * j], vl[2 * j + 1]);
                }
            }
        }
    }

    const int r0 = warp * 16 + (lane >> 2);
    if (!edge) {
        const float inv0 = 1.f / l0, inv1 = 1.f / l1;
        const size_t tk0 = (size_t)(b * S_ + qb * 64 + r0) * D_ + hh * 64;
        const size_t tk1 = tk0 + 8 * D_;
#pragma unroll
        for (int f = 0; f < 8; ++f) {
            const int c = f * 8 + 2 * (lane & 3);
            __half2 h01, h23;
            h01.x = __float2half(Of[f][0] * inv0);
            h01.y = __float2half(Of[f][1] * inv0);
            h23.x = __float2half(Of[f][2] * inv1);
            h23.y = __float2half(Of[f][3] * inv1);
            *(__half2*)(g_chi + tk0 + c) = h01;
            *(__half2*)(g_chi + tk1 + c) = h23;
        }
    } else {
        float* base = g_part + ((size_t)((((b * H_ + hh) * 2 + e) * 8 + slice) * 64)) * 66;
        float* pp0 = base + (size_t)r0 * 66;
        float* pp1 = base + (size_t)(r0 + 8) * 66;
#pragma unroll
        for (int f = 0; f < 8; ++f) {
            const int c = f * 8 + 2 * (lane & 3);
            pp0[c] = Of[f][0]; pp0[c + 1] = Of[f][1];
            pp1[c] = Of[f][2]; pp1[c + 1] = Of[f][3];
        }
        if ((lane & 3) == 0) {
            pp0[64] = m0; pp0[65] = l0;
            pp1[64] = m1; pp1[65] = l1;
        }
    }
}

__global__ __launch_bounds__(256) void merge_kernel() {
    const int e = blockIdx.x, hh = blockIdx.y, b = blockIdx.z;
    const int tid = threadIdx.x;
    const int r = tid >> 2, t4 = tid & 3;
    const size_t base = ((size_t)(((b * H_ + hh) * 2 + e) * 8)) * 64 * 66;

    float M = -1e30f;
#pragma unroll
    for (int s = 0; s < 8; ++s) M = fmaxf(M, g_part[base + ((size_t)s * 64 + r) * 66 + 64]);
    float L = 0.f, acc[16];
#pragma unroll
    for (int i = 0; i < 16; ++i) acc[i] = 0.f;
#pragma unroll
    for (int s = 0; s < 8; ++s) {
        const float* pp = g_part + base + ((size_t)s * 64 + r) * 66;
        const float w = __expf(pp[64] - M);
        L += pp[65] * w;
#pragma unroll
        for (int i = 0; i < 16; ++i) acc[i] += pp[t4 * 16 + i] * w;
    }
    const float inv = 1.0f / L;
    const int qb = e ? (NB_ - 1) : 0;
    const size_t idx = ((size_t)(b * S_ + qb * 64 + r)) * D_ + hh * 64 + t4 * 16;
#pragma unroll
    for (int i = 0; i < 16; ++i)
        g_chi[idx + i] = __float2half(acc[i] * inv);
}

// ---------------- classifier ----------------
__global__ void cls1_kernel(const float* __restrict__ h, const float* __restrict__ w,
                            const float* __restrict__ bias, float* __restrict__ out) {
    int gid = blockIdx.x * blockDim.x + threadIdx.x;
    if (gid >= 2 * 512) return;
    int b = gid >> 9, n = gid & 511;
    const float* hrow = h + (size_t)b * S_ * D_;
    float s = 0.f;
    for (int k2 = 0; k2 < D_; ++k2) s += hrow[k2] * w[(size_t)k2 * 512 + n];
    out[gid] = fmaxf(s + bias[n], 0.f);
}
__global__ void cls2_kernel(const float* __restrict__ rin, const float* __restrict__ w,
                            const float* __restrict__ bias, float* __restrict__ out) {
    int gid = blockIdx.x * blockDim.x + threadIdx.x;
    if (gid >= 2 * TGT_) return;
    int b = gid >> 10, n = gid & 1023;
    float s = 0.f;
    for (int k2 = 0; k2 < 512; ++k2) s += rin[b * 512 + k2] * w[(size_t)k2 * TGT_ + n];
    out[gid] = s + bias[n];
}

// ---------------- host ----------------
typedef CUresult (*EncFn)(CUtensorMap*, CUtensorMapDataType, cuuint32_t, void*,
                          const cuuint64_t*, const cuuint64_t*, const cuuint32_t*, const cuuint32_t*,
                          CUtensorMapInterleave, CUtensorMapSwizzle, CUtensorMapL2promotion,
                          CUtensorMapFloatOOBfill);

extern "C" void kernel_launch(void* const* d_in, const int* in_sizes, int n_in,
                              void* d_out, int out_size)
{
    const float* x        = (const float*)d_in[0];
    const float* mask     = (const float*)d_in[1];
    const float* proj_b   = (const float*)d_in[3];
    const float* pos_emb  = (const float*)d_in[4];
    const float* tok_emb  = (const float*)d_in[5];
    const float* emb_g    = (const float*)d_in[6];
    const float* emb_b    = (const float*)d_in[7];
    const float* bq_all   = (const float*)d_in[9];
    const float* bk_all   = (const float*)d_in[11];
    const float* bv_all   = (const float*)d_in[13];
    const float* bo_all   = (const float*)d_in[15];
    const float* ln1g_all = (const float*)d_in[16];
    const float* ln1b_all = (const float*)d_in[17];
    const float* bi_all   = (const float*)d_in[19];
    const float* bo2_all  = (const float*)d_in[21];
    const float* ln2g_all = (const float*)d_in[22];
    const float* ln2b_all = (const float*)d_in[23];
    const float* cls_w1   = (const float*)d_in[24];
    const float* cls_b1   = (const float*)d_in[25];
    const float* cls_w2   = (const float*)d_in[26];
    const float* cls_b2   = (const float*)d_in[27];
    const int*   rb       = (const int*)d_in[28];
    float* out = (float*)d_out;

    float *ph, *ptmp, *pcls, *pbqkv;
    __half *pwhi, *pwlo, *pxhi, *pxlo, *phhi, *pchi, *pfhi, *pqvh, *pqvl;
    cudaGetSymbolAddress((void**)&ph,   g_h);
    cudaGetSymbolAddress((void**)&ptmp, g_tmp);
    cudaGetSymbolAddress((void**)&pcls, g_cls);
    cudaGetSymbolAddress((void**)&pbqkv, g_bqkv);
    cudaGetSymbolAddress((void**)&pwhi, g_whi);
    cudaGetSymbolAddress((void**)&pwlo, g_wlo);
    cudaGetSymbolAddress((void**)&pxhi, g_xhi);
    cudaGetSymbolAddress((void**)&pxlo, g_xlo);
    cudaGetSymbolAddress((void**)&phhi, g_hhi);
    cudaGetSymbolAddress((void**)&pchi, g_chi);
    cudaGetSymbolAddress((void**)&pfhi, g_fhi);
    cudaGetSymbolAddress((void**)&pqvh, g_qkvhi);
    cudaGetSymbolAddress((void**)&pqvl, g_qkvlo);

    EncFn enc = nullptr;
    cudaDriverEntryPointQueryResult qr;
    cudaGetDriverEntryPointByVersion("cuTensorMapEncodeTiled", (void**)&enc, 12000,
                                     cudaEnableDefault, &qr);

    auto mk2 = [&](CUtensorMap* m, void* p, uint64_t K) {
        cuuint64_t d[2] = {K, T_};
        cuuint64_t st[1] = {K * 2};
        cuuint32_t bx[2] = {64, 128}, es[2] = {1, 1};
        enc(m, CU_TENSOR_MAP_DATA_TYPE_FLOAT16, 2, p, d, st, bx, es,
            CU_TENSOR_MAP_INTERLEAVE_NONE, CU_TENSOR_MAP_SWIZZLE_128B,
            CU_TENSOR_MAP_L2_PROMOTION_L2_128B, CU_TENSOR_MAP_FLOAT_OOB_FILL_NONE);
    };
    auto mk3 = [&](CUtensorMap* m, void* p, uint64_t K, uint64_t N, uint64_t Lz) {
        cuuint64_t d[3] = {K, N, Lz};
        cuuint64_t st[2] = {K * 2, N * K * 2};
        cuuint32_t bx[3] = {64, 128, 1}, es[3] = {1, 1, 1};
        enc(m, CU_TENSOR_MAP_DATA_TYPE_FLOAT16, 3, p, d, st, bx, es,
            CU_TENSOR_MAP_INTERLEAVE_NONE, CU_TENSOR_MAP_SWIZZLE_128B,
            CU_TENSOR_MAP_L2_PROMOTION_L2_128B, CU_TENSOR_MAP_FLOAT_OOB_FILL_NONE);
    };

    CUtensorMap mxh, mxl, mhh, mch, mfh;
    CUtensorMap mpjh, mpjl, mqkvh, mqkvl, moh, mol, mih, mil, m2h, m2l;
    mk2(&mxh, pxhi, IN_); mk2(&mxl, pxlo, IN_);
    mk2(&mhh, phhi, D_);
    mk2(&mch, pchi, D_);
    mk2(&mfh, pfhi, FF_);
    mk3(&mpjh, pwhi + OFF_PROJ, IN_, D_, 1);   mk3(&mpjl, pwlo + OFF_PROJ, IN_, D_, 1);
    mk3(&mqkvh, pwhi + OFF_QKV, D_, NQKV, L_); mk3(&mqkvl, pwlo + OFF_QKV, D_, NQKV, L_);
    mk3(&moh, pwhi + OFF_WO, D_, D_, L_);      mk3(&mol, pwlo + OFF_WO, D_, D_, L_);
    mk3(&mih, pwhi + OFF_WI, D_, FF_, L_);     mk3(&mil, pwlo + OFF_WI, D_, FF_, L_);
    mk3(&m2h, pwhi + OFF_WO2, FF_, D_, L_);    mk3(&m2l, pwlo + OFF_WO2, FF_, D_, L_);

    cudaFuncSetAttribute(tgemm_kernel<false, false, false, true, true, true, false>,
                         cudaFuncAttributeMaxDynamicSharedMemorySize, GEMM_SMEM);
    cudaFuncSetAttribute(tgemm_kernel<false, false, true, false, false, false, true>,
                         cudaFuncAttributeMaxDynamicSharedMemorySize, GEMM_SMEM);
    cudaFuncSetAttribute(tgemm_kernel<false, true, false, true, false, false, false>,
                         cudaFuncAttributeMaxDynamicSharedMemorySize, GEMM_SMEM);
    cudaFuncSetAttribute(tgemm_kernel<true, false, true, false, false, true, false>,
                         cudaFuncAttributeMaxDynamicSharedMemorySize, GEMM_SMEM);
    cudaFuncSetAttribute(attn_tc_kernel,
                         cudaFuncAttributeMaxDynamicSharedMemorySize, ATTN_SMEM);

    // prep
    dim3 tb(32, 8);
    tsplit_kernel<<<dim3(D_ / 32, IN_ / 32, 1), tb>>>((const float*)d_in[2], pwhi + OFF_PROJ, pwlo + OFF_PROJ, IN_, D_, IN_ * D_);
    tsplit_kernel<<<dim3(D_ / 32, D_ / 32, L_), tb>>>((const float*)d_in[8],  pwhi + OFF_QKV,               pwlo + OFF_QKV,               D_, D_, NQKV * D_);
    tsplit_kernel<<<dim3(D_ / 32, D_ / 32, L_), tb>>>((const float*)d_in[10], pwhi + OFF_QKV + 768 * 768,   pwlo + OFF_QKV + 768 * 768,   D_, D_, NQKV * D_);
    tsplit_kernel<<<dim3(D_ / 32, D_ / 32, L_), tb>>>((const float*)d_in[12], pwhi + OFF_QKV + 2 * 768 * 768, pwlo + OFF_QKV + 2 * 768 * 768, D_, D_, NQKV * D_);
    tsplit_kernel<<<dim3(D_ / 32, D_ / 32, L_), tb>>>((const float*)d_in[14], pwhi + OFF_WO, pwlo + OFF_WO, D_, D_, D_ * D_);
    tsplit_kernel<<<dim3(FF_ / 32, D_ / 32, L_), tb>>>((const float*)d_in[18], pwhi + OFF_WI, pwlo + OFF_WI, D_, FF_, D_ * FF_);
    tsplit_kernel<<<dim3(D_ / 32, FF_ / 32, L_), tb>>>((const float*)d_in[20], pwhi + OFF_WO2, pwlo + OFF_WO2, FF_, D_, FF_ * D_);
    split_kernel<<<(T_ * IN_ + 255) / 256, 256>>>(x, pxhi, pxlo, T_ * IN_);
    build_gi_kernel<<<1, 64>>>(rb);
    bcat_kernel<<<(L_ * NQKV + 255) / 256, 256>>>(bq_all, bk_all, bv_all);

    const dim3 gD(D_ / 128, T_ / 128);
    const dim3 gQKV(NQKV / 128, T_ / 128);
    const dim3 gF(FF_ / 128, T_ / 128);
    const dim3 gA(78, H_, B_);
    const dim3 gM(2, H_, B_);

    // embedding proj: 3-plane fp16
    tgemm_kernel<false, false, false, true, true, true, false><<<gD, 256, GEMM_SMEM>>>(
        mxh, mxl, mpjh, mpjl, proj_b, nullptr, ptmp, nullptr, nullptr, D_, IN_, 0);
    ln_kernel<<<T_, 256>>>(ptmp, emb_g, emb_b, ph, phhi, pos_emb, tok_emb);

    for (int l = 0; l < L_; ++l) {
        // QKV: 1-plane fp16, hi+lo split output for attention K/V lo planes
        tgemm_kernel<false, false, true, false, false, false, true><<<gQKV, 256, GEMM_SMEM>>>(
            mhh, mhh, mqkvh, mqkvl, pbqkv + (size_t)l * NQKV, nullptr,
            nullptr, pqvh, pqvl, NQKV, D_, l);

        attn_tc_kernel<<<gA, 128, ATTN_SMEM>>>(pqvh, pqvl, mask);
        merge_kernel<<<gM, 256>>>();

        // wo: 1-plane fp16, residual, f32 out
        tgemm_kernel<false, true, false, true, false, false, false><<<gD, 256, GEMM_SMEM>>>(
            mch, mch, moh, mol, bo_all + (size_t)l * D_, ph, ptmp, nullptr, nullptr, D_, D_, l);
        ln_kernel<<<T_, 256>>>(ptmp, ln1g_all + (size_t)l * D_, ln1b_all + (size_t)l * D_,
                               ph, phhi, nullptr, nullptr);

        // wi: 2-plane fp16 (keeps weight-lo; measured-toxic class), GELU, hi-only out
        tgemm_kernel<true, false, true, false, false, true, false><<<gF, 256, GEMM_SMEM>>>(
            mhh, mhh, mih, mil, bi_all + (size_t)l * FF_, nullptr, nullptr, pfhi, nullptr, FF_, D_, l);
        // wo2: 1-plane fp16, residual, f32 out
        tgemm_kernel<false, true, false, true, false, false, false><<<gD, 256, GEMM_SMEM>>>(
            mfh, mfh, m2h, m2l, bo2_all + (size_t)l * D_, ph, ptmp, nullptr, nullptr, D_, FF_, l);
        ln_kernel<<<T_, 256>>>(ptmp, ln2g_all + (size_t)l * D_, ln2b_all + (size_t)l * D_,
                               ph, phhi, nullptr, nullptr);
    }

    cls1_kernel<<<4, 256>>>(ph, cls_w1, cls_b1, pcls);
    cls2_kernel<<<8, 256>>>(pcls, cls_w2, cls_b2, out);
}

// round 16
// speedup vs baseline: 2.3107x; 1.2951x over previous
#include <cuda_runtime.h>
#include <cuda.h>
#include <cuda_fp16.h>
#include <math.h>
#include <stdint.h>

#define B_    2
#define S_    4096
#define T_    8192
#define IN_   1280
#define D_    768
#define H_    12
#define FF_   3072
#define L_    12
#define TGT_  1024
#define NB_   64
#define NQKV  2304

#define OFF_PROJ 0
#define OFF_QKV  (IN_*D_)
#define OFF_WO   (OFF_QKV + L_*NQKV*D_)
#define OFF_WI   (OFF_WO + L_*D_*D_)
#define OFF_WO2  (OFF_WI + L_*D_*FF_)
#define WTOT     (OFF_WO2 + L_*FF_*D_)

#define GEMM_SMEM (1024 + 3*65536)
#define ATTN_SMEM 27648

// ---------------- scratch ----------------
__device__ float g_h[T_ * D_];
__device__ float g_tmp[T_ * D_];
__device__ float g_cls[2 * 512];
__device__ float g_bqkv[L_ * NQKV];
__device__ int   g_gi[NB_ * 8];

__device__ __align__(128) __half g_whi[WTOT];
__device__ __align__(128) __half g_wlo[WTOT];
__device__ __align__(128) __half g_xhi[T_ * IN_];
__device__ __align__(128) __half g_xlo[T_ * IN_];
__device__ __align__(128) __half g_hhi[T_ * D_];
__device__ __align__(128) __half g_chi[T_ * D_];
__device__ __align__(128) __half g_fhi[T_ * FF_];
__device__ __align__(128) __half g_qkvhi[T_ * NQKV];
__device__ float g_part[B_ * H_ * 2 * 8 * 64 * 66];

// ---------------- PTX helpers ----------------
__device__ __forceinline__ uint32_t s2u(const void* p) { return (uint32_t)__cvta_generic_to_shared(p); }
__device__ __forceinline__ void mbar_init(uint32_t a, uint32_t c) {
    asm volatile("mbarrier.init.shared.b64 [%0], %1;" :: "r"(a), "r"(c) : "memory");
}
__device__ __forceinline__ void mbar_expect(uint32_t a, uint32_t b) {
    asm volatile("mbarrier.arrive.expect_tx.shared.b64 _, [%0], %1;" :: "r"(a), "r"(b) : "memory");
}
__device__ __forceinline__ void mbar_wait(uint32_t a, uint32_t par) {
    asm volatile("{\n\t.reg .pred P;\n\tW_%=:\n\t"
                 "mbarrier.try_wait.parity.acquire.cta.shared::cta.b64 P, [%0], %1, 0x989680;\n\t"
                 "@P bra.uni D_%=;\n\tbra.uni W_%=;\n\tD_%=:\n\t}" :: "r"(a), "r"(par) : "memory");
}
__device__ __forceinline__ void tma2d(uint32_t dst, const void* tm, int x, int y, uint32_t mb) {
    asm volatile("cp.async.bulk.tensor.2d.shared::cta.global.tile.mbarrier::complete_tx::bytes "
                 "[%0], [%1, {%2, %3}], [%4];" :: "r"(dst), "l"(tm), "r"(x), "r"(y), "r"(mb) : "memory");
}
__device__ __forceinline__ void tma3d(uint32_t dst, const void* tm, int x, int y, int z, uint32_t mb) {
    asm volatile("cp.async.bulk.tensor.3d.shared::cta.global.tile.mbarrier::complete_tx::bytes "
                 "[%0], [%1, {%2, %3, %4}], [%5];" :: "r"(dst), "l"(tm), "r"(x), "r"(y), "r"(z), "r"(mb) : "memory");
}
__device__ __forceinline__ void ldsm4a(uint32_t* r, uint32_t a) {
    asm volatile("ldmatrix.sync.aligned.m8n8.x4.shared.b16 {%0,%1,%2,%3}, [%4];"
                 : "=r"(r[0]), "=r"(r[1]), "=r"(r[2]), "=r"(r[3]) : "r"(a));
}
__device__ __forceinline__ void ldsm4t(uint32_t* r, uint32_t a) {
    asm volatile("ldmatrix.sync.aligned.m8n8.x4.trans.shared.b16 {%0,%1,%2,%3}, [%4];"
                 : "=r"(r[0]), "=r"(r[1]), "=r"(r[2]), "=r"(r[3]) : "r"(a));
}
__device__ __forceinline__ void mma16816(float* d, const uint32_t* a, uint32_t b0, uint32_t b1) {
    asm volatile("mma.sync.aligned.m16n8k16.row.col.f32.f16.f16.f32 "
                 "{%0,%1,%2,%3}, {%4,%5,%6,%7}, {%8,%9}, {%0,%1,%2,%3};"
                 : "+f"(d[0]), "+f"(d[1]), "+f"(d[2]), "+f"(d[3])
                 : "r"(a[0]), "r"(a[1]), "r"(a[2]), "r"(a[3]), "r"(b0), "r"(b1));
}

// ---------------- prep kernels ----------------
__global__ void split_kernel(const float* __restrict__ s, __half* __restrict__ hi,
                             __half* __restrict__ lo, int n) {
    int i = blockIdx.x * blockDim.x + threadIdx.x;
    if (i >= n) return;
    float v = s[i];
    __half h = __float2half(v);
    hi[i] = h;
    lo[i] = __float2half(v - __half2float(h));
}

__global__ void tsplit_kernel(const float* __restrict__ src, __half* __restrict__ hi,
                              __half* __restrict__ lo, int K, int N, int lstride) {
    __shared__ float t[32][33];
    const int l = blockIdx.z;
    const int n0 = blockIdx.x * 32, k0 = blockIdx.y * 32;
    const float* S = src + (size_t)l * K * N;
    const int tx = threadIdx.x, ty = threadIdx.y;
#pragma unroll
    for (int j = 0; j < 4; ++j)
        t[ty + j * 8][tx] = S[(size_t)(k0 + ty + j * 8) * N + n0 + tx];
    __syncthreads();
    __half* Ht = hi + (size_t)l * lstride;
    __half* Lt = lo + (size_t)l * lstride;
#pragma unroll
    for (int j = 0; j < 4; ++j) {
        int n = n0 + ty + j * 8;
        float v = t[tx][ty + j * 8];
        __half h = __float2half(v);
        Ht[(size_t)n * K + k0 + tx] = h;
        Lt[(size_t)n * K + k0 + tx] = __float2half(v - __half2float(h));
    }
}

__global__ void build_gi_kernel(const int* __restrict__ rb) {
    int n = threadIdx.x;
    if (n < 1 || n >= NB_ - 1) return;
    int* p = g_gi + n * 8;
    p[0] = 0; p[1] = n - 1; p[2] = n; p[3] = n + 1; p[4] = NB_ - 1;
    p[5] = rb[n * 3 + 0]; p[6] = rb[n * 3 + 1]; p[7] = rb[n * 3 + 2];
}

__global__ void bcat_kernel(const float* __restrict__ bq, const float* __restrict__ bk,
                            const float* __restrict__ bv) {
    int i = blockIdx.x * blockDim.x + threadIdx.x;
    if (i >= L_ * NQKV) return;
    int l = i / NQKV, n = i % NQKV;
    float v = (n < 768) ? bq[l * 768 + n] : (n < 1536) ? bk[l * 768 + n - 768] : bv[l * 768 + n - 1536];
    g_bqkv[i] = v;
}

// ---------------- TMA + mma.sync fp16 GEMM (1/2/3-plane), 3-stage pipeline ----------------
template<bool GELU, bool RES, bool SPLITOUT, bool WRITEF32, bool ALO, bool BLO>
__global__ __launch_bounds__(256, 1) void tgemm_kernel(
    const __grid_constant__ CUtensorMap tAh, const __grid_constant__ CUtensorMap tAl,
    const __grid_constant__ CUtensorMap tBh, const __grid_constant__ CUtensorMap tBl,
    const float* __restrict__ bias, const float* __restrict__ res,
    float* __restrict__ C, __half* __restrict__ Chi,
    int N, int K, int layer)
{
    extern __shared__ char dsm[];
    const uint32_t ctl = s2u(dsm);
    const uint32_t tiles = (ctl + 64 + 1023) & ~1023u;
    const int tid = threadIdx.x;
    const int warp = tid >> 5, lane = tid & 31;
    const int wr = warp >> 1, wc = warp & 1;
    const int m0 = blockIdx.y * 128, n0 = blockIdx.x * 128;
    const int nch = K >> 6;

    if (tid == 0) {
        mbar_init(ctl, 1);
        mbar_init(ctl + 8, 1);
        mbar_init(ctl + 16, 1);
        asm volatile("fence.proxy.async.shared::cta;" ::: "memory");
    }
    __syncthreads();

    auto issue = [&](int i) {
        const int st = i % 3;
        const uint32_t mb = ctl + st * 8;
        const uint32_t tb = tiles + st * 65536;
        mbar_expect(mb, 16384u * (2 + (ALO ? 1 : 0) + (BLO ? 1 : 0)));
        const int k0 = i << 6;
        tma2d(tb +     0, &tAh, k0, m0, mb);
        if (ALO) tma2d(tb + 16384, &tAl, k0, m0, mb);
        tma3d(tb + 32768, &tBh, k0, n0, layer, mb);
        if (BLO) tma3d(tb + 49152, &tBl, k0, n0, layer, mb);
    };
    const bool prod = (tid == 0);
    if (prod) {
        issue(0);
        if (nch > 1) issue(1);
        if (nch > 2) issue(2);
    }

    float acc[2][8][4];
#pragma unroll
    for (int mi = 0; mi < 2; ++mi)
#pragma unroll
        for (int ni = 0; ni < 8; ++ni)
#pragma unroll
            for (int r = 0; r < 4; ++r) acc[mi][ni][r] = 0.f;

    const int lrow = lane & 15;
    const uint32_t hb16 = (lane >> 4) * 16;
    uint32_t arow[2], axr[2], brow[4], bxr[4];
#pragma unroll
    for (int mi = 0; mi < 2; ++mi) {
        int r = wr * 32 + mi * 16 + lrow;
        arow[mi] = r * 128; axr[mi] = (r & 7) * 16;
    }
#pragma unroll
    for (int np = 0; np < 4; ++np) {
        int r = wc * 64 + np * 16 + lrow;
        brow[np] = r * 128; bxr[np] = (r & 7) * 16;
    }

    for (int i = 0; i < nch; ++i) {
        const int st = i % 3;
        mbar_wait(ctl + st * 8, (i / 3) & 1);
        const uint32_t bAh = tiles + st * 65536;
        const uint32_t bAl = bAh + 16384;
        const uint32_t bBh = bAh + 32768;
        const uint32_t bBl = bAh + 49152;
#pragma unroll
        for (int ks = 0; ks < 4; ++ks) {
            const uint32_t colb = ks * 32 + hb16;
            uint32_t ah[2][4], al[2][4];
#pragma unroll
            for (int mi = 0; mi < 2; ++mi) {
                ldsm4a(ah[mi], bAh + arow[mi] + (colb ^ axr[mi]));
                if (ALO) ldsm4a(al[mi], bAl + arow[mi] + (colb ^ axr[mi]));
            }
#pragma unroll
            for (int np = 0; np < 4; ++np) {
                uint32_t bh[4], bl[4];
                ldsm4a(bh, bBh + brow[np] + (colb ^ bxr[np]));
                if (BLO) ldsm4a(bl, bBl + brow[np] + (colb ^ bxr[np]));
#pragma unroll
                for (int j = 0; j < 2; ++j) {
                    const int ni = np * 2 + j;
#pragma unroll
                    for (int mi = 0; mi < 2; ++mi) {
                        mma16816(acc[mi][ni], ah[mi], bh[j], bh[j + 2]);
                        if (BLO) mma16816(acc[mi][ni], ah[mi], bl[j], bl[j + 2]);
                        if (ALO) mma16816(acc[mi][ni], al[mi], bh[j], bh[j + 2]);
                    }
                }
            }
        }
        __syncthreads();
        if (prod && i + 3 < nch) issue(i + 3);
    }

#pragma unroll
    for (int mi = 0; mi < 2; ++mi) {
        const int rbase = m0 + wr * 32 + mi * 16 + (lane >> 2);
#pragma unroll
        for (int ni = 0; ni < 8; ++ni) {
            const int cbase = n0 + wc * 64 + ni * 8 + (lane & 3) * 2;
            const float b0 = bias[cbase], b1 = bias[cbase + 1];
#pragma unroll
            for (int hr = 0; hr < 2; ++hr) {
                const int row = rbase + hr * 8;
                float v0 = acc[mi][ni][hr * 2 + 0] + b0;
                float v1 = acc[mi][ni][hr * 2 + 1] + b1;
                if (RES) {
                    v0 += res[(size_t)row * N + cbase];
                    v1 += res[(size_t)row * N + cbase + 1];
                }
                if (GELU) {
                    float u = v0;
                    v0 = 0.5f * u * (1.0f + tanhf(0.7978845608028654f * (u + 0.044715f * u * u * u)));
                    u = v1;
                    v1 = 0.5f * u * (1.0f + tanhf(0.7978845608028654f * (u + 0.044715f * u * u * u)));
                }
                const size_t idx = (size_t)row * N + cbase;
                if (WRITEF32) { C[idx] = v0; C[idx + 1] = v1; }
                if (SPLITOUT) {
                    Chi[idx]     = __float2half(v0);
                    Chi[idx + 1] = __float2half(v1);
                }
            }
        }
    }
}

// ---------------- LayerNorm (f32 + fp16-hi out) ----------------
__global__ __launch_bounds__(256) void ln_kernel(
    const float* __restrict__ in, const float* __restrict__ gamma,
    const float* __restrict__ beta, float* __restrict__ out,
    __half* __restrict__ ohi,
    const float* __restrict__ pos, const float* __restrict__ tok)
{
    const int r = blockIdx.x, s = r % S_, t = threadIdx.x;
    const float* row = in + (size_t)r * D_;
    float x[3];
#pragma unroll
    for (int j = 0; j < 3; ++j) {
        int i = t + j * 256;
        float v = row[i];
        if (pos) v += pos[(size_t)s * D_ + i] + tok[i];
        x[j] = v;
    }
    float sum = x[0] + x[1] + x[2];
    float sq  = x[0] * x[0] + x[1] * x[1] + x[2] * x[2];
    __shared__ float rs[8], rq[8];
#pragma unroll
    for (int o = 16; o > 0; o >>= 1) {
        sum += __shfl_xor_sync(0xffffffffu, sum, o);
        sq  += __shfl_xor_sync(0xffffffffu, sq, o);
    }
    if ((t & 31) == 0) { rs[t >> 5] = sum; rq[t >> 5] = sq; }
    __syncthreads();
    if (t < 32) {
        float s2 = (t < 8) ? rs[t] : 0.f;
        float q2 = (t < 8) ? rq[t] : 0.f;
#pragma unroll
        for (int o = 4; o > 0; o >>= 1) {
            s2 += __shfl_xor_sync(0xffffffffu, s2, o);
            q2 += __shfl_xor_sync(0xffffffffu, q2, o);
        }
        if (t == 0) { rs[0] = s2; rq[0] = q2; }
    }
    __syncthreads();
    const float mean = rs[0] * (1.0f / 768.0f);
    float var = rq[0] * (1.0f / 768.0f) - mean * mean;
    const float rstd = rsqrtf(fmaxf(var, 0.f) + 1e-12f);
#pragma unroll
    for (int j = 0; j < 3; ++j) {
        int i = t + j * 256;
        float y = (x[j] - mean) * rstd * gamma[i] + beta[i];
        size_t idx = (size_t)r * D_ + i;
        out[idx] = y;
        ohi[idx] = __float2half(y);
    }
}

// ---------------- tensor-core block-sparse flash attention (fp16x1) ----------------
// S = Qhi*Khi; O += Phi*Vhi. ctx already fp16-truncated at wo input, so dropped
// lo-planes are same error class as existing truncation.
__global__ __launch_bounds__(128, 3) void attn_tc_kernel(
    const __half* __restrict__ qkvh, const float* __restrict__ mask)
{
    extern __shared__ char smraw[];
    const uint32_t su = s2u(smraw);
    const uint32_t QH = su, KH = su + 9216, VH = su + 18432;

    const int b = blockIdx.z, hh = blockIdx.y, ib = blockIdx.x;
    const int tid = threadIdx.x, warp = tid >> 5, lane = tid & 31;

    int qb, t0 = 0, e = 0, slice = 0;
    bool edge;
    if (ib < 62) { qb = ib + 1; edge = false; }
    else {
        edge = true;
        int xx = ib - 62;
        e = xx >> 3; slice = xx & 7;
        qb = e ? (NB_ - 1) : 0;
        t0 = slice * 8;
    }

    const int rrow = tid >> 1, half = tid & 1;
    {
        const size_t gq = (size_t)(b * S_ + qb * 64 + rrow) * NQKV + hh * 64 + half * 32;
        const uint4* s0 = (const uint4*)(qkvh + gq);
        uint4* d0 = (uint4*)(smraw + rrow * 144 + half * 64);
#pragma unroll
        for (int j = 0; j < 4; ++j) d0[j] = s0[j];
    }

    float Sf[8][4], Of[8][4];
#pragma unroll
    for (int f = 0; f < 8; ++f)
#pragma unroll
        for (int r = 0; r < 4; ++r) Of[f][r] = 0.f;
    float m0 = -1e30f, m1 = -1e30f, l0 = 0.f, l1 = 0.f;

    const uint32_t lr15 = (lane & 15);
    const uint32_t hb = (lane >> 4);

    for (int kt = 0; kt < 8; ++kt) {
        const int kb = edge ? (t0 + kt) : g_gi[qb * 8 + kt];
        __syncthreads();
        {
            const size_t gk = (size_t)(b * S_ + kb * 64 + rrow) * NQKV + hh * 64 + half * 32;
            const uint4* kh = (const uint4*)(qkvh + gk + 768);
            const uint4* vh = (const uint4*)(qkvh + gk + 1536);
            const int off = rrow * 144 + half * 64;
            uint4* dkh = (uint4*)(smraw + 9216 + off);
            uint4* dvh = (uint4*)(smraw + 18432 + off);
#pragma unroll
            for (int j = 0; j < 4; ++j) { dkh[j] = kh[j]; dvh[j] = vh[j]; }
        }
        __syncthreads();

#pragma unroll
        for (int f = 0; f < 8; ++f)
#pragma unroll
            for (int r = 0; r < 4; ++r) Sf[f][r] = 0.f;
#pragma unroll
        for (int ks = 0; ks < 4; ++ks) {
            const uint32_t colb = ks * 32 + hb * 16;
            const uint32_t qoff = (warp * 16 + lr15) * 144 + colb;
            uint32_t qh[4];
            ldsm4a(qh, QH + qoff);
#pragma unroll
            for (int np = 0; np < 4; ++np) {
                const uint32_t koff = (np * 16 + lr15) * 144 + colb;
                uint32_t kh[4];
                ldsm4a(kh, KH + koff);
#pragma unroll
                for (int j = 0; j < 2; ++j)
                    mma16816(Sf[np * 2 + j], qh, kh[j], kh[j + 2]);
            }
        }

        const float* mrow = mask + (size_t)b * S_ + kb * 64;
        float t0m = -1e30f, t1m = -1e30f;
#pragma unroll
        for (int f = 0; f < 8; ++f) {
            const int c = f * 8 + 2 * (lane & 3);
            const float2 mk = *(const float2*)(mrow + c);
            Sf[f][0] = Sf[f][0] * 0.125f - 1e9f * (1.f - mk.x);
            Sf[f][1] = Sf[f][1] * 0.125f - 1e9f * (1.f - mk.y);
            Sf[f][2] = Sf[f][2] * 0.125f - 1e9f * (1.f - mk.x);
            Sf[f][3] = Sf[f][3] * 0.125f - 1e9f * (1.f - mk.y);
            t0m = fmaxf(t0m, fmaxf(Sf[f][0], Sf[f][1]));
            t1m = fmaxf(t1m, fmaxf(Sf[f][2], Sf[f][3]));
        }
        t0m = fmaxf(t0m, __shfl_xor_sync(0xffffffffu, t0m, 1));
        t0m = fmaxf(t0m, __shfl_xor_sync(0xffffffffu, t0m, 2));
        t1m = fmaxf(t1m, __shfl_xor_sync(0xffffffffu, t1m, 1));
        t1m = fmaxf(t1m, __shfl_xor_sync(0xffffffffu, t1m, 2));
        const float mn0 = fmaxf(m0, t0m), mn1 = fmaxf(m1, t1m);
        const float cr0 = __expf(m0 - mn0), cr1 = __expf(m1 - mn1);
        float ps0 = 0.f, ps1 = 0.f;
#pragma unroll
        for (int f = 0; f < 8; ++f) {
            Sf[f][0] = __expf(Sf[f][0] - mn0);
            Sf[f][1] = __expf(Sf[f][1] - mn0);
            Sf[f][2] = __expf(Sf[f][2] - mn1);
            Sf[f][3] = __expf(Sf[f][3] - mn1);
            ps0 += Sf[f][0] + Sf[f][1];
            ps1 += Sf[f][2] + Sf[f][3];
        }
        ps0 += __shfl_xor_sync(0xffffffffu, ps0, 1);
        ps0 += __shfl_xor_sync(0xffffffffu, ps0, 2);
        ps1 += __shfl_xor_sync(0xffffffffu, ps1, 1);
        ps1 += __shfl_xor_sync(0xffffffffu, ps1, 2);
        l0 = l0 * cr0 + ps0; m0 = mn0;
        l1 = l1 * cr1 + ps1; m1 = mn1;
#pragma unroll
        for (int f = 0; f < 8; ++f) {
            Of[f][0] *= cr0; Of[f][1] *= cr0; Of[f][2] *= cr1; Of[f][3] *= cr1;
        }

        uint32_t ph[4][4];
#pragma unroll
        for (int j2 = 0; j2 < 4; ++j2) {
            const float* A = Sf[2 * j2];
            const float* Bq = Sf[2 * j2 + 1];
            __half2 t;
            t.x = __float2half(A[0]);  t.y = __float2half(A[1]);  ph[j2][0] = *(uint32_t*)&t;
            t.x = __float2half(A[2]);  t.y = __float2half(A[3]);  ph[j2][1] = *(uint32_t*)&t;
            t.x = __float2half(Bq[0]); t.y = __float2half(Bq[1]); ph[j2][2] = *(uint32_t*)&t;
            t.x = __float2half(Bq[2]); t.y = __float2half(Bq[3]); ph[j2][3] = *(uint32_t*)&t;
        }

#pragma unroll
        for (int ks2 = 0; ks2 < 4; ++ks2) {
#pragma unroll
            for (int g = 0; g < 4; ++g) {
                const uint32_t voff = (ks2 * 16 + lr15) * 144 + (g * 16 + hb * 8) * 2;
                uint32_t vh[4];
                ldsm4t(vh, VH + voff);
#pragma unroll
                for (int j = 0; j < 2; ++j)
                    mma16816(Of[g * 2 + j], ph[ks2], vh[2 * j], vh[2 * j + 1]);
            }
        }
    }

    const int r0 = warp * 16 + (lane >> 2);
    if (!edge) {
        const float inv0 = 1.f / l0, inv1 = 1.f / l1;
        const size_t tk0 = (size_t)(b * S_ + qb * 64 + r0) * D_ + hh * 64;
        const size_t tk1 = tk0 + 8 * D_;
#pragma unroll
        for (int f = 0; f < 8; ++f) {
            const int c = f * 8 + 2 * (lane & 3);
            __half2 h01, h23;
            h01.x = __float2half(Of[f][0] * inv0);
            h01.y = __float2half(Of[f][1] * inv0);
            h23.x = __float2half(Of[f][2] * inv1);
            h23.y = __float2half(Of[f][3] * inv1);
            *(__half2*)(g_chi + tk0 + c) = h01;
            *(__half2*)(g_chi + tk1 + c) = h23;
        }
    } else {
        float* base = g_part + ((size_t)((((b * H_ + hh) * 2 + e) * 8 + slice) * 64)) * 66;
        float* pp0 = base + (size_t)r0 * 66;
        float* pp1 = base + (size_t)(r0 + 8) * 66;
#pragma unroll
        for (int f = 0; f < 8; ++f) {
            const int c = f * 8 + 2 * (lane & 3);
            pp0[c] = Of[f][0]; pp0[c + 1] = Of[f][1];
            pp1[c] = Of[f][2]; pp1[c + 1] = Of[f][3];
        }
        if ((lane & 3) == 0) {
            pp0[64] = m0; pp0[65] = l0;
            pp1[64] = m1; pp1[65] = l1;
        }
    }
}

__global__ __launch_bounds__(256) void merge_kernel() {
    const int e = blockIdx.x, hh = blockIdx.y, b = blockIdx.z;
    const int tid = threadIdx.x;
    const int r = tid >> 2, t4 = tid & 3;
    const size_t base = ((size_t)(((b * H_ + hh) * 2 + e) * 8)) * 64 * 66;

    float M = -1e30f;
#pragma unroll
    for (int s = 0; s < 8; ++s) M = fmaxf(M, g_part[base + ((size_t)s * 64 + r) * 66 + 64]);
    float L = 0.f, acc[16];
#pragma unroll
    for (int i = 0; i < 16; ++i) acc[i] = 0.f;
#pragma unroll
    for (int s = 0; s < 8; ++s) {
        const float* pp = g_part + base + ((size_t)s * 64 + r) * 66;
        const float w = __expf(pp[64] - M);
        L += pp[65] * w;
#pragma unroll
        for (int i = 0; i < 16; ++i) acc[i] += pp[t4 * 16 + i] * w;
    }
    const float inv = 1.0f / L;
    const int qb = e ? (NB_ - 1) : 0;
    const size_t idx = ((size_t)(b * S_ + qb * 64 + r)) * D_ + hh * 64 + t4 * 16;
#pragma unroll
    for (int i = 0; i < 16; ++i)
        g_chi[idx + i] = __float2half(acc[i] * inv);
}

// ---------------- classifier ----------------
__global__ void cls1_kernel(const float* __restrict__ h, const float* __restrict__ w,
                            const float* __restrict__ bias, float* __restrict__ out) {
    int gid = blockIdx.x * blockDim.x + threadIdx.x;
    if (gid >= 2 * 512) return;
    int b = gid >> 9, n = gid & 511;
    const float* hrow = h + (size_t)b * S_ * D_;
    float s = 0.f;
    for (int k2 = 0; k2 < D_; ++k2) s += hrow[k2] * w[(size_t)k2 * 512 + n];
    out[gid] = fmaxf(s + bias[n], 0.f);
}
__global__ void cls2_kernel(const float* __restrict__ rin, const float* __restrict__ w,
                            const float* __restrict__ bias, float* __restrict__ out) {
    int gid = blockIdx.x * blockDim.x + threadIdx.x;
    if (gid >= 2 * TGT_) return;
    int b = gid >> 10, n = gid & 1023;
    float s = 0.f;
    for (int k2 = 0; k2 < 512; ++k2) s += rin[b * 512 + k2] * w[(size_t)k2 * TGT_ + n];
    out[gid] = s + bias[n];
}

// ---------------- host ----------------
typedef CUresult (*EncFn)(CUtensorMap*, CUtensorMapDataType, cuuint32_t, void*,
                          const cuuint64_t*, const cuuint64_t*, const cuuint32_t*, const cuuint32_t*,
                          CUtensorMapInterleave, CUtensorMapSwizzle, CUtensorMapL2promotion,
                          CUtensorMapFloatOOBfill);

extern "C" void kernel_launch(void* const* d_in, const int* in_sizes, int n_in,
                              void* d_out, int out_size)
{
    const float* x        = (const float*)d_in[0];
    const float* mask     = (const float*)d_in[1];
    const float* proj_b   = (const float*)d_in[3];
    const float* pos_emb  = (const float*)d_in[4];
    const float* tok_emb  = (const float*)d_in[5];
    const float* emb_g    = (const float*)d_in[6];
    const float* emb_b    = (const float*)d_in[7];
    const float* bq_all   = (const float*)d_in[9];
    const float* bk_all   = (const float*)d_in[11];
    const float* bv_all   = (const float*)d_in[13];
    const float* bo_all   = (const float*)d_in[15];
    const float* ln1g_all = (const float*)d_in[16];
    const float* ln1b_all = (const float*)d_in[17];
    const float* bi_all   = (const float*)d_in[19];
    const float* bo2_all  = (const float*)d_in[21];
    const float* ln2g_all = (const float*)d_in[22];
    const float* ln2b_all = (const float*)d_in[23];
    const float* cls_w1   = (const float*)d_in[24];
    const float* cls_b1   = (const float*)d_in[25];
    const float* cls_w2   = (const float*)d_in[26];
    const float* cls_b2   = (const float*)d_in[27];
    const int*   rb       = (const int*)d_in[28];
    float* out = (float*)d_out;

    float *ph, *ptmp, *pcls, *pbqkv;
    __half *pwhi, *pwlo, *pxhi, *pxlo, *phhi, *pchi, *pfhi, *pqvh;
    cudaGetSymbolAddress((void**)&ph,   g_h);
    cudaGetSymbolAddress((void**)&ptmp, g_tmp);
    cudaGetSymbolAddress((void**)&pcls, g_cls);
    cudaGetSymbolAddress((void**)&pbqkv, g_bqkv);
    cudaGetSymbolAddress((void**)&pwhi, g_whi);
    cudaGetSymbolAddress((void**)&pwlo, g_wlo);
    cudaGetSymbolAddress((void**)&pxhi, g_xhi);
    cudaGetSymbolAddress((void**)&pxlo, g_xlo);
    cudaGetSymbolAddress((void**)&phhi, g_hhi);
    cudaGetSymbolAddress((void**)&pchi, g_chi);
    cudaGetSymbolAddress((void**)&pfhi, g_fhi);
    cudaGetSymbolAddress((void**)&pqvh, g_qkvhi);

    EncFn enc = nullptr;
    cudaDriverEntryPointQueryResult qr;
    cudaGetDriverEntryPointByVersion("cuTensorMapEncodeTiled", (void**)&enc, 12000,
                                     cudaEnableDefault, &qr);

    auto mk2 = [&](CUtensorMap* m, void* p, uint64_t K) {
        cuuint64_t d[2] = {K, T_};
        cuuint64_t st[1] = {K * 2};
        cuuint32_t bx[2] = {64, 128}, es[2] = {1, 1};
        enc(m, CU_TENSOR_MAP_DATA_TYPE_FLOAT16, 2, p, d, st, bx, es,
            CU_TENSOR_MAP_INTERLEAVE_NONE, CU_TENSOR_MAP_SWIZZLE_128B,
            CU_TENSOR_MAP_L2_PROMOTION_L2_128B, CU_TENSOR_MAP_FLOAT_OOB_FILL_NONE);
    };
    auto mk3 = [&](CUtensorMap* m, void* p, uint64_t K, uint64_t N, uint64_t Lz) {
        cuuint64_t d[3] = {K, N, Lz};
        cuuint64_t st[2] = {K * 2, N * K * 2};
        cuuint32_t bx[3] = {64, 128, 1}, es[3] = {1, 1, 1};
        enc(m, CU_TENSOR_MAP_DATA_TYPE_FLOAT16, 3, p, d, st, bx, es,
            CU_TENSOR_MAP_INTERLEAVE_NONE, CU_TENSOR_MAP_SWIZZLE_128B,
            CU_TENSOR_MAP_L2_PROMOTION_L2_128B, CU_TENSOR_MAP_FLOAT_OOB_FILL_NONE);
    };

    CUtensorMap mxh, mxl, mhh, mch, mfh;
    CUtensorMap mpjh, mpjl, mqkvh, mqkvl, moh, mol, mih, mil, m2h, m2l;
    mk2(&mxh, pxhi, IN_); mk2(&mxl, pxlo, IN_);
    mk2(&mhh, phhi, D_);
    mk2(&mch, pchi, D_);
    mk2(&mfh, pfhi, FF_);
    mk3(&mpjh, pwhi + OFF_PROJ, IN_, D_, 1);   mk3(&mpjl, pwlo + OFF_PROJ, IN_, D_, 1);
    mk3(&mqkvh, pwhi + OFF_QKV, D_, NQKV, L_); mk3(&mqkvl, pwlo + OFF_QKV, D_, NQKV, L_);
    mk3(&moh, pwhi + OFF_WO, D_, D_, L_);      mk3(&mol, pwlo + OFF_WO, D_, D_, L_);
    mk3(&mih, pwhi + OFF_WI, D_, FF_, L_);     mk3(&mil, pwlo + OFF_WI, D_, FF_, L_);
    mk3(&m2h, pwhi + OFF_WO2, FF_, D_, L_);    mk3(&m2l, pwlo + OFF_WO2, FF_, D_, L_);

    cudaFuncSetAttribute(tgemm_kernel<false, false, false, true, true, true>,
                         cudaFuncAttributeMaxDynamicSharedMemorySize, GEMM_SMEM);
    cudaFuncSetAttribute(tgemm_kernel<false, false, true, false, false, false>,
                         cudaFuncAttributeMaxDynamicSharedMemorySize, GEMM_SMEM);
    cudaFuncSetAttribute(tgemm_kernel<false, true, false, true, false, false>,
                         cudaFuncAttributeMaxDynamicSharedMemorySize, GEMM_SMEM);
    cudaFuncSetAttribute(tgemm_kernel<true, false, true, false, false, false>,
                         cudaFuncAttributeMaxDynamicSharedMemorySize, GEMM_SMEM);
    cudaFuncSetAttribute(attn_tc_kernel,
                         cudaFuncAttributeMaxDynamicSharedMemorySize, ATTN_SMEM);

    // prep
    dim3 tb(32, 8);
    tsplit_kernel<<<dim3(D_ / 32, IN_ / 32, 1), tb>>>((const float*)d_in[2], pwhi + OFF_PROJ, pwlo + OFF_PROJ, IN_, D_, IN_ * D_);
    tsplit_kernel<<<dim3(D_ / 32, D_ / 32, L_), tb>>>((const float*)d_in[8],  pwhi + OFF_QKV,               pwlo + OFF_QKV,               D_, D_, NQKV * D_);
    tsplit_kernel<<<dim3(D_ / 32, D_ / 32, L_), tb>>>((const float*)d_in[10], pwhi + OFF_QKV + 768 * 768,   pwlo + OFF_QKV + 768 * 768,   D_, D_, NQKV * D_);
    tsplit_kernel<<<dim3(D_ / 32, D_ / 32, L_), tb>>>((const float*)d_in[12], pwhi + OFF_QKV + 2 * 768 * 768, pwlo + OFF_QKV + 2 * 768 * 768, D_, D_, NQKV * D_);
    tsplit_kernel<<<dim3(D_ / 32, D_ / 32, L_), tb>>>((const float*)d_in[14], pwhi + OFF_WO, pwlo + OFF_WO, D_, D_, D_ * D_);
    tsplit_kernel<<<dim3(FF_ / 32, D_ / 32, L_), tb>>>((const float*)d_in[18], pwhi + OFF_WI, pwlo + OFF_WI, D_, FF_, D_ * FF_);
    tsplit_kernel<<<dim3(D_ / 32, FF_ / 32, L_), tb>>>((const float*)d_in[20], pwhi + OFF_WO2, pwlo + OFF_WO2, FF_, D_, FF_ * D_);
    split_kernel<<<(T_ * IN_ + 255) / 256, 256>>>(x, pxhi, pxlo, T_ * IN_);
    build_gi_kernel<<<1, 64>>>(rb);
    bcat_kernel<<<(L_ * NQKV + 255) / 256, 256>>>(bq_all, bk_all, bv_all);

    const dim3 gD(D_ / 128, T_ / 128);
    const dim3 gQKV(NQKV / 128, T_ / 128);
    const dim3 gF(FF_ / 128, T_ / 128);
    const dim3 gA(78, H_, B_);
    const dim3 gM(2, H_, B_);

    // embedding proj: 3-plane fp16
    tgemm_kernel<false, false, false, true, true, true><<<gD, 256, GEMM_SMEM>>>(
        mxh, mxl, mpjh, mpjl, proj_b, nullptr, ptmp, nullptr, D_, IN_, 0);
    ln_kernel<<<T_, 256>>>(ptmp, emb_g, emb_b, ph, phhi, pos_emb, tok_emb);

    for (int l = 0; l < L_; ++l) {
        // QKV: 1-plane fp16, hi-only output
        tgemm_kernel<false, false, true, false, false, false><<<gQKV, 256, GEMM_SMEM>>>(
            mhh, mhh, mqkvh, mqkvl, pbqkv + (size_t)l * NQKV, nullptr,
            nullptr, pqvh, NQKV, D_, l);

        attn_tc_kernel<<<gA, 128, ATTN_SMEM>>>(pqvh, mask);
        merge_kernel<<<gM, 256>>>();

        // wo: 1-plane fp16, residual, f32 out
        tgemm_kernel<false, true, false, true, false, false><<<gD, 256, GEMM_SMEM>>>(
            mch, mch, moh, mol, bo_all + (size_t)l * D_, ph, ptmp, nullptr, D_, D_, l);
        ln_kernel<<<T_, 256>>>(ptmp, ln1g_all + (size_t)l * D_, ln1b_all + (size_t)l * D_,
                               ph, phhi, nullptr, nullptr);

        // wi: 1-plane fp16, GELU, hi-only out
        tgemm_kernel<true, false, true, false, false, false><<<gF, 256, GEMM_SMEM>>>(
            mhh, mhh, mih, mil, bi_all + (size_t)l * FF_, nullptr, nullptr, pfhi, FF_, D_, l);
        // wo2: 1-plane fp16, residual, f32 out
        tgemm_kernel<false, true, false, true, false, false><<<gD, 256, GEMM_SMEM>>>(
            mfh, mfh, m2h, m2l, bo2_all + (size_t)l * D_, ph, ptmp, nullptr, D_, FF_, l);
        ln_kernel<<<T_, 256>>>(ptmp, ln2g_all + (size_t)l * D_, ln2b_all + (size_t)l * D_,
                               ph, phhi, nullptr, nullptr);
    }

    cls1_kernel<<<4, 256>>>(ph, cls_w1, cls_b1, pcls);
    cls2_kernel<<<8, 256>>>(pcls, cls_w2, cls_b2, out);
}